// round 9
// baseline (speedup 1.0000x reference)
#include <cuda_runtime.h>
#include <cuda_bf16.h>
#include <math.h>
#include <stdint.h>

#define BB 32
#define NN 1024
#define DD 64
#define HALF (BB*NN*DD)
#define SZB ((size_t)BB*NN*NN)

// ---------------- scratch (device globals; no allocation allowed) ----------
static __device__ __nv_bfloat16 g_sHi[2*SZB];  // phase1: sigmoid hi [which][b][n][j]
                                               // phase2: EmHi [0,SZB) , EmLo [SZB,2SZB)
static __device__ __nv_bfloat16 g_sLo[2*SZB];  // phase1: sigmoid lo
                                               // phase2: NhHi, NhLo
static __device__ __nv_bfloat16 g_vHi[(size_t)2*NN*NN];
static __device__ __nv_bfloat16 g_vLo[(size_t)2*NN*NN];
static __device__ __nv_bfloat16 g_xH[(size_t)BB*NN*DD];
static __device__ __nv_bfloat16 g_xL[(size_t)BB*NN*DD];
static __device__ float g_EF  [SZB];
static __device__ float g_NG  [SZB];
static __device__ float g_bsTf[(size_t)NN*NN];
static __device__ float g_bsTg[(size_t)NN*NN];
static __device__ float g_e1f[BB*NN], g_e2f[BB*NN], g_e1g[BB*NN], g_e2g[BB*NN];
static __device__ float g_Amix[NN*NN];
static __device__ float g_add[(size_t)BB*NN*DD];   // xw + cb + x0*sig(alpha)

__device__ __forceinline__ float sigm(float v) { return 1.0f / (1.0f + __expf(-v)); }
__device__ __forceinline__ uint32_t smem_u32(const void* p) {
    uint32_t a;
    asm("{ .reg .u64 t; cvta.to.shared.u64 t, %1; cvt.u32.u64 %0, t; }" : "=r"(a) : "l"(p));
    return a;
}
__device__ __forceinline__ void bf16_split(float x, __nv_bfloat16& hi, __nv_bfloat16& lo) {
    hi = __float2bfloat16(x);
    lo = __float2bfloat16(x - __bfloat162float(hi));
}
__device__ __forceinline__ void mma16(float* c, const uint32_t* a, const uint32_t* b) {
    asm volatile("mma.sync.aligned.m16n8k16.row.col.f32.bf16.bf16.f32 "
                 "{%0,%1,%2,%3}, {%4,%5,%6,%7}, {%8,%9}, {%0,%1,%2,%3};"
                 : "+f"(c[0]), "+f"(c[1]), "+f"(c[2]), "+f"(c[3])
                 : "r"(a[0]), "r"(a[1]), "r"(a[2]), "r"(a[3]),
                   "r"(b[0]), "r"(b[1]));
}
__device__ __forceinline__ void ldm_x4(uint32_t* r, uint32_t addr) {
    asm volatile("ldmatrix.sync.aligned.m8n8.x4.shared.b16 {%0,%1,%2,%3}, [%4];"
                 : "=r"(r[0]), "=r"(r[1]), "=r"(r[2]), "=r"(r[3]) : "r"(addr));
}
__device__ __forceinline__ void ldm_x4t(uint32_t* r, uint32_t addr) {
    asm volatile("ldmatrix.sync.aligned.m8n8.x4.trans.shared.b16 {%0,%1,%2,%3}, [%4];"
                 : "=r"(r[0]), "=r"(r[1]), "=r"(r[2]), "=r"(r[3]) : "r"(addr));
}

// ============ kernel 0: fused prep (evec | amix | transp | vs-split | x-split)
#define PB_EVEC   4096   // (BB*NN)/8 warps-per-block=8 -> 4096 blocks (was 1024: BUG)
#define PB_AMIX   1024
#define PB_TRANSP 2048
#define PB_SPLIT  2048
#define PB_XSPL   2048
__global__ void __launch_bounds__(256) k_prep(
        const float* __restrict__ x,
        const float* __restrict__ fw1, const float* __restrict__ fw2,
        const float* __restrict__ gw1, const float* __restrict__ gw2,
        const float* __restrict__ fvs, const float* __restrict__ gvs,
        const float* __restrict__ fbs, const float* __restrict__ gbs,
        const float* __restrict__ adj, const float* __restrict__ convw) {
    int bid = blockIdx.x;
    int tid = threadIdx.x;
    if (bid < PB_EVEC) {
        int gwarp = bid * 8 + (tid >> 5);
        int lane  = tid & 31;
        const float* xp = x + (size_t)gwarp * DD;
        float v0 = xp[lane], v1 = xp[lane + 32];
        float s0 = v0 * fw1[lane] + v1 * fw1[lane + 32];
        float s1 = v0 * fw2[lane] + v1 * fw2[lane + 32];
        float s2 = v0 * gw1[lane] + v1 * gw1[lane + 32];
        float s3 = v0 * gw2[lane] + v1 * gw2[lane + 32];
        #pragma unroll
        for (int o = 16; o > 0; o >>= 1) {
            s0 += __shfl_xor_sync(0xffffffffu, s0, o);
            s1 += __shfl_xor_sync(0xffffffffu, s1, o);
            s2 += __shfl_xor_sync(0xffffffffu, s2, o);
            s3 += __shfl_xor_sync(0xffffffffu, s3, o);
        }
        if (lane == 0) {
            g_e1f[gwarp] = s0; g_e2f[gwarp] = s1;
            g_e1g[gwarp] = s2; g_e2g[gwarp] = s3;
        }
        return;
    }
    bid -= PB_EVEC;
    if (bid < PB_AMIX) {
        int t = bid * 256 + tid;
        int base = t * 4;
        int i = base >> 10;
        int j = base & (NN - 1);
        float c0 = convw[0], c1 = convw[1];
        float dsub = c0 + c1;
        float4 a0 = *(const float4*)(adj + base);
        float4 a1 = *(const float4*)(adj + (size_t)NN * NN + base);
        float4 r;
        r.x = c0 * a0.x + c1 * a1.x - ((i == j + 0) ? dsub : 0.0f);
        r.y = c0 * a0.y + c1 * a1.y - ((i == j + 1) ? dsub : 0.0f);
        r.z = c0 * a0.z + c1 * a1.z - ((i == j + 2) ? dsub : 0.0f);
        r.w = c0 * a0.w + c1 * a1.w - ((i == j + 3) ? dsub : 0.0f);
        *(float4*)(g_Amix + base) = r;
        return;
    }
    bid -= PB_AMIX;
    if (bid < PB_TRANSP) {
        __shared__ float t[32][33];
        int z = bid >> 10;
        int rem = bid & 1023;
        int x0t = (rem & 31) * 32, y0t = (rem >> 5) * 32;
        const float* src = z ? gbs : fbs;
        float* dst = z ? g_bsTg : g_bsTf;
        int tx = tid & 31, ty = tid >> 5;
        #pragma unroll
        for (int r = ty; r < 32; r += 8)
            t[r][tx] = src[(size_t)(y0t + r) * NN + x0t + tx];
        __syncthreads();
        #pragma unroll
        for (int r = ty; r < 32; r += 8)
            dst[(size_t)(x0t + r) * NN + y0t + tx] = t[tx][r];
        return;
    }
    bid -= PB_TRANSP;
    if (bid < PB_SPLIT) {
        int t = bid * 256 + tid;
        int which = t >= (NN * NN / 4);
        int e = which ? t - NN * NN / 4 : t;
        const float4* src = (const float4*)(which ? gvs : fvs);
        float4 a = src[e];
        __nv_bfloat16 h0, l0, h1, l1, h2, l2, h3, l3;
        bf16_split(a.x, h0, l0); bf16_split(a.y, h1, l1);
        bf16_split(a.z, h2, l2); bf16_split(a.w, h3, l3);
        size_t off = (size_t)which * NN * NN + (size_t)e * 4;
        __nv_bfloat162* ph = (__nv_bfloat162*)(g_vHi + off);
        __nv_bfloat162* pl = (__nv_bfloat162*)(g_vLo + off);
        ph[0] = __nv_bfloat162{h0, h1}; ph[1] = __nv_bfloat162{h2, h3};
        pl[0] = __nv_bfloat162{l0, l1}; pl[1] = __nv_bfloat162{l2, l3};
        return;
    }
    bid -= PB_SPLIT;
    {
        int e = bid * 256 + tid;          // over BB*NN*DD/4 float4s
        float4 a = ((const float4*)x)[e];
        __nv_bfloat16 h0, l0, h1, l1, h2, l2, h3, l3;
        bf16_split(a.x, h0, l0); bf16_split(a.y, h1, l1);
        bf16_split(a.z, h2, l2); bf16_split(a.w, h3, l3);
        size_t off = (size_t)e * 4;
        __nv_bfloat162* ph = (__nv_bfloat162*)(g_xH + off);
        __nv_bfloat162* pl = (__nv_bfloat162*)(g_xL + off);
        ph[0] = __nv_bfloat162{h0, h1}; ph[1] = __nv_bfloat162{h2, h3};
        pl[0] = __nv_bfloat162{l0, l1}; pl[1] = __nv_bfloat162{l2, l3};
        return;
    }
}

// ============ kernel addterm: g_add = xr@W_hat + cb + x0*sigm(alpha) =======
#define XSTRIDE 68   // floats; 272B = multiple of 16 -> aligned float4 rows
__global__ void __launch_bounds__(256) k_addterm(
        const float* __restrict__ x, const float* __restrict__ x0,
        const float* __restrict__ w, const float* __restrict__ d,
        const float* __restrict__ alpha, const float* __restrict__ convb) {
    __shared__ float sWh[64 * 64];
    __shared__ float sXi[64 * XSTRIDE];
    int b = blockIdx.y, i0 = blockIdx.x * 64;
    int tid = threadIdx.x;

    // compute W_hat = (w*clip(d)) @ w^T - I   (redundant per block, tiny)
    #pragma unroll
    for (int e = 0; e < 16; e++) {
        int idx = tid + e * 256;
        int i = idx >> 6, j = idx & 63;
        float s = 0.0f;
        #pragma unroll 8
        for (int k = 0; k < DD; k++) {
            float dc = fminf(fmaxf(d[k], 0.0f), 1.0f);
            s += w[i * DD + k] * dc * w[j * DD + k];
        }
        sWh[idx] = s - ((i == j) ? 1.0f : 0.0f);
    }
    // load Xi rows
    #pragma unroll
    for (int q = 0; q < 4; q++) {
        int lin = tid + q * 256;
        int row = lin >> 4, cc = (lin & 15) * 4;
        *(float4*)&sXi[row * XSTRIDE + cc] =
            *(const float4*)(x + (size_t)(b * NN + i0 + row) * DD + cc);
    }
    __syncthreads();

    int il = tid >> 2, c0 = (tid & 3) * 16;
    float acc[16];
    #pragma unroll
    for (int q = 0; q < 16; q++) acc[q] = 0.0f;
    #pragma unroll 8
    for (int k = 0; k < DD; k++) {
        float xik = sXi[il * XSTRIDE + k];
        #pragma unroll
        for (int q = 0; q < 4; q++) {
            float4 wv = *(float4*)&sWh[k * 64 + c0 + q * 4];
            acc[q * 4 + 0] += xik * wv.x; acc[q * 4 + 1] += xik * wv.y;
            acc[q * 4 + 2] += xik * wv.z; acc[q * 4 + 3] += xik * wv.w;
        }
    }
    float cb = convb[0];
    float sa = sigm(alpha[i0 + il]);
    size_t obase = ((size_t)b * NN + i0 + il) * DD + c0;
    #pragma unroll
    for (int q = 0; q < 4; q++) {
        float4 x0v = *(const float4*)(x0 + obase + q * 4);
        float4 r;
        r.x = acc[q * 4 + 0] + cb + x0v.x * sa;
        r.y = acc[q * 4 + 1] + cb + x0v.y * sa;
        r.z = acc[q * 4 + 2] + cb + x0v.z * sa;
        r.w = acc[q * 4 + 3] + cb + x0v.w * sa;
        *(float4*)(g_add + obase + q * 4) = r;
    }
}

// -------- kernel sig: S[b,n,j] = sigmoid(e2[b,n]*e1[b,j] + bsT[n,j]), hi/lo
__global__ void k_sig(void) {
    int n = blockIdx.x, b = blockIdx.y, which = blockIdx.z;
    int j = threadIdx.x * 4;
    const float* e1 = which ? g_e1g : g_e1f;
    const float* e2 = which ? g_e2g : g_e2f;
    const float* bsT = (which ? g_bsTg : g_bsTf) + (size_t)n * NN + j;
    size_t off = (((size_t)which * BB + b) * NN + n) * NN + j;
    float  a   = e2[b * NN + n];
    float4 e1v = *(const float4*)(e1 + b * NN + j);
    float4 bv  = *(const float4*)bsT;
    float sx = sigm(a * e1v.x + bv.x);
    float sy = sigm(a * e1v.y + bv.y);
    float sz = sigm(a * e1v.z + bv.z);
    float sw = sigm(a * e1v.w + bv.w);
    __nv_bfloat16 h0, l0, h1, l1, h2, l2, h3, l3;
    bf16_split(sx, h0, l0); bf16_split(sy, h1, l1);
    bf16_split(sz, h2, l2); bf16_split(sw, h3, l3);
    __nv_bfloat162* ph = (__nv_bfloat162*)(g_sHi + off);
    __nv_bfloat162* pl = (__nv_bfloat162*)(g_sLo + off);
    ph[0] = __nv_bfloat162{h0, h1}; ph[1] = __nv_bfloat162{h2, h3};
    pl[0] = __nv_bfloat162{l0, l1}; pl[1] = __nv_bfloat162{l2, l3};
}

// ---------------- kernel gemm: bf16x3 mma.sync batched GEMM ----------------
#define KT     32
#define STRB   80
#define TILE_BYTES (128*STRB)
#define STAGE_BYTES (4*TILE_BYTES)
#define GEMM_SMEM  (2*STAGE_BYTES)

__global__ void __launch_bounds__(256) k_gemm(int which) {
    extern __shared__ char smg[];
    uint32_t smb = smem_u32(smg);
    int tid = threadIdx.x;
    int b = blockIdx.z;
    const __nv_bfloat16* __restrict__ Ahi = g_vHi + (size_t)which * NN * NN;
    const __nv_bfloat16* __restrict__ Alo = g_vLo + (size_t)which * NN * NN;
    const __nv_bfloat16* __restrict__ Bhi = g_sHi + ((size_t)which * BB + b) * NN * NN;
    const __nv_bfloat16* __restrict__ Blo = g_sLo + ((size_t)which * BB + b) * NN * NN;
    float* __restrict__ C = (which ? g_NG : g_EF) + (size_t)b * NN * NN;
    int i0 = blockIdx.y * 128, n0 = blockIdx.x * 128;

    int wid = tid >> 5, lane = tid & 31;
    int gid = lane >> 2, tg = lane & 3;
    int wm = (wid & 1) * 64, wn = (wid >> 1) * 32;

    int lr    = lane & 7;
    int lrow8 = (lane >> 3) & 1;
    int lk8   = (lane >> 4) & 1;
    uint32_t aoff = (uint32_t)((wm + lrow8 * 8 + lr) * STRB + lk8 * 16);
    uint32_t boff = (uint32_t)((wn + lrow8 * 8 + lr) * STRB + lk8 * 16);

    int slot_tile[8], slot_row[8], slot_ch[8];
    #pragma unroll
    for (int it = 0; it < 8; it++) {
        int slot = tid + it * 256;
        slot_tile[it] = slot >> 9;
        int r2 = slot & 511;
        slot_row[it] = r2 >> 2;
        slot_ch[it]  = r2 & 3;
    }

    float acc[4][4][4];
    #pragma unroll
    for (int mf = 0; mf < 4; mf++)
        #pragma unroll
        for (int nf = 0; nf < 4; nf++)
            #pragma unroll
            for (int q = 0; q < 4; q++) acc[mf][nf][q] = 0.0f;

    #define G_ISSUE(S) do {                                                      \
        uint32_t sb_ = smb + ((S) & 1) * STAGE_BYTES;                            \
        int kc_ = (S) * KT;                                                      \
        _Pragma("unroll")                                                        \
        for (int it = 0; it < 8; it++) {                                         \
            int tile = slot_tile[it], row = slot_row[it], ch = slot_ch[it];      \
            const __nv_bfloat16* src =                                           \
                (tile == 0) ? Ahi + (size_t)(i0 + row) * NN :                    \
                (tile == 1) ? Alo + (size_t)(i0 + row) * NN :                    \
                (tile == 2) ? Bhi + (size_t)(n0 + row) * NN :                    \
                              Blo + (size_t)(n0 + row) * NN;                     \
            const char* gp = (const char*)(src + kc_) + ch * 16;                 \
            uint32_t sp = sb_ + (uint32_t)(tile * TILE_BYTES + row * STRB + ch * 16); \
            asm volatile("cp.async.ca.shared.global [%0], [%1], 16;"             \
                         :: "r"(sp), "l"(gp));                                   \
        }                                                                        \
        asm volatile("cp.async.commit_group;");                                  \
    } while (0)

    G_ISSUE(0);
    for (int s = 0; s < NN / KT; s++) {
        if (s < NN / KT - 1) {
            G_ISSUE(s + 1);
            asm volatile("cp.async.wait_group 1;");
        } else {
            asm volatile("cp.async.wait_group 0;");
        }
        __syncthreads();
        uint32_t base = smb + (s & 1) * STAGE_BYTES;
        uint32_t tAh = base, tAl = base + TILE_BYTES;
        uint32_t tBh = base + 2 * TILE_BYTES, tBl = base + 3 * TILE_BYTES;

        #pragma unroll
        for (int kh = 0; kh < 2; kh++) {
            uint32_t kb = (uint32_t)(kh * 32);
            uint32_t ah[4][4], al[4][4], bh[4][2], bl[4][2];
            #pragma unroll
            for (int mf = 0; mf < 4; mf++) {
                uint32_t ao = aoff + (uint32_t)(mf * 16 * STRB) + kb;
                ldm_x4(ah[mf], tAh + ao);
                ldm_x4(al[mf], tAl + ao);
            }
            #pragma unroll
            for (int p = 0; p < 2; p++) {
                uint32_t bo = boff + (uint32_t)(p * 16 * STRB) + kb;
                uint32_t th[4], tl[4];
                ldm_x4(th, tBh + bo);
                ldm_x4(tl, tBl + bo);
                bh[2*p][0]   = th[0]; bh[2*p][1]   = th[2];
                bh[2*p+1][0] = th[1]; bh[2*p+1][1] = th[3];
                bl[2*p][0]   = tl[0]; bl[2*p][1]   = tl[2];
                bl[2*p+1][0] = tl[1]; bl[2*p+1][1] = tl[3];
            }
            #pragma unroll
            for (int mf = 0; mf < 4; mf++)
                #pragma unroll
                for (int nf = 0; nf < 4; nf++) {
                    mma16(acc[mf][nf], ah[mf], bh[nf]);
                    mma16(acc[mf][nf], ah[mf], bl[nf]);
                    mma16(acc[mf][nf], al[mf], bh[nf]);
                }
        }
        __syncthreads();
    }

    #pragma unroll
    for (int mf = 0; mf < 4; mf++) {
        #pragma unroll
        for (int nf = 0; nf < 4; nf++) {
            int row = i0 + wm + mf * 16 + gid;
            int col = n0 + wn + nf * 8 + tg * 2;
            float2 v0 = make_float2(acc[mf][nf][0], acc[mf][nf][1]);
            float2 v1 = make_float2(acc[mf][nf][2], acc[mf][nf][3]);
            *(float2*)(C + (size_t)row * NN + col)       = v0;
            *(float2*)(C + (size_t)(row + 8) * NN + col) = v1;
        }
    }
}

// ------- kernel soft: row softmax; outputs Em/Nh as bf16 hi/lo aliases -----
__global__ void k_soft() {
    int i = blockIdx.x, b = blockIdx.y;
    size_t ro = ((size_t)b * NN + i) * NN;
    int c = threadIdx.x * 4;
    int wid = threadIdx.x >> 5, lane = threadIdx.x & 31;
    __shared__ float sE[8], sN[8];

    float4 ev = *(float4*)(g_EF + ro + c);
    float4 nv = *(float4*)(g_NG + ro + c);

    float mE = fmaxf(fmaxf(ev.x, ev.y), fmaxf(ev.z, ev.w));
    float mN = fmaxf(fmaxf(nv.x, nv.y), fmaxf(nv.z, nv.w));
    #pragma unroll
    for (int o = 16; o > 0; o >>= 1) {
        mE = fmaxf(mE, __shfl_xor_sync(0xffffffffu, mE, o));
        mN = fmaxf(mN, __shfl_xor_sync(0xffffffffu, mN, o));
    }
    if (lane == 0) { sE[wid] = mE; sN[wid] = mN; }
    __syncthreads();
    mE = sE[0]; mN = sN[0];
    #pragma unroll
    for (int wv = 1; wv < 8; wv++) { mE = fmaxf(mE, sE[wv]); mN = fmaxf(mN, sN[wv]); }
    __syncthreads();

    float4 eE, eN;
    eE.x = __expf(ev.x - mE); eE.y = __expf(ev.y - mE);
    eE.z = __expf(ev.z - mE); eE.w = __expf(ev.w - mE);
    eN.x = __expf(nv.x - mN); eN.y = __expf(nv.y - mN);
    eN.z = __expf(nv.z - mN); eN.w = __expf(nv.w - mN);
    float sumE = eE.x + eE.y + eE.z + eE.w;
    float sumN = eN.x + eN.y + eN.z + eN.w;
    #pragma unroll
    for (int o = 16; o > 0; o >>= 1) {
        sumE += __shfl_xor_sync(0xffffffffu, sumE, o);
        sumN += __shfl_xor_sync(0xffffffffu, sumN, o);
    }
    if (lane == 0) { sE[wid] = sumE; sN[wid] = sumN; }
    __syncthreads();
    sumE = 0.0f; sumN = 0.0f;
    #pragma unroll
    for (int wv = 0; wv < 8; wv++) { sumE += sE[wv]; sumN += sN[wv]; }

    float invE = __fdividef(1.0f, sumE);
    float invN = __fdividef(1.0f, sumN);

    float4 se;
    se.x = eE.x * invE; se.y = eE.y * invE; se.z = eE.z * invE; se.w = eE.w * invE;
    float4 nh;
    nh.x = __fdividef(eN.x * invN, se.x + 1e-5f);
    nh.y = __fdividef(eN.y * invN, se.y + 1e-5f);
    nh.z = __fdividef(eN.z * invN, se.z + 1e-5f);
    nh.w = __fdividef(eN.w * invN, se.w + 1e-5f);

    float4 am = *(float4*)(g_Amix + (size_t)i * NN + c);
    float4 em;
    em.x = se.x + am.x - ((c + 0 == i) ? 1.0f : 0.0f);
    em.y = se.y + am.y - ((c + 1 == i) ? 1.0f : 0.0f);
    em.z = se.z + am.z - ((c + 2 == i) ? 1.0f : 0.0f);
    em.w = se.w + am.w - ((c + 3 == i) ? 1.0f : 0.0f);

    __nv_bfloat16 h0, l0, h1, l1, h2, l2, h3, l3;
    bf16_split(em.x, h0, l0); bf16_split(em.y, h1, l1);
    bf16_split(em.z, h2, l2); bf16_split(em.w, h3, l3);
    *(__nv_bfloat162*)(g_sHi + ro + c)           = __nv_bfloat162{h0, h1};
    *(__nv_bfloat162*)(g_sHi + ro + c + 2)       = __nv_bfloat162{h2, h3};
    *(__nv_bfloat162*)(g_sHi + SZB + ro + c)     = __nv_bfloat162{l0, l1};
    *(__nv_bfloat162*)(g_sHi + SZB + ro + c + 2) = __nv_bfloat162{l2, l3};
    bf16_split(nh.x, h0, l0); bf16_split(nh.y, h1, l1);
    bf16_split(nh.z, h2, l2); bf16_split(nh.w, h3, l3);
    *(__nv_bfloat162*)(g_sLo + ro + c)           = __nv_bfloat162{h0, h1};
    *(__nv_bfloat162*)(g_sLo + ro + c + 2)       = __nv_bfloat162{h2, h3};
    *(__nv_bfloat162*)(g_sLo + SZB + ro + c)     = __nv_bfloat162{l0, l1};
    *(__nv_bfloat162*)(g_sLo + SZB + ro + c + 2) = __nv_bfloat162{l2, l3};
}

// --------- kernel final: f = tanh(Em@xr + add), g = tanh(Nh@xr) (bf16x3 MMA)
#define F_STR    80
#define F_TILE   (128*F_STR)             // 10240
#define F_XSTR   144
#define F_XTILE  (32*F_XSTR)             // 4608
#define F_XOFF   (4*F_TILE)              // 40960
#define F_STAGE  (F_XOFF + 2*F_XTILE)    // 50176
#define FIN_SMEM (2*F_STAGE)             // 100352

__global__ void __launch_bounds__(256) k_final(float* __restrict__ out) {
    extern __shared__ char smf[];
    uint32_t smb = smem_u32(smf);
    int tid = threadIdx.x;
    int b = blockIdx.y, i0 = blockIdx.x * 128;
    const __nv_bfloat16* EmH = g_sHi + (size_t)b * NN * NN;
    const __nv_bfloat16* EmL = EmH + SZB;
    const __nv_bfloat16* NhH = g_sLo + (size_t)b * NN * NN;
    const __nv_bfloat16* NhL = NhH + SZB;
    const __nv_bfloat16* xHb = g_xH + (size_t)b * NN * DD;
    const __nv_bfloat16* xLb = g_xL + (size_t)b * NN * DD;

    int wid = tid >> 5, lane = tid & 31;
    int gid = lane >> 2, tg = lane & 3;
    int wm = (wid & 3) * 32, wn = (wid >> 2) * 32;

    int lr    = lane & 7;
    int lrow8 = (lane >> 3) & 1;
    int lk8   = (lane >> 4) & 1;
    uint32_t aoff = (uint32_t)((wm + lrow8 * 8 + lr) * F_STR + lk8 * 16);
    int quad = lane >> 3;
    int xkrow = (quad & 1) * 8 + lr;
    int xn8   = (quad >> 1) * 8;

    float accF[2][4][4], accG[2][4][4];
    #pragma unroll
    for (int mf = 0; mf < 2; mf++)
        #pragma unroll
        for (int nf = 0; nf < 4; nf++)
            #pragma unroll
            for (int q = 0; q < 4; q++) { accF[mf][nf][q] = 0.0f; accG[mf][nf][q] = 0.0f; }

    // cp.async: 2560 16B chunks per stage, 10 per thread
    #define F_ISSUE(S) do {                                                      \
        uint32_t sb_ = smb + ((S) & 1) * F_STAGE;                                \
        int jc_ = (S) * 32;                                                      \
        _Pragma("unroll")                                                        \
        for (int it = 0; it < 10; it++) {                                        \
            int slot = tid + it * 256;                                           \
            if (slot < 2048) {                                                   \
                int tile = slot >> 9;                                            \
                int r2 = slot & 511;                                             \
                int row = r2 >> 2, ch = r2 & 3;                                  \
                const __nv_bfloat16* src =                                       \
                    (tile == 0) ? EmH : (tile == 1) ? EmL :                      \
                    (tile == 2) ? NhH : NhL;                                     \
                const char* gp = (const char*)(src + (size_t)(i0 + row) * NN + jc_ + ch * 8); \
                uint32_t sp = sb_ + (uint32_t)(tile * F_TILE + row * F_STR + ch * 16); \
                asm volatile("cp.async.ca.shared.global [%0], [%1], 16;"         \
                             :: "r"(sp), "l"(gp));                               \
            } else {                                                             \
                int t2 = slot - 2048;                                            \
                int xt = t2 >> 8;                                                \
                int r2 = t2 & 255;                                               \
                int row = r2 >> 3, ch = r2 & 7;                                  \
                const __nv_bfloat16* src = xt ? xLb : xHb;                       \
                const char* gp = (const char*)(src + (size_t)(jc_ + row) * DD + ch * 8); \
                uint32_t sp = sb_ + (uint32_t)(F_XOFF + xt * F_XTILE + row * F_XSTR + ch * 16); \
                asm volatile("cp.async.ca.shared.global [%0], [%1], 16;"         \
                             :: "r"(sp), "l"(gp));                               \
            }                                                                    \
        }                                                                        \
        asm volatile("cp.async.commit_group;");                                  \
    } while (0)

    F_ISSUE(0);
    for (int s = 0; s < NN / 32; s++) {
        if (s < NN / 32 - 1) {
            F_ISSUE(s + 1);
            asm volatile("cp.async.wait_group 1;");
        } else {
            asm volatile("cp.async.wait_group 0;");
        }
        __syncthreads();
        uint32_t base = smb + (s & 1) * F_STAGE;
        uint32_t tEh = base, tEl = base + F_TILE;
        uint32_t tNh = base + 2 * F_TILE, tNl = base + 3 * F_TILE;
        uint32_t tXh = base + F_XOFF, tXl = base + F_XOFF + F_XTILE;

        #pragma unroll
        for (int kh = 0; kh < 2; kh++) {
            uint32_t kb = (uint32_t)(kh * 32);     // A tiles: 16 bf16 = 32B
            // B (x) frags — shared by Em and Nh passes
            uint32_t bxh[4][2], bxl[4][2];
            #pragma unroll
            for (int p = 0; p < 2; p++) {
                uint32_t xad = (uint32_t)((kh * 16 + xkrow) * F_XSTR + (wn + p * 16 + xn8) * 2);
                uint32_t th[4], tl[4];
                ldm_x4t(th, tXh + xad);
                ldm_x4t(tl, tXl + xad);
                bxh[2*p][0]   = th[0]; bxh[2*p][1]   = th[1];
                bxh[2*p+1][0] = th[2]; bxh[2*p+1][1] = th[3];
                bxl[2*p][0]   = tl[0]; bxl[2*p][1]   = tl[1];
                bxl[2*p+1][0] = tl[2]; bxl[2*p+1][1] = tl[3];
            }
            {   // F pass (Em)
                uint32_t ah[2][4], al[2][4];
                #pragma unroll
                for (int mf = 0; mf < 2; mf++) {
                    uint32_t ao = aoff + (uint32_t)(mf * 16 * F_STR) + kb;
                    ldm_x4(ah[mf], tEh + ao);
                    ldm_x4(al[mf], tEl + ao);
                }
                #pragma unroll
                for (int mf = 0; mf < 2; mf++)
                    #pragma unroll
                    for (int nf = 0; nf < 4; nf++) {
                        mma16(accF[mf][nf], ah[mf], bxh[nf]);
                        mma16(accF[mf][nf], ah[mf], bxl[nf]);
                        mma16(accF[mf][nf], al[mf], bxh[nf]);
                    }
            }
            {   // G pass (Nh)
                uint32_t ah[2][4], al[2][4];
                #pragma unroll
                for (int mf = 0; mf < 2; mf++) {
                    uint32_t ao = aoff + (uint32_t)(mf * 16 * F_STR) + kb;
                    ldm_x4(ah[mf], tNh + ao);
                    ldm_x4(al[mf], tNl + ao);
                }
                #pragma unroll
                for (int mf = 0; mf < 2; mf++)
                    #pragma unroll
                    for (int nf = 0; nf < 4; nf++) {
                        mma16(accG[mf][nf], ah[mf], bxh[nf]);
                        mma16(accG[mf][nf], ah[mf], bxl[nf]);
                        mma16(accG[mf][nf], al[mf], bxh[nf]);
                    }
            }
        }
        __syncthreads();
    }

    // epilogue: f = tanh(accF + add), g = tanh(accG)
    #pragma unroll
    for (int mf = 0; mf < 2; mf++) {
        #pragma unroll
        for (int nf = 0; nf < 4; nf++) {
            int row = i0 + wm + mf * 16 + gid;
            int col = wn + nf * 8 + tg * 2;
            size_t o0 = ((size_t)b * NN + row) * DD + col;
            size_t o1 = ((size_t)b * NN + row + 8) * DD + col;
            float2 a0 = *(const float2*)(g_add + o0);
            float2 a1 = *(const float2*)(g_add + o1);
            float2 f0, f1, g0, g1;
            f0.x = tanhf(accF[mf][nf][0] + a0.x);
            f0.y = tanhf(accF[mf][nf][1] + a0.y);
            f1.x = tanhf(accF[mf][nf][2] + a1.x);
            f1.y = tanhf(accF[mf][nf][3] + a1.y);
            g0.x = tanhf(accG[mf][nf][0]);
            g0.y = tanhf(accG[mf][nf][1]);
            g1.x = tanhf(accG[mf][nf][2]);
            g1.y = tanhf(accG[mf][nf][3]);
            *(float2*)(out + o0)        = f0;
            *(float2*)(out + o1)        = f1;
            *(float2*)(out + HALF + o0) = g0;
            *(float2*)(out + HALF + o1) = g1;
        }
    }
}

// ---------------- launch ----------------------------------------------------
extern "C" void kernel_launch(void* const* d_in, const int* in_sizes, int n_in,
                              void* d_out, int out_size) {
    const float* x     = (const float*)d_in[0];
    const float* x0    = (const float*)d_in[1];
    const float* w     = (const float*)d_in[2];
    const float* d     = (const float*)d_in[3];
    const float* alpha = (const float*)d_in[4];
    const float* fw1   = (const float*)d_in[5];
    const float* fw2   = (const float*)d_in[6];
    const float* fvs   = (const float*)d_in[7];
    const float* fbs   = (const float*)d_in[8];
    const float* gw1   = (const float*)d_in[9];
    const float* gw2   = (const float*)d_in[10];
    const float* gvs   = (const float*)d_in[11];
    const float* gbs   = (const float*)d_in[12];
    const float* convw = (const float*)d_in[13];
    const float* convb = (const float*)d_in[14];
    const float* adj   = (const float*)d_in[15];
    float* out = (float*)d_out;

    cudaFuncSetAttribute(k_gemm, cudaFuncAttributeMaxDynamicSharedMemorySize, GEMM_SMEM);
    cudaFuncSetAttribute(k_final, cudaFuncAttributeMaxDynamicSharedMemorySize, FIN_SMEM);

    k_prep   <<<PB_EVEC + PB_AMIX + PB_TRANSP + PB_SPLIT + PB_XSPL, 256>>>(
                 x, fw1, fw2, gw1, gw2, fvs, gvs, fbs, gbs, adj, convw);
    k_addterm<<<dim3(16, BB), 256>>>(x, x0, w, d, alpha, convb);
    k_sig    <<<dim3(NN, BB, 2), 256>>>();
    k_gemm   <<<dim3(8, 8, BB), 256, GEMM_SMEM>>>(0);
    k_gemm   <<<dim3(8, 8, BB), 256, GEMM_SMEM>>>(1);
    k_soft   <<<dim3(NN, BB), 256>>>();
    k_final  <<<dim3(NN / 128, BB), 256, FIN_SMEM>>>(out);
}

// round 10
// speedup vs baseline: 1.0029x; 1.0029x over previous
#include <cuda_runtime.h>
#include <cuda_bf16.h>
#include <math.h>
#include <stdint.h>

#define BB 32
#define NN 1024
#define DD 64
#define HALF (BB*NN*DD)
#define SZB ((size_t)BB*NN*NN)

// ---------------- scratch (device globals; no allocation allowed) ----------
static __device__ __nv_bfloat16 g_sHi[2*SZB];  // phase1: sigmoid hi [which][b][n][j]
                                               // phase2: EmHi [0,SZB) , EmLo [SZB,2SZB)
static __device__ __nv_bfloat16 g_sLo[2*SZB];  // phase1: sigmoid lo
                                               // phase2: NhHi, NhLo
static __device__ __nv_bfloat16 g_vHi[(size_t)2*NN*NN];
static __device__ __nv_bfloat16 g_vLo[(size_t)2*NN*NN];
static __device__ __nv_bfloat16 g_xH[(size_t)BB*NN*DD];
static __device__ __nv_bfloat16 g_xL[(size_t)BB*NN*DD];
static __device__ float g_EF  [SZB];
static __device__ float g_NG  [SZB];
static __device__ float g_bsTf[(size_t)NN*NN];
static __device__ float g_bsTg[(size_t)NN*NN];
static __device__ float g_e1f[BB*NN], g_e2f[BB*NN], g_e1g[BB*NN], g_e2g[BB*NN];
static __device__ float g_Amix[NN*NN];
static __device__ float g_add[(size_t)BB*NN*DD];   // xw + cb + x0*sig(alpha)

__device__ __forceinline__ float sigm(float v) { return 1.0f / (1.0f + __expf(-v)); }
__device__ __forceinline__ uint32_t smem_u32(const void* p) {
    uint32_t a;
    asm("{ .reg .u64 t; cvta.to.shared.u64 t, %1; cvt.u32.u64 %0, t; }" : "=r"(a) : "l"(p));
    return a;
}
__device__ __forceinline__ void bf16_split(float x, __nv_bfloat16& hi, __nv_bfloat16& lo) {
    hi = __float2bfloat16(x);
    lo = __float2bfloat16(x - __bfloat162float(hi));
}
__device__ __forceinline__ void mma16(float* c, const uint32_t* a, const uint32_t* b) {
    asm volatile("mma.sync.aligned.m16n8k16.row.col.f32.bf16.bf16.f32 "
                 "{%0,%1,%2,%3}, {%4,%5,%6,%7}, {%8,%9}, {%0,%1,%2,%3};"
                 : "+f"(c[0]), "+f"(c[1]), "+f"(c[2]), "+f"(c[3])
                 : "r"(a[0]), "r"(a[1]), "r"(a[2]), "r"(a[3]),
                   "r"(b[0]), "r"(b[1]));
}
__device__ __forceinline__ void ldm_x4(uint32_t* r, uint32_t addr) {
    asm volatile("ldmatrix.sync.aligned.m8n8.x4.shared.b16 {%0,%1,%2,%3}, [%4];"
                 : "=r"(r[0]), "=r"(r[1]), "=r"(r[2]), "=r"(r[3]) : "r"(addr));
}
__device__ __forceinline__ void ldm_x4t(uint32_t* r, uint32_t addr) {
    asm volatile("ldmatrix.sync.aligned.m8n8.x4.trans.shared.b16 {%0,%1,%2,%3}, [%4];"
                 : "=r"(r[0]), "=r"(r[1]), "=r"(r[2]), "=r"(r[3]) : "r"(addr));
}

// ============ kernel 0: fused prep (evec | amix | transp | vs-split | x-split)
#define PB_EVEC   4096
#define PB_AMIX   1024
#define PB_TRANSP 2048
#define PB_SPLIT  2048
#define PB_XSPL   2048
__global__ void __launch_bounds__(256) k_prep(
        const float* __restrict__ x,
        const float* __restrict__ fw1, const float* __restrict__ fw2,
        const float* __restrict__ gw1, const float* __restrict__ gw2,
        const float* __restrict__ fvs, const float* __restrict__ gvs,
        const float* __restrict__ fbs, const float* __restrict__ gbs,
        const float* __restrict__ adj, const float* __restrict__ convw) {
    int bid = blockIdx.x;
    int tid = threadIdx.x;
    if (bid < PB_EVEC) {
        int gwarp = bid * 8 + (tid >> 5);
        int lane  = tid & 31;
        const float* xp = x + (size_t)gwarp * DD;
        float v0 = xp[lane], v1 = xp[lane + 32];
        float s0 = v0 * fw1[lane] + v1 * fw1[lane + 32];
        float s1 = v0 * fw2[lane] + v1 * fw2[lane + 32];
        float s2 = v0 * gw1[lane] + v1 * gw1[lane + 32];
        float s3 = v0 * gw2[lane] + v1 * gw2[lane + 32];
        #pragma unroll
        for (int o = 16; o > 0; o >>= 1) {
            s0 += __shfl_xor_sync(0xffffffffu, s0, o);
            s1 += __shfl_xor_sync(0xffffffffu, s1, o);
            s2 += __shfl_xor_sync(0xffffffffu, s2, o);
            s3 += __shfl_xor_sync(0xffffffffu, s3, o);
        }
        if (lane == 0) {
            g_e1f[gwarp] = s0; g_e2f[gwarp] = s1;
            g_e1g[gwarp] = s2; g_e2g[gwarp] = s3;
        }
        return;
    }
    bid -= PB_EVEC;
    if (bid < PB_AMIX) {
        int t = bid * 256 + tid;
        int base = t * 4;
        int i = base >> 10;
        int j = base & (NN - 1);
        float c0 = convw[0], c1 = convw[1];
        float dsub = c0 + c1;
        float4 a0 = *(const float4*)(adj + base);
        float4 a1 = *(const float4*)(adj + (size_t)NN * NN + base);
        float4 r;
        r.x = c0 * a0.x + c1 * a1.x - ((i == j + 0) ? dsub : 0.0f);
        r.y = c0 * a0.y + c1 * a1.y - ((i == j + 1) ? dsub : 0.0f);
        r.z = c0 * a0.z + c1 * a1.z - ((i == j + 2) ? dsub : 0.0f);
        r.w = c0 * a0.w + c1 * a1.w - ((i == j + 3) ? dsub : 0.0f);
        *(float4*)(g_Amix + base) = r;
        return;
    }
    bid -= PB_AMIX;
    if (bid < PB_TRANSP) {
        __shared__ float t[32][33];
        int z = bid >> 10;
        int rem = bid & 1023;
        int x0t = (rem & 31) * 32, y0t = (rem >> 5) * 32;
        const float* src = z ? gbs : fbs;
        float* dst = z ? g_bsTg : g_bsTf;
        int tx = tid & 31, ty = tid >> 5;
        #pragma unroll
        for (int r = ty; r < 32; r += 8)
            t[r][tx] = src[(size_t)(y0t + r) * NN + x0t + tx];
        __syncthreads();
        #pragma unroll
        for (int r = ty; r < 32; r += 8)
            dst[(size_t)(x0t + r) * NN + y0t + tx] = t[tx][r];
        return;
    }
    bid -= PB_TRANSP;
    if (bid < PB_SPLIT) {
        int t = bid * 256 + tid;
        int which = t >= (NN * NN / 4);
        int e = which ? t - NN * NN / 4 : t;
        const float4* src = (const float4*)(which ? gvs : fvs);
        float4 a = src[e];
        __nv_bfloat16 h0, l0, h1, l1, h2, l2, h3, l3;
        bf16_split(a.x, h0, l0); bf16_split(a.y, h1, l1);
        bf16_split(a.z, h2, l2); bf16_split(a.w, h3, l3);
        size_t off = (size_t)which * NN * NN + (size_t)e * 4;
        __nv_bfloat162* ph = (__nv_bfloat162*)(g_vHi + off);
        __nv_bfloat162* pl = (__nv_bfloat162*)(g_vLo + off);
        ph[0] = __nv_bfloat162{h0, h1}; ph[1] = __nv_bfloat162{h2, h3};
        pl[0] = __nv_bfloat162{l0, l1}; pl[1] = __nv_bfloat162{l2, l3};
        return;
    }
    bid -= PB_SPLIT;
    {
        int e = bid * 256 + tid;          // over BB*NN*DD/4 float4s
        float4 a = ((const float4*)x)[e];
        __nv_bfloat16 h0, l0, h1, l1, h2, l2, h3, l3;
        bf16_split(a.x, h0, l0); bf16_split(a.y, h1, l1);
        bf16_split(a.z, h2, l2); bf16_split(a.w, h3, l3);
        size_t off = (size_t)e * 4;
        __nv_bfloat162* ph = (__nv_bfloat162*)(g_xH + off);
        __nv_bfloat162* pl = (__nv_bfloat162*)(g_xL + off);
        ph[0] = __nv_bfloat162{h0, h1}; ph[1] = __nv_bfloat162{h2, h3};
        pl[0] = __nv_bfloat162{l0, l1}; pl[1] = __nv_bfloat162{l2, l3};
        return;
    }
}

// ============ kernel addterm: g_add = xr@W_hat + cb + x0*sigm(alpha) =======
#define XSTRIDE 68   // floats; 272B = multiple of 16 -> aligned float4 rows
__global__ void __launch_bounds__(256) k_addterm(
        const float* __restrict__ x, const float* __restrict__ x0,
        const float* __restrict__ w, const float* __restrict__ d,
        const float* __restrict__ alpha, const float* __restrict__ convb) {
    __shared__ float sWh[64 * 64];
    __shared__ float sXi[64 * XSTRIDE];
    int b = blockIdx.y, i0 = blockIdx.x * 64;
    int tid = threadIdx.x;

    #pragma unroll
    for (int e = 0; e < 16; e++) {
        int idx = tid + e * 256;
        int i = idx >> 6, j = idx & 63;
        float s = 0.0f;
        #pragma unroll 8
        for (int k = 0; k < DD; k++) {
            float dc = fminf(fmaxf(d[k], 0.0f), 1.0f);
            s += w[i * DD + k] * dc * w[j * DD + k];
        }
        sWh[idx] = s - ((i == j) ? 1.0f : 0.0f);
    }
    #pragma unroll
    for (int q = 0; q < 4; q++) {
        int lin = tid + q * 256;
        int row = lin >> 4, cc = (lin & 15) * 4;
        *(float4*)&sXi[row * XSTRIDE + cc] =
            *(const float4*)(x + (size_t)(b * NN + i0 + row) * DD + cc);
    }
    __syncthreads();

    int il = tid >> 2, c0 = (tid & 3) * 16;
    float acc[16];
    #pragma unroll
    for (int q = 0; q < 16; q++) acc[q] = 0.0f;
    #pragma unroll 8
    for (int k = 0; k < DD; k++) {
        float xik = sXi[il * XSTRIDE + k];
        #pragma unroll
        for (int q = 0; q < 4; q++) {
            float4 wv = *(float4*)&sWh[k * 64 + c0 + q * 4];
            acc[q * 4 + 0] += xik * wv.x; acc[q * 4 + 1] += xik * wv.y;
            acc[q * 4 + 2] += xik * wv.z; acc[q * 4 + 3] += xik * wv.w;
        }
    }
    float cb = convb[0];
    float sa = sigm(alpha[i0 + il]);
    size_t obase = ((size_t)b * NN + i0 + il) * DD + c0;
    #pragma unroll
    for (int q = 0; q < 4; q++) {
        float4 x0v = *(const float4*)(x0 + obase + q * 4);
        float4 r;
        r.x = acc[q * 4 + 0] + cb + x0v.x * sa;
        r.y = acc[q * 4 + 1] + cb + x0v.y * sa;
        r.z = acc[q * 4 + 2] + cb + x0v.z * sa;
        r.w = acc[q * 4 + 3] + cb + x0v.w * sa;
        *(float4*)(g_add + obase + q * 4) = r;
    }
}

// -------- kernel sig: S[b,n,j] = sigmoid(e2[b,n]*e1[b,j] + bsT[n,j]), hi/lo
__global__ void k_sig(void) {
    int n = blockIdx.x, b = blockIdx.y, which = blockIdx.z;
    int j = threadIdx.x * 4;
    const float* e1 = which ? g_e1g : g_e1f;
    const float* e2 = which ? g_e2g : g_e2f;
    const float* bsT = (which ? g_bsTg : g_bsTf) + (size_t)n * NN + j;
    size_t off = (((size_t)which * BB + b) * NN + n) * NN + j;
    float  a   = e2[b * NN + n];
    float4 e1v = *(const float4*)(e1 + b * NN + j);
    float4 bv  = *(const float4*)bsT;
    float sx = sigm(a * e1v.x + bv.x);
    float sy = sigm(a * e1v.y + bv.y);
    float sz = sigm(a * e1v.z + bv.z);
    float sw = sigm(a * e1v.w + bv.w);
    __nv_bfloat16 h0, l0, h1, l1, h2, l2, h3, l3;
    bf16_split(sx, h0, l0); bf16_split(sy, h1, l1);
    bf16_split(sz, h2, l2); bf16_split(sw, h3, l3);
    __nv_bfloat162* ph = (__nv_bfloat162*)(g_sHi + off);
    __nv_bfloat162* pl = (__nv_bfloat162*)(g_sLo + off);
    ph[0] = __nv_bfloat162{h0, h1}; ph[1] = __nv_bfloat162{h2, h3};
    pl[0] = __nv_bfloat162{l0, l1}; pl[1] = __nv_bfloat162{l2, l3};
}

// ---------------- kernel gemm: bf16x3 mma.sync batched GEMM ----------------
// CTA 128x256, 512 threads (16 warps, 2x8), warp tile 64x32, K-tile 32.
#define KT     32
#define STRB   80
#define A_TILE_B (128*STRB)              // 10240
#define B_TILE_B (256*STRB)              // 20480
#define STAGE_BYTES (2*A_TILE_B + 2*B_TILE_B)   // 61440
#define GEMM_SMEM  (2*STAGE_BYTES)              // 122880

__global__ void __launch_bounds__(512, 1) k_gemm() {
    extern __shared__ char smg[];
    uint32_t smb = smem_u32(smg);
    int tid = threadIdx.x;
    int z = blockIdx.z;
    int b = z & (BB - 1);
    int which = z >> 5;
    const __nv_bfloat16* __restrict__ Ahi = g_vHi + (size_t)which * NN * NN;
    const __nv_bfloat16* __restrict__ Alo = g_vLo + (size_t)which * NN * NN;
    const __nv_bfloat16* __restrict__ Bhi = g_sHi + ((size_t)which * BB + b) * NN * NN;
    const __nv_bfloat16* __restrict__ Blo = g_sLo + ((size_t)which * BB + b) * NN * NN;
    float* __restrict__ C = (which ? g_NG : g_EF) + (size_t)b * NN * NN;
    int i0 = blockIdx.y * 128, n0 = blockIdx.x * 256;

    int wid = tid >> 5, lane = tid & 31;
    int gid = lane >> 2, tg = lane & 3;
    int wm = (wid & 1) * 64, wn = (wid >> 1) * 32;   // 2 x 8 warp grid

    int lr    = lane & 7;
    int lrow8 = (lane >> 3) & 1;
    int lk8   = (lane >> 4) & 1;
    uint32_t aoff = (uint32_t)((wm + lrow8 * 8 + lr) * STRB + lk8 * 16);
    uint32_t boff = (uint32_t)((wn + lrow8 * 8 + lr) * STRB + lk8 * 16);

    // cp.async mapping: 3072 chunks of 16B per stage, 6 per thread
    int slot_tile[6], slot_row[6], slot_ch[6];
    #pragma unroll
    for (int it = 0; it < 6; it++) {
        int slot = tid + it * 512;
        if (slot < 1024) {                 // A tiles (hi/lo), 512 chunks each
            slot_tile[it] = slot >> 9;     // 0=Ahi,1=Alo
            int r2 = slot & 511;
            slot_row[it] = r2 >> 2;
            slot_ch[it]  = r2 & 3;
        } else {                           // B tiles (hi/lo), 1024 chunks each
            int s2 = slot - 1024;
            slot_tile[it] = 2 + (s2 >> 10);  // 2=Bhi,3=Blo
            int r2 = s2 & 1023;
            slot_row[it] = r2 >> 2;
            slot_ch[it]  = r2 & 3;
        }
    }

    float acc[4][4][4];
    #pragma unroll
    for (int mf = 0; mf < 4; mf++)
        #pragma unroll
        for (int nf = 0; nf < 4; nf++)
            #pragma unroll
            for (int q = 0; q < 4; q++) acc[mf][nf][q] = 0.0f;

    #define G_ISSUE(S) do {                                                      \
        uint32_t sb_ = smb + ((S) & 1) * STAGE_BYTES;                            \
        int kc_ = (S) * KT;                                                      \
        _Pragma("unroll")                                                        \
        for (int it = 0; it < 6; it++) {                                         \
            int tile = slot_tile[it], row = slot_row[it], ch = slot_ch[it];      \
            const __nv_bfloat16* src;                                            \
            uint32_t toff;                                                       \
            if (tile == 0)      { src = Ahi + (size_t)(i0 + row) * NN; toff = 0; }            \
            else if (tile == 1) { src = Alo + (size_t)(i0 + row) * NN; toff = A_TILE_B; }     \
            else if (tile == 2) { src = Bhi + (size_t)(n0 + row) * NN; toff = 2 * A_TILE_B; } \
            else                { src = Blo + (size_t)(n0 + row) * NN; toff = 2 * A_TILE_B + B_TILE_B; } \
            const char* gp = (const char*)(src + kc_) + ch * 16;                 \
            uint32_t sp = sb_ + toff + (uint32_t)(row * STRB + ch * 16);         \
            asm volatile("cp.async.ca.shared.global [%0], [%1], 16;"             \
                         :: "r"(sp), "l"(gp));                                   \
        }                                                                        \
        asm volatile("cp.async.commit_group;");                                  \
    } while (0)

    G_ISSUE(0);
    for (int s = 0; s < NN / KT; s++) {
        if (s < NN / KT - 1) {
            G_ISSUE(s + 1);
            asm volatile("cp.async.wait_group 1;");
        } else {
            asm volatile("cp.async.wait_group 0;");
        }
        __syncthreads();
        uint32_t base = smb + (s & 1) * STAGE_BYTES;
        uint32_t tAh = base, tAl = base + A_TILE_B;
        uint32_t tBh = base + 2 * A_TILE_B, tBl = tBh + B_TILE_B;

        #pragma unroll
        for (int kh = 0; kh < 2; kh++) {
            uint32_t kb = (uint32_t)(kh * 32);
            uint32_t ah[4][4], al[4][4], bh[4][2], bl[4][2];
            #pragma unroll
            for (int mf = 0; mf < 4; mf++) {
                uint32_t ao = aoff + (uint32_t)(mf * 16 * STRB) + kb;
                ldm_x4(ah[mf], tAh + ao);
                ldm_x4(al[mf], tAl + ao);
            }
            #pragma unroll
            for (int p = 0; p < 2; p++) {
                uint32_t bo = boff + (uint32_t)(p * 16 * STRB) + kb;
                uint32_t th[4], tl[4];
                ldm_x4(th, tBh + bo);
                ldm_x4(tl, tBl + bo);
                bh[2*p][0]   = th[0]; bh[2*p][1]   = th[2];
                bh[2*p+1][0] = th[1]; bh[2*p+1][1] = th[3];
                bl[2*p][0]   = tl[0]; bl[2*p][1]   = tl[2];
                bl[2*p+1][0] = tl[1]; bl[2*p+1][1] = tl[3];
            }
            #pragma unroll
            for (int mf = 0; mf < 4; mf++)
                #pragma unroll
                for (int nf = 0; nf < 4; nf++) {
                    mma16(acc[mf][nf], ah[mf], bh[nf]);
                    mma16(acc[mf][nf], ah[mf], bl[nf]);
                    mma16(acc[mf][nf], al[mf], bh[nf]);
                }
        }
        __syncthreads();
    }

    #pragma unroll
    for (int mf = 0; mf < 4; mf++) {
        #pragma unroll
        for (int nf = 0; nf < 4; nf++) {
            int row = i0 + wm + mf * 16 + gid;
            int col = n0 + wn + nf * 8 + tg * 2;
            float2 v0 = make_float2(acc[mf][nf][0], acc[mf][nf][1]);
            float2 v1 = make_float2(acc[mf][nf][2], acc[mf][nf][3]);
            *(float2*)(C + (size_t)row * NN + col)       = v0;
            *(float2*)(C + (size_t)(row + 8) * NN + col) = v1;
        }
    }
}

// ------- kernel soft: row softmax; outputs Em/Nh as bf16 hi/lo aliases -----
__global__ void k_soft() {
    int i = blockIdx.x, b = blockIdx.y;
    size_t ro = ((size_t)b * NN + i) * NN;
    int c = threadIdx.x * 4;
    int wid = threadIdx.x >> 5, lane = threadIdx.x & 31;
    __shared__ float sE[8], sN[8];

    float4 ev = *(float4*)(g_EF + ro + c);
    float4 nv = *(float4*)(g_NG + ro + c);

    float mE = fmaxf(fmaxf(ev.x, ev.y), fmaxf(ev.z, ev.w));
    float mN = fmaxf(fmaxf(nv.x, nv.y), fmaxf(nv.z, nv.w));
    #pragma unroll
    for (int o = 16; o > 0; o >>= 1) {
        mE = fmaxf(mE, __shfl_xor_sync(0xffffffffu, mE, o));
        mN = fmaxf(mN, __shfl_xor_sync(0xffffffffu, mN, o));
    }
    if (lane == 0) { sE[wid] = mE; sN[wid] = mN; }
    __syncthreads();
    mE = sE[0]; mN = sN[0];
    #pragma unroll
    for (int wv = 1; wv < 8; wv++) { mE = fmaxf(mE, sE[wv]); mN = fmaxf(mN, sN[wv]); }
    __syncthreads();

    float4 eE, eN;
    eE.x = __expf(ev.x - mE); eE.y = __expf(ev.y - mE);
    eE.z = __expf(ev.z - mE); eE.w = __expf(ev.w - mE);
    eN.x = __expf(nv.x - mN); eN.y = __expf(nv.y - mN);
    eN.z = __expf(nv.z - mN); eN.w = __expf(nv.w - mN);
    float sumE = eE.x + eE.y + eE.z + eE.w;
    float sumN = eN.x + eN.y + eN.z + eN.w;
    #pragma unroll
    for (int o = 16; o > 0; o >>= 1) {
        sumE += __shfl_xor_sync(0xffffffffu, sumE, o);
        sumN += __shfl_xor_sync(0xffffffffu, sumN, o);
    }
    if (lane == 0) { sE[wid] = sumE; sN[wid] = sumN; }
    __syncthreads();
    sumE = 0.0f; sumN = 0.0f;
    #pragma unroll
    for (int wv = 0; wv < 8; wv++) { sumE += sE[wv]; sumN += sN[wv]; }

    float invE = __fdividef(1.0f, sumE);
    float invN = __fdividef(1.0f, sumN);

    float4 se;
    se.x = eE.x * invE; se.y = eE.y * invE; se.z = eE.z * invE; se.w = eE.w * invE;
    float4 nh;
    nh.x = __fdividef(eN.x * invN, se.x + 1e-5f);
    nh.y = __fdividef(eN.y * invN, se.y + 1e-5f);
    nh.z = __fdividef(eN.z * invN, se.z + 1e-5f);
    nh.w = __fdividef(eN.w * invN, se.w + 1e-5f);

    float4 am = *(float4*)(g_Amix + (size_t)i * NN + c);
    float4 em;
    em.x = se.x + am.x - ((c + 0 == i) ? 1.0f : 0.0f);
    em.y = se.y + am.y - ((c + 1 == i) ? 1.0f : 0.0f);
    em.z = se.z + am.z - ((c + 2 == i) ? 1.0f : 0.0f);
    em.w = se.w + am.w - ((c + 3 == i) ? 1.0f : 0.0f);

    __nv_bfloat16 h0, l0, h1, l1, h2, l2, h3, l3;
    bf16_split(em.x, h0, l0); bf16_split(em.y, h1, l1);
    bf16_split(em.z, h2, l2); bf16_split(em.w, h3, l3);
    *(__nv_bfloat162*)(g_sHi + ro + c)           = __nv_bfloat162{h0, h1};
    *(__nv_bfloat162*)(g_sHi + ro + c + 2)       = __nv_bfloat162{h2, h3};
    *(__nv_bfloat162*)(g_sHi + SZB + ro + c)     = __nv_bfloat162{l0, l1};
    *(__nv_bfloat162*)(g_sHi + SZB + ro + c + 2) = __nv_bfloat162{l2, l3};
    bf16_split(nh.x, h0, l0); bf16_split(nh.y, h1, l1);
    bf16_split(nh.z, h2, l2); bf16_split(nh.w, h3, l3);
    *(__nv_bfloat162*)(g_sLo + ro + c)           = __nv_bfloat162{h0, h1};
    *(__nv_bfloat162*)(g_sLo + ro + c + 2)       = __nv_bfloat162{h2, h3};
    *(__nv_bfloat162*)(g_sLo + SZB + ro + c)     = __nv_bfloat162{l0, l1};
    *(__nv_bfloat162*)(g_sLo + SZB + ro + c + 2) = __nv_bfloat162{l2, l3};
}

// --------- kernel final: f = tanh(Em@xr + add), g = tanh(Nh@xr) (bf16x3 MMA)
#define F_STR    80
#define F_TILE   (128*F_STR)             // 10240
#define F_XSTR   144
#define F_XTILE  (32*F_XSTR)             // 4608
#define F_XOFF   (4*F_TILE)              // 40960
#define F_STAGE  (F_XOFF + 2*F_XTILE)    // 50176
#define FIN_SMEM (2*F_STAGE)             // 100352

__global__ void __launch_bounds__(256) k_final(float* __restrict__ out) {
    extern __shared__ char smf[];
    uint32_t smb = smem_u32(smf);
    int tid = threadIdx.x;
    int b = blockIdx.y, i0 = blockIdx.x * 128;
    const __nv_bfloat16* EmH = g_sHi + (size_t)b * NN * NN;
    const __nv_bfloat16* EmL = EmH + SZB;
    const __nv_bfloat16* NhH = g_sLo + (size_t)b * NN * NN;
    const __nv_bfloat16* NhL = NhH + SZB;
    const __nv_bfloat16* xHb = g_xH + (size_t)b * NN * DD;
    const __nv_bfloat16* xLb = g_xL + (size_t)b * NN * DD;

    int wid = tid >> 5, lane = tid & 31;
    int gid = lane >> 2, tg = lane & 3;
    int wm = (wid & 3) * 32, wn = (wid >> 2) * 32;

    int lr    = lane & 7;
    int lrow8 = (lane >> 3) & 1;
    int lk8   = (lane >> 4) & 1;
    uint32_t aoff = (uint32_t)((wm + lrow8 * 8 + lr) * F_STR + lk8 * 16);
    int quad = lane >> 3;
    int xkrow = (quad & 1) * 8 + lr;
    int xn8   = (quad >> 1) * 8;

    float accF[2][4][4], accG[2][4][4];
    #pragma unroll
    for (int mf = 0; mf < 2; mf++)
        #pragma unroll
        for (int nf = 0; nf < 4; nf++)
            #pragma unroll
            for (int q = 0; q < 4; q++) { accF[mf][nf][q] = 0.0f; accG[mf][nf][q] = 0.0f; }

    #define F_ISSUE(S) do {                                                      \
        uint32_t sb_ = smb + ((S) & 1) * F_STAGE;                                \
        int jc_ = (S) * 32;                                                      \
        _Pragma("unroll")                                                        \
        for (int it = 0; it < 10; it++) {                                        \
            int slot = tid + it * 256;                                           \
            if (slot < 2048) {                                                   \
                int tile = slot >> 9;                                            \
                int r2 = slot & 511;                                             \
                int row = r2 >> 2, ch = r2 & 3;                                  \
                const __nv_bfloat16* src =                                       \
                    (tile == 0) ? EmH : (tile == 1) ? EmL :                      \
                    (tile == 2) ? NhH : NhL;                                     \
                const char* gp = (const char*)(src + (size_t)(i0 + row) * NN + jc_ + ch * 8); \
                uint32_t sp = sb_ + (uint32_t)(tile * F_TILE + row * F_STR + ch * 16); \
                asm volatile("cp.async.ca.shared.global [%0], [%1], 16;"         \
                             :: "r"(sp), "l"(gp));                               \
            } else {                                                             \
                int t2 = slot - 2048;                                            \
                int xt = t2 >> 8;                                                \
                int r2 = t2 & 255;                                               \
                int row = r2 >> 3, ch = r2 & 7;                                  \
                const __nv_bfloat16* src = xt ? xLb : xHb;                       \
                const char* gp = (const char*)(src + (size_t)(jc_ + row) * DD + ch * 8); \
                uint32_t sp = sb_ + (uint32_t)(F_XOFF + xt * F_XTILE + row * F_XSTR + ch * 16); \
                asm volatile("cp.async.ca.shared.global [%0], [%1], 16;"         \
                             :: "r"(sp), "l"(gp));                               \
            }                                                                    \
        }                                                                        \
        asm volatile("cp.async.commit_group;");                                  \
    } while (0)

    F_ISSUE(0);
    for (int s = 0; s < NN / 32; s++) {
        if (s < NN / 32 - 1) {
            F_ISSUE(s + 1);
            asm volatile("cp.async.wait_group 1;");
        } else {
            asm volatile("cp.async.wait_group 0;");
        }
        __syncthreads();
        uint32_t base = smb + (s & 1) * F_STAGE;
        uint32_t tEh = base, tEl = base + F_TILE;
        uint32_t tNh = base + 2 * F_TILE, tNl = base + 3 * F_TILE;
        uint32_t tXh = base + F_XOFF, tXl = base + F_XOFF + F_XTILE;

        #pragma unroll
        for (int kh = 0; kh < 2; kh++) {
            uint32_t kb = (uint32_t)(kh * 32);
            uint32_t bxh[4][2], bxl[4][2];
            #pragma unroll
            for (int p = 0; p < 2; p++) {
                uint32_t xad = (uint32_t)((kh * 16 + xkrow) * F_XSTR + (wn + p * 16 + xn8) * 2);
                uint32_t th[4], tl[4];
                ldm_x4t(th, tXh + xad);
                ldm_x4t(tl, tXl + xad);
                bxh[2*p][0]   = th[0]; bxh[2*p][1]   = th[1];
                bxh[2*p+1][0] = th[2]; bxh[2*p+1][1] = th[3];
                bxl[2*p][0]   = tl[0]; bxl[2*p][1]   = tl[1];
                bxl[2*p+1][0] = tl[2]; bxl[2*p+1][1] = tl[3];
            }
            {
                uint32_t ah[2][4], al[2][4];
                #pragma unroll
                for (int mf = 0; mf < 2; mf++) {
                    uint32_t ao = aoff + (uint32_t)(mf * 16 * F_STR) + kb;
                    ldm_x4(ah[mf], tEh + ao);
                    ldm_x4(al[mf], tEl + ao);
                }
                #pragma unroll
                for (int mf = 0; mf < 2; mf++)
                    #pragma unroll
                    for (int nf = 0; nf < 4; nf++) {
                        mma16(accF[mf][nf], ah[mf], bxh[nf]);
                        mma16(accF[mf][nf], ah[mf], bxl[nf]);
                        mma16(accF[mf][nf], al[mf], bxh[nf]);
                    }
            }
            {
                uint32_t ah[2][4], al[2][4];
                #pragma unroll
                for (int mf = 0; mf < 2; mf++) {
                    uint32_t ao = aoff + (uint32_t)(mf * 16 * F_STR) + kb;
                    ldm_x4(ah[mf], tNh + ao);
                    ldm_x4(al[mf], tNl + ao);
                }
                #pragma unroll
                for (int mf = 0; mf < 2; mf++)
                    #pragma unroll
                    for (int nf = 0; nf < 4; nf++) {
                        mma16(accG[mf][nf], ah[mf], bxh[nf]);
                        mma16(accG[mf][nf], ah[mf], bxl[nf]);
                        mma16(accG[mf][nf], al[mf], bxh[nf]);
                    }
            }
        }
        __syncthreads();
    }

    #pragma unroll
    for (int mf = 0; mf < 2; mf++) {
        #pragma unroll
        for (int nf = 0; nf < 4; nf++) {
            int row = i0 + wm + mf * 16 + gid;
            int col = wn + nf * 8 + tg * 2;
            size_t o0 = ((size_t)b * NN + row) * DD + col;
            size_t o1 = ((size_t)b * NN + row + 8) * DD + col;
            float2 a0 = *(const float2*)(g_add + o0);
            float2 a1 = *(const float2*)(g_add + o1);
            float2 f0, f1, g0, g1;
            f0.x = tanhf(accF[mf][nf][0] + a0.x);
            f0.y = tanhf(accF[mf][nf][1] + a0.y);
            f1.x = tanhf(accF[mf][nf][2] + a1.x);
            f1.y = tanhf(accF[mf][nf][3] + a1.y);
            g0.x = tanhf(accG[mf][nf][0]);
            g0.y = tanhf(accG[mf][nf][1]);
            g1.x = tanhf(accG[mf][nf][2]);
            g1.y = tanhf(accG[mf][nf][3]);
            *(float2*)(out + o0)        = f0;
            *(float2*)(out + o1)        = f1;
            *(float2*)(out + HALF + o0) = g0;
            *(float2*)(out + HALF + o1) = g1;
        }
    }
}

// ---------------- launch ----------------------------------------------------
extern "C" void kernel_launch(void* const* d_in, const int* in_sizes, int n_in,
                              void* d_out, int out_size) {
    const float* x     = (const float*)d_in[0];
    const float* x0    = (const float*)d_in[1];
    const float* w     = (const float*)d_in[2];
    const float* d     = (const float*)d_in[3];
    const float* alpha = (const float*)d_in[4];
    const float* fw1   = (const float*)d_in[5];
    const float* fw2   = (const float*)d_in[6];
    const float* fvs   = (const float*)d_in[7];
    const float* fbs   = (const float*)d_in[8];
    const float* gw1   = (const float*)d_in[9];
    const float* gw2   = (const float*)d_in[10];
    const float* gvs   = (const float*)d_in[11];
    const float* gbs   = (const float*)d_in[12];
    const float* convw = (const float*)d_in[13];
    const float* convb = (const float*)d_in[14];
    const float* adj   = (const float*)d_in[15];
    float* out = (float*)d_out;

    cudaFuncSetAttribute(k_gemm, cudaFuncAttributeMaxDynamicSharedMemorySize, GEMM_SMEM);
    cudaFuncSetAttribute(k_final, cudaFuncAttributeMaxDynamicSharedMemorySize, FIN_SMEM);

    k_prep   <<<PB_EVEC + PB_AMIX + PB_TRANSP + PB_SPLIT + PB_XSPL, 256>>>(
                 x, fw1, fw2, gw1, gw2, fvs, gvs, fbs, gbs, adj, convw);
    k_addterm<<<dim3(16, BB), 256>>>(x, x0, w, d, alpha, convb);
    k_sig    <<<dim3(NN, BB, 2), 256>>>();
    k_gemm   <<<dim3(NN / 256, NN / 128, 2 * BB), 512, GEMM_SMEM>>>();
    k_soft   <<<dim3(NN, BB), 256>>>();
    k_final  <<<dim3(NN / 128, BB), 256, FIN_SMEM>>>(out);
}

// round 11
// speedup vs baseline: 1.0313x; 1.0284x over previous
#include <cuda_runtime.h>
#include <cuda_bf16.h>
#include <math.h>
#include <stdint.h>

#define BB 32
#define NN 1024
#define DD 64
#define HALF (BB*NN*DD)
#define SZB ((size_t)BB*NN*NN)

// ---------------- scratch (device globals; no allocation allowed) ----------
static __device__ __nv_bfloat16 g_sHi[2*SZB];  // phase1: sigmoid hi [which][b][n][j]
                                               // phase2: EmHi [0,SZB), EmLo [SZB,2SZB)
static __device__ __nv_bfloat16 g_sLo[2*SZB];  // phase1: sigmoid lo ; phase2: NhHi, NhLo
static __device__ __nv_bfloat16 g_vHi[(size_t)2*NN*NN];
static __device__ __nv_bfloat16 g_vLo[(size_t)2*NN*NN];
static __device__ __nv_bfloat16 g_xH[(size_t)BB*NN*DD];
static __device__ __nv_bfloat16 g_xL[(size_t)BB*NN*DD];
static __device__ float g_EF  [SZB];
static __device__ float g_NG  [SZB];
static __device__ float g_bsTf[(size_t)NN*NN];
static __device__ float g_bsTg[(size_t)NN*NN];
static __device__ float g_e1f[BB*NN], g_e2f[BB*NN], g_e1g[BB*NN], g_e2g[BB*NN];
static __device__ float g_Amix[NN*NN];
static __device__ float g_add[(size_t)BB*NN*DD];   // xw + cb + x0*sig(alpha)

__device__ __forceinline__ float sigm(float v) { return 1.0f / (1.0f + __expf(-v)); }
__device__ __forceinline__ uint32_t smem_u32(const void* p) {
    uint32_t a;
    asm("{ .reg .u64 t; cvta.to.shared.u64 t, %1; cvt.u32.u64 %0, t; }" : "=r"(a) : "l"(p));
    return a;
}
__device__ __forceinline__ void bf16_split(float x, __nv_bfloat16& hi, __nv_bfloat16& lo) {
    hi = __float2bfloat16(x);
    lo = __float2bfloat16(x - __bfloat162float(hi));
}
__device__ __forceinline__ void mma16(float* c, const uint32_t* a, const uint32_t* b) {
    asm volatile("mma.sync.aligned.m16n8k16.row.col.f32.bf16.bf16.f32 "
                 "{%0,%1,%2,%3}, {%4,%5,%6,%7}, {%8,%9}, {%0,%1,%2,%3};"
                 : "+f"(c[0]), "+f"(c[1]), "+f"(c[2]), "+f"(c[3])
                 : "r"(a[0]), "r"(a[1]), "r"(a[2]), "r"(a[3]),
                   "r"(b[0]), "r"(b[1]));
}
__device__ __forceinline__ void ldm_x4(uint32_t* r, uint32_t addr) {
    asm volatile("ldmatrix.sync.aligned.m8n8.x4.shared.b16 {%0,%1,%2,%3}, [%4];"
                 : "=r"(r[0]), "=r"(r[1]), "=r"(r[2]), "=r"(r[3]) : "r"(addr));
}
__device__ __forceinline__ void ldm_x4t(uint32_t* r, uint32_t addr) {
    asm volatile("ldmatrix.sync.aligned.m8n8.x4.trans.shared.b16 {%0,%1,%2,%3}, [%4];"
                 : "=r"(r[0]), "=r"(r[1]), "=r"(r[2]), "=r"(r[3]) : "r"(addr));
}

// ---------------- kernel: e1/e2 row dots -----------------------------------
__global__ void k_evec(const float* __restrict__ x,
                       const float* __restrict__ fw1, const float* __restrict__ fw2,
                       const float* __restrict__ gw1, const float* __restrict__ gw2) {
    int gwarp = (blockIdx.x * blockDim.x + threadIdx.x) >> 5;
    int lane  = threadIdx.x & 31;
    const float* xp = x + (size_t)gwarp * DD;
    float v0 = xp[lane], v1 = xp[lane + 32];
    float s0 = v0 * fw1[lane] + v1 * fw1[lane + 32];
    float s1 = v0 * fw2[lane] + v1 * fw2[lane + 32];
    float s2 = v0 * gw1[lane] + v1 * gw1[lane + 32];
    float s3 = v0 * gw2[lane] + v1 * gw2[lane + 32];
    #pragma unroll
    for (int o = 16; o > 0; o >>= 1) {
        s0 += __shfl_xor_sync(0xffffffffu, s0, o);
        s1 += __shfl_xor_sync(0xffffffffu, s1, o);
        s2 += __shfl_xor_sync(0xffffffffu, s2, o);
        s3 += __shfl_xor_sync(0xffffffffu, s3, o);
    }
    if (lane == 0) {
        g_e1f[gwarp] = s0; g_e2f[gwarp] = s1;
        g_e1g[gwarp] = s2; g_e2g[gwarp] = s3;
    }
}

// ---------------- kernel: A_mix --------------------------------------------
__global__ void k_amix(const float* __restrict__ adj, const float* __restrict__ convw) {
    int t = blockIdx.x * blockDim.x + threadIdx.x;
    int base = t * 4;
    int i = base >> 10;
    int j = base & (NN - 1);
    float c0 = convw[0], c1 = convw[1];
    float dsub = c0 + c1;
    float4 a0 = *(const float4*)(adj + base);
    float4 a1 = *(const float4*)(adj + (size_t)NN * NN + base);
    float4 r;
    r.x = c0 * a0.x + c1 * a1.x - ((i == j + 0) ? dsub : 0.0f);
    r.y = c0 * a0.y + c1 * a1.y - ((i == j + 1) ? dsub : 0.0f);
    r.z = c0 * a0.z + c1 * a1.z - ((i == j + 2) ? dsub : 0.0f);
    r.w = c0 * a0.w + c1 * a1.w - ((i == j + 3) ? dsub : 0.0f);
    *(float4*)(g_Amix + base) = r;
}

// ---------------- kernel: transpose fbs/gbs --------------------------------
__global__ void k_transp(const float* __restrict__ fbs, const float* __restrict__ gbs) {
    __shared__ float t[32][33];
    const float* src = blockIdx.z ? gbs : fbs;
    float* dst = blockIdx.z ? g_bsTg : g_bsTf;
    int x0 = blockIdx.x * 32, y0 = blockIdx.y * 32;
    #pragma unroll
    for (int r = threadIdx.y; r < 32; r += 8)
        t[r][threadIdx.x] = src[(size_t)(y0 + r) * NN + x0 + threadIdx.x];
    __syncthreads();
    #pragma unroll
    for (int r = threadIdx.y; r < 32; r += 8)
        dst[(size_t)(x0 + r) * NN + y0 + threadIdx.x] = t[threadIdx.x][r];
}

// ---------------- kernel: bf16-split vs ------------------------------------
__global__ void k_split(const float* __restrict__ fvs, const float* __restrict__ gvs) {
    int t = blockIdx.x * blockDim.x + threadIdx.x;
    int which = t >= (NN * NN / 4);
    int e = which ? t - NN * NN / 4 : t;
    const float4* src = (const float4*)(which ? gvs : fvs);
    float4 a = src[e];
    __nv_bfloat16 h0, l0, h1, l1, h2, l2, h3, l3;
    bf16_split(a.x, h0, l0); bf16_split(a.y, h1, l1);
    bf16_split(a.z, h2, l2); bf16_split(a.w, h3, l3);
    size_t off = (size_t)which * NN * NN + (size_t)e * 4;
    __nv_bfloat162* ph = (__nv_bfloat162*)(g_vHi + off);
    __nv_bfloat162* pl = (__nv_bfloat162*)(g_vLo + off);
    ph[0] = __nv_bfloat162{h0, h1}; ph[1] = __nv_bfloat162{h2, h3};
    pl[0] = __nv_bfloat162{l0, l1}; pl[1] = __nv_bfloat162{l2, l3};
}

// ---------------- kernel: bf16-split x -------------------------------------
__global__ void k_xsplit(const float* __restrict__ x) {
    int e = blockIdx.x * blockDim.x + threadIdx.x;   // over BB*NN*DD/4
    float4 a = ((const float4*)x)[e];
    __nv_bfloat16 h0, l0, h1, l1, h2, l2, h3, l3;
    bf16_split(a.x, h0, l0); bf16_split(a.y, h1, l1);
    bf16_split(a.z, h2, l2); bf16_split(a.w, h3, l3);
    size_t off = (size_t)e * 4;
    __nv_bfloat162* ph = (__nv_bfloat162*)(g_xH + off);
    __nv_bfloat162* pl = (__nv_bfloat162*)(g_xL + off);
    ph[0] = __nv_bfloat162{h0, h1}; ph[1] = __nv_bfloat162{h2, h3};
    pl[0] = __nv_bfloat162{l0, l1}; pl[1] = __nv_bfloat162{l2, l3};
}

// ------- kernel addterm: g_add = xr@W_hat + cb + x0*sigm(alpha) ------------
#define XSTRIDE 68   // floats; 272B = multiple of 16 -> aligned float4 rows
__global__ void __launch_bounds__(256) k_addterm(
        const float* __restrict__ x, const float* __restrict__ x0,
        const float* __restrict__ w, const float* __restrict__ d,
        const float* __restrict__ alpha, const float* __restrict__ convb) {
    __shared__ float sWh[64 * 64];
    __shared__ float sXi[64 * XSTRIDE];
    int b = blockIdx.y, i0 = blockIdx.x * 64;
    int tid = threadIdx.x;

    #pragma unroll
    for (int e = 0; e < 16; e++) {
        int idx = tid + e * 256;
        int i = idx >> 6, j = idx & 63;
        float s = 0.0f;
        #pragma unroll 8
        for (int k = 0; k < DD; k++) {
            float dc = fminf(fmaxf(d[k], 0.0f), 1.0f);
            s += w[i * DD + k] * dc * w[j * DD + k];
        }
        sWh[idx] = s - ((i == j) ? 1.0f : 0.0f);
    }
    #pragma unroll
    for (int q = 0; q < 4; q++) {
        int lin = tid + q * 256;
        int row = lin >> 4, cc = (lin & 15) * 4;
        *(float4*)&sXi[row * XSTRIDE + cc] =
            *(const float4*)(x + (size_t)(b * NN + i0 + row) * DD + cc);
    }
    __syncthreads();

    int il = tid >> 2, c0 = (tid & 3) * 16;
    float acc[16];
    #pragma unroll
    for (int q = 0; q < 16; q++) acc[q] = 0.0f;
    #pragma unroll 8
    for (int k = 0; k < DD; k++) {
        float xik = sXi[il * XSTRIDE + k];
        #pragma unroll
        for (int q = 0; q < 4; q++) {
            float4 wv = *(float4*)&sWh[k * 64 + c0 + q * 4];
            acc[q * 4 + 0] += xik * wv.x; acc[q * 4 + 1] += xik * wv.y;
            acc[q * 4 + 2] += xik * wv.z; acc[q * 4 + 3] += xik * wv.w;
        }
    }
    float cb = convb[0];
    float sa = sigm(alpha[i0 + il]);
    size_t obase = ((size_t)b * NN + i0 + il) * DD + c0;
    #pragma unroll
    for (int q = 0; q < 4; q++) {
        float4 x0v = *(const float4*)(x0 + obase + q * 4);
        float4 r;
        r.x = acc[q * 4 + 0] + cb + x0v.x * sa;
        r.y = acc[q * 4 + 1] + cb + x0v.y * sa;
        r.z = acc[q * 4 + 2] + cb + x0v.z * sa;
        r.w = acc[q * 4 + 3] + cb + x0v.w * sa;
        *(float4*)(g_add + obase + q * 4) = r;
    }
}

// -------- kernel sig: S[b,n,j] = sigmoid(e2[b,n]*e1[b,j] + bsT[n,j]), hi/lo
__global__ void k_sig(void) {
    int n = blockIdx.x, b = blockIdx.y, which = blockIdx.z;
    int j = threadIdx.x * 4;
    const float* e1 = which ? g_e1g : g_e1f;
    const float* e2 = which ? g_e2g : g_e2f;
    const float* bsT = (which ? g_bsTg : g_bsTf) + (size_t)n * NN + j;
    size_t off = (((size_t)which * BB + b) * NN + n) * NN + j;
    float  a   = e2[b * NN + n];
    float4 e1v = *(const float4*)(e1 + b * NN + j);
    float4 bv  = *(const float4*)bsT;
    float sx = sigm(a * e1v.x + bv.x);
    float sy = sigm(a * e1v.y + bv.y);
    float sz = sigm(a * e1v.z + bv.z);
    float sw = sigm(a * e1v.w + bv.w);
    __nv_bfloat16 h0, l0, h1, l1, h2, l2, h3, l3;
    bf16_split(sx, h0, l0); bf16_split(sy, h1, l1);
    bf16_split(sz, h2, l2); bf16_split(sw, h3, l3);
    __nv_bfloat162* ph = (__nv_bfloat162*)(g_sHi + off);
    __nv_bfloat162* pl = (__nv_bfloat162*)(g_sLo + off);
    ph[0] = __nv_bfloat162{h0, h1}; ph[1] = __nv_bfloat162{h2, h3};
    pl[0] = __nv_bfloat162{l0, l1}; pl[1] = __nv_bfloat162{l2, l3};
}

// ------- kernel gemm: bf16x3 mma.sync batched GEMM (R6 config, best) -------
// CTA 128x128, 8 warps (2x4), warp tile 64x32, K-tile 32, single z=64 launch.
#define KT     32
#define STRB   80
#define TILE_BYTES (128*STRB)
#define STAGE_BYTES (4*TILE_BYTES)
#define GEMM_SMEM  (2*STAGE_BYTES)

__global__ void __launch_bounds__(256) k_gemm() {
    extern __shared__ char smg[];
    uint32_t smb = smem_u32(smg);
    int tid = threadIdx.x;
    int z = blockIdx.z;
    int b = z & (BB - 1);
    int which = z >> 5;
    const __nv_bfloat16* __restrict__ Ahi = g_vHi + (size_t)which * NN * NN;
    const __nv_bfloat16* __restrict__ Alo = g_vLo + (size_t)which * NN * NN;
    const __nv_bfloat16* __restrict__ Bhi = g_sHi + ((size_t)which * BB + b) * NN * NN;
    const __nv_bfloat16* __restrict__ Blo = g_sLo + ((size_t)which * BB + b) * NN * NN;
    float* __restrict__ C = (which ? g_NG : g_EF) + (size_t)b * NN * NN;
    int i0 = blockIdx.y * 128, n0 = blockIdx.x * 128;

    int wid = tid >> 5, lane = tid & 31;
    int gid = lane >> 2, tg = lane & 3;
    int wm = (wid & 1) * 64, wn = (wid >> 1) * 32;

    int lr    = lane & 7;
    int lrow8 = (lane >> 3) & 1;
    int lk8   = (lane >> 4) & 1;
    uint32_t aoff = (uint32_t)((wm + lrow8 * 8 + lr) * STRB + lk8 * 16);
    uint32_t boff = (uint32_t)((wn + lrow8 * 8 + lr) * STRB + lk8 * 16);

    int slot_tile[8], slot_row[8], slot_ch[8];
    #pragma unroll
    for (int it = 0; it < 8; it++) {
        int slot = tid + it * 256;
        slot_tile[it] = slot >> 9;
        int r2 = slot & 511;
        slot_row[it] = r2 >> 2;
        slot_ch[it]  = r2 & 3;
    }

    float acc[4][4][4];
    #pragma unroll
    for (int mf = 0; mf < 4; mf++)
        #pragma unroll
        for (int nf = 0; nf < 4; nf++)
            #pragma unroll
            for (int q = 0; q < 4; q++) acc[mf][nf][q] = 0.0f;

    #define G_ISSUE(S) do {                                                      \
        uint32_t sb_ = smb + ((S) & 1) * STAGE_BYTES;                            \
        int kc_ = (S) * KT;                                                      \
        _Pragma("unroll")                                                        \
        for (int it = 0; it < 8; it++) {                                         \
            int tile = slot_tile[it], row = slot_row[it], ch = slot_ch[it];      \
            const __nv_bfloat16* src =                                           \
                (tile == 0) ? Ahi + (size_t)(i0 + row) * NN :                    \
                (tile == 1) ? Alo + (size_t)(i0 + row) * NN :                    \
                (tile == 2) ? Bhi + (size_t)(n0 + row) * NN :                    \
                              Blo + (size_t)(n0 + row) * NN;                     \
            const char* gp = (const char*)(src + kc_) + ch * 16;                 \
            uint32_t sp = sb_ + (uint32_t)(tile * TILE_BYTES + row * STRB + ch * 16); \
            asm volatile("cp.async.ca.shared.global [%0], [%1], 16;"             \
                         :: "r"(sp), "l"(gp));                                   \
        }                                                                        \
        asm volatile("cp.async.commit_group;");                                  \
    } while (0)

    G_ISSUE(0);
    for (int s = 0; s < NN / KT; s++) {
        if (s < NN / KT - 1) {
            G_ISSUE(s + 1);
            asm volatile("cp.async.wait_group 1;");
        } else {
            asm volatile("cp.async.wait_group 0;");
        }
        __syncthreads();
        uint32_t base = smb + (s & 1) * STAGE_BYTES;
        uint32_t tAh = base, tAl = base + TILE_BYTES;
        uint32_t tBh = base + 2 * TILE_BYTES, tBl = base + 3 * TILE_BYTES;

        #pragma unroll
        for (int kh = 0; kh < 2; kh++) {
            uint32_t kb = (uint32_t)(kh * 32);
            uint32_t ah[4][4], al[4][4], bh[4][2], bl[4][2];
            #pragma unroll
            for (int mf = 0; mf < 4; mf++) {
                uint32_t ao = aoff + (uint32_t)(mf * 16 * STRB) + kb;
                ldm_x4(ah[mf], tAh + ao);
                ldm_x4(al[mf], tAl + ao);
            }
            #pragma unroll
            for (int p = 0; p < 2; p++) {
                uint32_t bo = boff + (uint32_t)(p * 16 * STRB) + kb;
                uint32_t th[4], tl[4];
                ldm_x4(th, tBh + bo);
                ldm_x4(tl, tBl + bo);
                bh[2*p][0]   = th[0]; bh[2*p][1]   = th[2];
                bh[2*p+1][0] = th[1]; bh[2*p+1][1] = th[3];
                bl[2*p][0]   = tl[0]; bl[2*p][1]   = tl[2];
                bl[2*p+1][0] = tl[1]; bl[2*p+1][1] = tl[3];
            }
            #pragma unroll
            for (int mf = 0; mf < 4; mf++)
                #pragma unroll
                for (int nf = 0; nf < 4; nf++) {
                    mma16(acc[mf][nf], ah[mf], bh[nf]);
                    mma16(acc[mf][nf], ah[mf], bl[nf]);
                    mma16(acc[mf][nf], al[mf], bh[nf]);
                }
        }
        __syncthreads();
    }

    #pragma unroll
    for (int mf = 0; mf < 4; mf++) {
        #pragma unroll
        for (int nf = 0; nf < 4; nf++) {
            int row = i0 + wm + mf * 16 + gid;
            int col = n0 + wn + nf * 8 + tg * 2;
            float2 v0 = make_float2(acc[mf][nf][0], acc[mf][nf][1]);
            float2 v1 = make_float2(acc[mf][nf][2], acc[mf][nf][3]);
            *(float2*)(C + (size_t)row * NN + col)       = v0;
            *(float2*)(C + (size_t)(row + 8) * NN + col) = v1;
        }
    }
}

// ------- kernel soft: row softmax; outputs Em/Nh as bf16 hi/lo aliases -----
__global__ void k_soft() {
    int i = blockIdx.x, b = blockIdx.y;
    size_t ro = ((size_t)b * NN + i) * NN;
    int c = threadIdx.x * 4;
    int wid = threadIdx.x >> 5, lane = threadIdx.x & 31;
    __shared__ float sE[8], sN[8];

    float4 ev = *(float4*)(g_EF + ro + c);
    float4 nv = *(float4*)(g_NG + ro + c);

    float mE = fmaxf(fmaxf(ev.x, ev.y), fmaxf(ev.z, ev.w));
    float mN = fmaxf(fmaxf(nv.x, nv.y), fmaxf(nv.z, nv.w));
    #pragma unroll
    for (int o = 16; o > 0; o >>= 1) {
        mE = fmaxf(mE, __shfl_xor_sync(0xffffffffu, mE, o));
        mN = fmaxf(mN, __shfl_xor_sync(0xffffffffu, mN, o));
    }
    if (lane == 0) { sE[wid] = mE; sN[wid] = mN; }
    __syncthreads();
    mE = sE[0]; mN = sN[0];
    #pragma unroll
    for (int wv = 1; wv < 8; wv++) { mE = fmaxf(mE, sE[wv]); mN = fmaxf(mN, sN[wv]); }
    __syncthreads();

    float4 eE, eN;
    eE.x = __expf(ev.x - mE); eE.y = __expf(ev.y - mE);
    eE.z = __expf(ev.z - mE); eE.w = __expf(ev.w - mE);
    eN.x = __expf(nv.x - mN); eN.y = __expf(nv.y - mN);
    eN.z = __expf(nv.z - mN); eN.w = __expf(nv.w - mN);
    float sumE = eE.x + eE.y + eE.z + eE.w;
    float sumN = eN.x + eN.y + eN.z + eN.w;
    #pragma unroll
    for (int o = 16; o > 0; o >>= 1) {
        sumE += __shfl_xor_sync(0xffffffffu, sumE, o);
        sumN += __shfl_xor_sync(0xffffffffu, sumN, o);
    }
    if (lane == 0) { sE[wid] = sumE; sN[wid] = sumN; }
    __syncthreads();
    sumE = 0.0f; sumN = 0.0f;
    #pragma unroll
    for (int wv = 0; wv < 8; wv++) { sumE += sE[wv]; sumN += sN[wv]; }

    float invE = __fdividef(1.0f, sumE);
    float invN = __fdividef(1.0f, sumN);

    float4 se;
    se.x = eE.x * invE; se.y = eE.y * invE; se.z = eE.z * invE; se.w = eE.w * invE;
    float4 nh;
    nh.x = __fdividef(eN.x * invN, se.x + 1e-5f);
    nh.y = __fdividef(eN.y * invN, se.y + 1e-5f);
    nh.z = __fdividef(eN.z * invN, se.z + 1e-5f);
    nh.w = __fdividef(eN.w * invN, se.w + 1e-5f);

    float4 am = *(float4*)(g_Amix + (size_t)i * NN + c);
    float4 em;
    em.x = se.x + am.x - ((c + 0 == i) ? 1.0f : 0.0f);
    em.y = se.y + am.y - ((c + 1 == i) ? 1.0f : 0.0f);
    em.z = se.z + am.z - ((c + 2 == i) ? 1.0f : 0.0f);
    em.w = se.w + am.w - ((c + 3 == i) ? 1.0f : 0.0f);

    __nv_bfloat16 h0, l0, h1, l1, h2, l2, h3, l3;
    bf16_split(em.x, h0, l0); bf16_split(em.y, h1, l1);
    bf16_split(em.z, h2, l2); bf16_split(em.w, h3, l3);
    *(__nv_bfloat162*)(g_sHi + ro + c)           = __nv_bfloat162{h0, h1};
    *(__nv_bfloat162*)(g_sHi + ro + c + 2)       = __nv_bfloat162{h2, h3};
    *(__nv_bfloat162*)(g_sHi + SZB + ro + c)     = __nv_bfloat162{l0, l1};
    *(__nv_bfloat162*)(g_sHi + SZB + ro + c + 2) = __nv_bfloat162{l2, l3};
    bf16_split(nh.x, h0, l0); bf16_split(nh.y, h1, l1);
    bf16_split(nh.z, h2, l2); bf16_split(nh.w, h3, l3);
    *(__nv_bfloat162*)(g_sLo + ro + c)           = __nv_bfloat162{h0, h1};
    *(__nv_bfloat162*)(g_sLo + ro + c + 2)       = __nv_bfloat162{h2, h3};
    *(__nv_bfloat162*)(g_sLo + SZB + ro + c)     = __nv_bfloat162{l0, l1};
    *(__nv_bfloat162*)(g_sLo + SZB + ro + c + 2) = __nv_bfloat162{l2, l3};
}

// --------- kernel final: f = tanh(Em@xr + add), g = tanh(Nh@xr) (bf16x3 MMA)
#define F_STR    80
#define F_TILE   (128*F_STR)             // 10240
#define F_XSTR   144
#define F_XTILE  (32*F_XSTR)             // 4608
#define F_XOFF   (4*F_TILE)              // 40960
#define F_STAGE  (F_XOFF + 2*F_XTILE)    // 50176
#define FIN_SMEM (2*F_STAGE)             // 100352

__global__ void __launch_bounds__(256) k_final(float* __restrict__ out) {
    extern __shared__ char smf[];
    uint32_t smb = smem_u32(smf);
    int tid = threadIdx.x;
    int b = blockIdx.y, i0 = blockIdx.x * 128;
    const __nv_bfloat16* EmH = g_sHi + (size_t)b * NN * NN;
    const __nv_bfloat16* EmL = EmH + SZB;
    const __nv_bfloat16* NhH = g_sLo + (size_t)b * NN * NN;
    const __nv_bfloat16* NhL = NhH + SZB;
    const __nv_bfloat16* xHb = g_xH + (size_t)b * NN * DD;
    const __nv_bfloat16* xLb = g_xL + (size_t)b * NN * DD;

    int wid = tid >> 5, lane = tid & 31;
    int gid = lane >> 2, tg = lane & 3;
    int wm = (wid & 3) * 32, wn = (wid >> 2) * 32;

    int lr    = lane & 7;
    int lrow8 = (lane >> 3) & 1;
    int lk8   = (lane >> 4) & 1;
    uint32_t aoff = (uint32_t)((wm + lrow8 * 8 + lr) * F_STR + lk8 * 16);
    int quad = lane >> 3;
    int xkrow = (quad & 1) * 8 + lr;
    int xn8   = (quad >> 1) * 8;

    float accF[2][4][4], accG[2][4][4];
    #pragma unroll
    for (int mf = 0; mf < 2; mf++)
        #pragma unroll
        for (int nf = 0; nf < 4; nf++)
            #pragma unroll
            for (int q = 0; q < 4; q++) { accF[mf][nf][q] = 0.0f; accG[mf][nf][q] = 0.0f; }

    #define F_ISSUE(S) do {                                                      \
        uint32_t sb_ = smb + ((S) & 1) * F_STAGE;                                \
        int jc_ = (S) * 32;                                                      \
        _Pragma("unroll")                                                        \
        for (int it = 0; it < 10; it++) {                                        \
            int slot = tid + it * 256;                                           \
            if (slot < 2048) {                                                   \
                int tile = slot >> 9;                                            \
                int r2 = slot & 511;                                             \
                int row = r2 >> 2, ch = r2 & 3;                                  \
                const __nv_bfloat16* src =                                       \
                    (tile == 0) ? EmH : (tile == 1) ? EmL :                      \
                    (tile == 2) ? NhH : NhL;                                     \
                const char* gp = (const char*)(src + (size_t)(i0 + row) * NN + jc_ + ch * 8); \
                uint32_t sp = sb_ + (uint32_t)(tile * F_TILE + row * F_STR + ch * 16); \
                asm volatile("cp.async.ca.shared.global [%0], [%1], 16;"         \
                             :: "r"(sp), "l"(gp));                               \
            } else {                                                             \
                int t2 = slot - 2048;                                            \
                int xt = t2 >> 8;                                                \
                int r2 = t2 & 255;                                               \
                int row = r2 >> 3, ch = r2 & 7;                                  \
                const __nv_bfloat16* src = xt ? xLb : xHb;                       \
                const char* gp = (const char*)(src + (size_t)(jc_ + row) * DD + ch * 8); \
                uint32_t sp = sb_ + (uint32_t)(F_XOFF + xt * F_XTILE + row * F_XSTR + ch * 16); \
                asm volatile("cp.async.ca.shared.global [%0], [%1], 16;"         \
                             :: "r"(sp), "l"(gp));                               \
            }                                                                    \
        }                                                                        \
        asm volatile("cp.async.commit_group;");                                  \
    } while (0)

    F_ISSUE(0);
    for (int s = 0; s < NN / 32; s++) {
        if (s < NN / 32 - 1) {
            F_ISSUE(s + 1);
            asm volatile("cp.async.wait_group 1;");
        } else {
            asm volatile("cp.async.wait_group 0;");
        }
        __syncthreads();
        uint32_t base = smb + (s & 1) * F_STAGE;
        uint32_t tEh = base, tEl = base + F_TILE;
        uint32_t tNh = base + 2 * F_TILE, tNl = base + 3 * F_TILE;
        uint32_t tXh = base + F_XOFF, tXl = base + F_XOFF + F_XTILE;

        #pragma unroll
        for (int kh = 0; kh < 2; kh++) {
            uint32_t kb = (uint32_t)(kh * 32);
            uint32_t bxh[4][2], bxl[4][2];
            #pragma unroll
            for (int p = 0; p < 2; p++) {
                uint32_t xad = (uint32_t)((kh * 16 + xkrow) * F_XSTR + (wn + p * 16 + xn8) * 2);
                uint32_t th[4], tl[4];
                ldm_x4t(th, tXh + xad);
                ldm_x4t(tl, tXl + xad);
                bxh[2*p][0]   = th[0]; bxh[2*p][1]   = th[1];
                bxh[2*p+1][0] = th[2]; bxh[2*p+1][1] = th[3];
                bxl[2*p][0]   = tl[0]; bxl[2*p][1]   = tl[1];
                bxl[2*p+1][0] = tl[2]; bxl[2*p+1][1] = tl[3];
            }
            {
                uint32_t ah[2][4], al[2][4];
                #pragma unroll
                for (int mf = 0; mf < 2; mf++) {
                    uint32_t ao = aoff + (uint32_t)(mf * 16 * F_STR) + kb;
                    ldm_x4(ah[mf], tEh + ao);
                    ldm_x4(al[mf], tEl + ao);
                }
                #pragma unroll
                for (int mf = 0; mf < 2; mf++)
                    #pragma unroll
                    for (int nf = 0; nf < 4; nf++) {
                        mma16(accF[mf][nf], ah[mf], bxh[nf]);
                        mma16(accF[mf][nf], ah[mf], bxl[nf]);
                        mma16(accF[mf][nf], al[mf], bxh[nf]);
                    }
            }
            {
                uint32_t ah[2][4], al[2][4];
                #pragma unroll
                for (int mf = 0; mf < 2; mf++) {
                    uint32_t ao = aoff + (uint32_t)(mf * 16 * F_STR) + kb;
                    ldm_x4(ah[mf], tNh + ao);
                    ldm_x4(al[mf], tNl + ao);
                }
                #pragma unroll
                for (int mf = 0; mf < 2; mf++)
                    #pragma unroll
                    for (int nf = 0; nf < 4; nf++) {
                        mma16(accG[mf][nf], ah[mf], bxh[nf]);
                        mma16(accG[mf][nf], ah[mf], bxl[nf]);
                        mma16(accG[mf][nf], al[mf], bxh[nf]);
                    }
            }
        }
        __syncthreads();
    }

    #pragma unroll
    for (int mf = 0; mf < 2; mf++) {
        #pragma unroll
        for (int nf = 0; nf < 4; nf++) {
            int row = i0 + wm + mf * 16 + gid;
            int col = wn + nf * 8 + tg * 2;
            size_t o0 = ((size_t)b * NN + row) * DD + col;
            size_t o1 = ((size_t)b * NN + row + 8) * DD + col;
            float2 a0 = *(const float2*)(g_add + o0);
            float2 a1 = *(const float2*)(g_add + o1);
            float2 f0, f1, g0, g1;
            f0.x = tanhf(accF[mf][nf][0] + a0.x);
            f0.y = tanhf(accF[mf][nf][1] + a0.y);
            f1.x = tanhf(accF[mf][nf][2] + a1.x);
            f1.y = tanhf(accF[mf][nf][3] + a1.y);
            g0.x = tanhf(accG[mf][nf][0]);
            g0.y = tanhf(accG[mf][nf][1]);
            g1.x = tanhf(accG[mf][nf][2]);
            g1.y = tanhf(accG[mf][nf][3]);
            *(float2*)(out + o0)        = f0;
            *(float2*)(out + o1)        = f1;
            *(float2*)(out + HALF + o0) = g0;
            *(float2*)(out + HALF + o1) = g1;
        }
    }
}

// ---------------- launch ----------------------------------------------------
extern "C" void kernel_launch(void* const* d_in, const int* in_sizes, int n_in,
                              void* d_out, int out_size) {
    const float* x     = (const float*)d_in[0];
    const float* x0    = (const float*)d_in[1];
    const float* w     = (const float*)d_in[2];
    const float* d     = (const float*)d_in[3];
    const float* alpha = (const float*)d_in[4];
    const float* fw1   = (const float*)d_in[5];
    const float* fw2   = (const float*)d_in[6];
    const float* fvs   = (const float*)d_in[7];
    const float* fbs   = (const float*)d_in[8];
    const float* gw1   = (const float*)d_in[9];
    const float* gw2   = (const float*)d_in[10];
    const float* gvs   = (const float*)d_in[11];
    const float* gbs   = (const float*)d_in[12];
    const float* convw = (const float*)d_in[13];
    const float* convb = (const float*)d_in[14];
    const float* adj   = (const float*)d_in[15];
    float* out = (float*)d_out;

    cudaFuncSetAttribute(k_gemm, cudaFuncAttributeMaxDynamicSharedMemorySize, GEMM_SMEM);
    cudaFuncSetAttribute(k_final, cudaFuncAttributeMaxDynamicSharedMemorySize, FIN_SMEM);

    k_evec   <<<(BB * NN) / 8, 256>>>(x, fw1, fw2, gw1, gw2);
    k_amix   <<<(NN * NN / 4) / 256, 256>>>(adj, convw);
    k_transp <<<dim3(32, 32, 2), dim3(32, 8)>>>(fbs, gbs);
    k_split  <<<(2 * NN * NN / 4) / 256, 256>>>(fvs, gvs);
    k_xsplit <<<(BB * NN * DD / 4) / 256, 256>>>(x);
    k_addterm<<<dim3(16, BB), 256>>>(x, x0, w, d, alpha, convb);
    k_sig    <<<dim3(NN, BB, 2), 256>>>();
    k_gemm   <<<dim3(8, 8, 2 * BB), 256, GEMM_SMEM>>>();
    k_soft   <<<dim3(NN, BB), 256>>>();
    k_final  <<<dim3(NN / 128, BB), 256, FIN_SMEM>>>(out);
}

// round 12
// speedup vs baseline: 1.0330x; 1.0016x over previous
#include <cuda_runtime.h>
#include <cuda_bf16.h>
#include <math.h>
#include <stdint.h>

#define BB 32
#define NN 1024
#define DD 64
#define HALF (BB*NN*DD)
#define SZB ((size_t)BB*NN*NN)

// ---------------- scratch (device globals; no allocation allowed) ----------
static __device__ __nv_bfloat16 g_sHi[2*SZB];  // phase1: sigmoid hi [which][b][n][j]
                                               // phase2: EmHi [0,SZB), EmLo [SZB,2SZB)
static __device__ __nv_bfloat16 g_sLo[2*SZB];  // phase1: sigmoid lo ; phase2: NhHi, NhLo
static __device__ __nv_bfloat16 g_vHi[(size_t)2*NN*NN];
static __device__ __nv_bfloat16 g_vLo[(size_t)2*NN*NN];
static __device__ __nv_bfloat16 g_xH[(size_t)BB*NN*DD];
static __device__ __nv_bfloat16 g_xL[(size_t)BB*NN*DD];
static __device__ float g_EF  [SZB];
static __device__ float g_NG  [SZB];
static __device__ float g_bsTf[(size_t)NN*NN];
static __device__ float g_bsTg[(size_t)NN*NN];
static __device__ float g_e1f[BB*NN], g_e2f[BB*NN], g_e1g[BB*NN], g_e2g[BB*NN];
static __device__ float g_Amix[NN*NN];
static __device__ float g_add[(size_t)BB*NN*DD];   // xw + cb + x0*sig(alpha)

__device__ __forceinline__ float sigm(float v) { return 1.0f / (1.0f + __expf(-v)); }
__device__ __forceinline__ uint32_t smem_u32(const void* p) {
    uint32_t a;
    asm("{ .reg .u64 t; cvta.to.shared.u64 t, %1; cvt.u32.u64 %0, t; }" : "=r"(a) : "l"(p));
    return a;
}
__device__ __forceinline__ void bf16_split(float x, __nv_bfloat16& hi, __nv_bfloat16& lo) {
    hi = __float2bfloat16(x);
    lo = __float2bfloat16(x - __bfloat162float(hi));
}
__device__ __forceinline__ void mma16(float* c, const uint32_t* a, const uint32_t* b) {
    asm volatile("mma.sync.aligned.m16n8k16.row.col.f32.bf16.bf16.f32 "
                 "{%0,%1,%2,%3}, {%4,%5,%6,%7}, {%8,%9}, {%0,%1,%2,%3};"
                 : "+f"(c[0]), "+f"(c[1]), "+f"(c[2]), "+f"(c[3])
                 : "r"(a[0]), "r"(a[1]), "r"(a[2]), "r"(a[3]),
                   "r"(b[0]), "r"(b[1]));
}
__device__ __forceinline__ void ldm_x4(uint32_t* r, uint32_t addr) {
    asm volatile("ldmatrix.sync.aligned.m8n8.x4.shared.b16 {%0,%1,%2,%3}, [%4];"
                 : "=r"(r[0]), "=r"(r[1]), "=r"(r[2]), "=r"(r[3]) : "r"(addr));
}
__device__ __forceinline__ void ldm_x4t(uint32_t* r, uint32_t addr) {
    asm volatile("ldmatrix.sync.aligned.m8n8.x4.trans.shared.b16 {%0,%1,%2,%3}, [%4];"
                 : "=r"(r[0]), "=r"(r[1]), "=r"(r[2]), "=r"(r[3]) : "r"(addr));
}

// ---------------- kernel: e1/e2 row dots -----------------------------------
__global__ void k_evec(const float* __restrict__ x,
                       const float* __restrict__ fw1, const float* __restrict__ fw2,
                       const float* __restrict__ gw1, const float* __restrict__ gw2) {
    int gwarp = (blockIdx.x * blockDim.x + threadIdx.x) >> 5;
    int lane  = threadIdx.x & 31;
    const float* xp = x + (size_t)gwarp * DD;
    float v0 = xp[lane], v1 = xp[lane + 32];
    float s0 = v0 * fw1[lane] + v1 * fw1[lane + 32];
    float s1 = v0 * fw2[lane] + v1 * fw2[lane + 32];
    float s2 = v0 * gw1[lane] + v1 * gw1[lane + 32];
    float s3 = v0 * gw2[lane] + v1 * gw2[lane + 32];
    #pragma unroll
    for (int o = 16; o > 0; o >>= 1) {
        s0 += __shfl_xor_sync(0xffffffffu, s0, o);
        s1 += __shfl_xor_sync(0xffffffffu, s1, o);
        s2 += __shfl_xor_sync(0xffffffffu, s2, o);
        s3 += __shfl_xor_sync(0xffffffffu, s3, o);
    }
    if (lane == 0) {
        g_e1f[gwarp] = s0; g_e2f[gwarp] = s1;
        g_e1g[gwarp] = s2; g_e2g[gwarp] = s3;
    }
}

// ---------------- kernel: A_mix --------------------------------------------
__global__ void k_amix(const float* __restrict__ adj, const float* __restrict__ convw) {
    int t = blockIdx.x * blockDim.x + threadIdx.x;
    int base = t * 4;
    int i = base >> 10;
    int j = base & (NN - 1);
    float c0 = convw[0], c1 = convw[1];
    float dsub = c0 + c1;
    float4 a0 = *(const float4*)(adj + base);
    float4 a1 = *(const float4*)(adj + (size_t)NN * NN + base);
    float4 r;
    r.x = c0 * a0.x + c1 * a1.x - ((i == j + 0) ? dsub : 0.0f);
    r.y = c0 * a0.y + c1 * a1.y - ((i == j + 1) ? dsub : 0.0f);
    r.z = c0 * a0.z + c1 * a1.z - ((i == j + 2) ? dsub : 0.0f);
    r.w = c0 * a0.w + c1 * a1.w - ((i == j + 3) ? dsub : 0.0f);
    *(float4*)(g_Amix + base) = r;
}

// ---------------- kernel: transpose fbs/gbs --------------------------------
__global__ void k_transp(const float* __restrict__ fbs, const float* __restrict__ gbs) {
    __shared__ float t[32][33];
    const float* src = blockIdx.z ? gbs : fbs;
    float* dst = blockIdx.z ? g_bsTg : g_bsTf;
    int x0 = blockIdx.x * 32, y0 = blockIdx.y * 32;
    #pragma unroll
    for (int r = threadIdx.y; r < 32; r += 8)
        t[r][threadIdx.x] = src[(size_t)(y0 + r) * NN + x0 + threadIdx.x];
    __syncthreads();
    #pragma unroll
    for (int r = threadIdx.y; r < 32; r += 8)
        dst[(size_t)(x0 + r) * NN + y0 + threadIdx.x] = t[threadIdx.x][r];
}

// ---------------- kernel: bf16-split vs ------------------------------------
__global__ void k_split(const float* __restrict__ fvs, const float* __restrict__ gvs) {
    int t = blockIdx.x * blockDim.x + threadIdx.x;
    int which = t >= (NN * NN / 4);
    int e = which ? t - NN * NN / 4 : t;
    const float4* src = (const float4*)(which ? gvs : fvs);
    float4 a = src[e];
    __nv_bfloat16 h0, l0, h1, l1, h2, l2, h3, l3;
    bf16_split(a.x, h0, l0); bf16_split(a.y, h1, l1);
    bf16_split(a.z, h2, l2); bf16_split(a.w, h3, l3);
    size_t off = (size_t)which * NN * NN + (size_t)e * 4;
    __nv_bfloat162* ph = (__nv_bfloat162*)(g_vHi + off);
    __nv_bfloat162* pl = (__nv_bfloat162*)(g_vLo + off);
    ph[0] = __nv_bfloat162{h0, h1}; ph[1] = __nv_bfloat162{h2, h3};
    pl[0] = __nv_bfloat162{l0, l1}; pl[1] = __nv_bfloat162{l2, l3};
}

// ---------------- kernel: bf16-split x -------------------------------------
__global__ void k_xsplit(const float* __restrict__ x) {
    int e = blockIdx.x * blockDim.x + threadIdx.x;   // over BB*NN*DD/4
    float4 a = ((const float4*)x)[e];
    __nv_bfloat16 h0, l0, h1, l1, h2, l2, h3, l3;
    bf16_split(a.x, h0, l0); bf16_split(a.y, h1, l1);
    bf16_split(a.z, h2, l2); bf16_split(a.w, h3, l3);
    size_t off = (size_t)e * 4;
    __nv_bfloat162* ph = (__nv_bfloat162*)(g_xH + off);
    __nv_bfloat162* pl = (__nv_bfloat162*)(g_xL + off);
    ph[0] = __nv_bfloat162{h0, h1}; ph[1] = __nv_bfloat162{h2, h3};
    pl[0] = __nv_bfloat162{l0, l1}; pl[1] = __nv_bfloat162{l2, l3};
}

// ------- kernel addterm: g_add = xr@W_hat + cb + x0*sigm(alpha) ------------
#define XSTRIDE 68
__global__ void __launch_bounds__(256) k_addterm(
        const float* __restrict__ x, const float* __restrict__ x0,
        const float* __restrict__ w, const float* __restrict__ d,
        const float* __restrict__ alpha, const float* __restrict__ convb) {
    __shared__ float sWh[64 * 64];
    __shared__ float sXi[64 * XSTRIDE];
    int b = blockIdx.y, i0 = blockIdx.x * 64;
    int tid = threadIdx.x;

    #pragma unroll
    for (int e = 0; e < 16; e++) {
        int idx = tid + e * 256;
        int i = idx >> 6, j = idx & 63;
        float s = 0.0f;
        #pragma unroll 8
        for (int k = 0; k < DD; k++) {
            float dc = fminf(fmaxf(d[k], 0.0f), 1.0f);
            s += w[i * DD + k] * dc * w[j * DD + k];
        }
        sWh[idx] = s - ((i == j) ? 1.0f : 0.0f);
    }
    #pragma unroll
    for (int q = 0; q < 4; q++) {
        int lin = tid + q * 256;
        int row = lin >> 4, cc = (lin & 15) * 4;
        *(float4*)&sXi[row * XSTRIDE + cc] =
            *(const float4*)(x + (size_t)(b * NN + i0 + row) * DD + cc);
    }
    __syncthreads();

    int il = tid >> 2, c0 = (tid & 3) * 16;
    float acc[16];
    #pragma unroll
    for (int q = 0; q < 16; q++) acc[q] = 0.0f;
    #pragma unroll 8
    for (int k = 0; k < DD; k++) {
        float xik = sXi[il * XSTRIDE + k];
        #pragma unroll
        for (int q = 0; q < 4; q++) {
            float4 wv = *(float4*)&sWh[k * 64 + c0 + q * 4];
            acc[q * 4 + 0] += xik * wv.x; acc[q * 4 + 1] += xik * wv.y;
            acc[q * 4 + 2] += xik * wv.z; acc[q * 4 + 3] += xik * wv.w;
        }
    }
    float cb = convb[0];
    float sa = sigm(alpha[i0 + il]);
    size_t obase = ((size_t)b * NN + i0 + il) * DD + c0;
    #pragma unroll
    for (int q = 0; q < 4; q++) {
        float4 x0v = *(const float4*)(x0 + obase + q * 4);
        float4 r;
        r.x = acc[q * 4 + 0] + cb + x0v.x * sa;
        r.y = acc[q * 4 + 1] + cb + x0v.y * sa;
        r.z = acc[q * 4 + 2] + cb + x0v.z * sa;
        r.w = acc[q * 4 + 3] + cb + x0v.w * sa;
        *(float4*)(g_add + obase + q * 4) = r;
    }
}

// -------- kernel sig: S[b,n,j] = sigmoid(e2[b,n]*e1[b,j] + bsT[n,j]), hi/lo
__global__ void k_sig(void) {
    int n = blockIdx.x, b = blockIdx.y, which = blockIdx.z;
    int j = threadIdx.x * 4;
    const float* e1 = which ? g_e1g : g_e1f;
    const float* e2 = which ? g_e2g : g_e2f;
    const float* bsT = (which ? g_bsTg : g_bsTf) + (size_t)n * NN + j;
    size_t off = (((size_t)which * BB + b) * NN + n) * NN + j;
    float  a   = e2[b * NN + n];
    float4 e1v = *(const float4*)(e1 + b * NN + j);
    float4 bv  = *(const float4*)bsT;
    float sx = sigm(a * e1v.x + bv.x);
    float sy = sigm(a * e1v.y + bv.y);
    float sz = sigm(a * e1v.z + bv.z);
    float sw = sigm(a * e1v.w + bv.w);
    __nv_bfloat16 h0, l0, h1, l1, h2, l2, h3, l3;
    bf16_split(sx, h0, l0); bf16_split(sy, h1, l1);
    bf16_split(sz, h2, l2); bf16_split(sw, h3, l3);
    __nv_bfloat162* ph = (__nv_bfloat162*)(g_sHi + off);
    __nv_bfloat162* pl = (__nv_bfloat162*)(g_sLo + off);
    ph[0] = __nv_bfloat162{h0, h1}; ph[1] = __nv_bfloat162{h2, h3};
    pl[0] = __nv_bfloat162{l0, l1}; pl[1] = __nv_bfloat162{l2, l3};
}

// ------- kernel gemm: bf16x3 mma.sync batched GEMM -------------------------
// CTA 128x128, 8 warps (2x4), warp tile 64x32, K-tile 32, single z=64 launch.
// MMA issue restructured into 3 sweeps over all 16 accumulators (RAW dist 16).
#define KT     32
#define STRB   80
#define TILE_BYTES (128*STRB)
#define STAGE_BYTES (4*TILE_BYTES)
#define GEMM_SMEM  (2*STAGE_BYTES)

__global__ void __launch_bounds__(256) k_gemm() {
    extern __shared__ char smg[];
    uint32_t smb = smem_u32(smg);
    int tid = threadIdx.x;
    int z = blockIdx.z;
    int b = z & (BB - 1);
    int which = z >> 5;
    const __nv_bfloat16* __restrict__ Ahi = g_vHi + (size_t)which * NN * NN;
    const __nv_bfloat16* __restrict__ Alo = g_vLo + (size_t)which * NN * NN;
    const __nv_bfloat16* __restrict__ Bhi = g_sHi + ((size_t)which * BB + b) * NN * NN;
    const __nv_bfloat16* __restrict__ Blo = g_sLo + ((size_t)which * BB + b) * NN * NN;
    float* __restrict__ C = (which ? g_NG : g_EF) + (size_t)b * NN * NN;
    int i0 = blockIdx.y * 128, n0 = blockIdx.x * 128;

    int wid = tid >> 5, lane = tid & 31;
    int gid = lane >> 2, tg = lane & 3;
    int wm = (wid & 1) * 64, wn = (wid >> 1) * 32;

    int lr    = lane & 7;
    int lrow8 = (lane >> 3) & 1;
    int lk8   = (lane >> 4) & 1;
    uint32_t aoff = (uint32_t)((wm + lrow8 * 8 + lr) * STRB + lk8 * 16);
    uint32_t boff = (uint32_t)((wn + lrow8 * 8 + lr) * STRB + lk8 * 16);

    int slot_tile[8], slot_row[8], slot_ch[8];
    #pragma unroll
    for (int it = 0; it < 8; it++) {
        int slot = tid + it * 256;
        slot_tile[it] = slot >> 9;
        int r2 = slot & 511;
        slot_row[it] = r2 >> 2;
        slot_ch[it]  = r2 & 3;
    }

    float acc[4][4][4];
    #pragma unroll
    for (int mf = 0; mf < 4; mf++)
        #pragma unroll
        for (int nf = 0; nf < 4; nf++)
            #pragma unroll
            for (int q = 0; q < 4; q++) acc[mf][nf][q] = 0.0f;

    #define G_ISSUE(S) do {                                                      \
        uint32_t sb_ = smb + ((S) & 1) * STAGE_BYTES;                            \
        int kc_ = (S) * KT;                                                      \
        _Pragma("unroll")                                                        \
        for (int it = 0; it < 8; it++) {                                         \
            int tile = slot_tile[it], row = slot_row[it], ch = slot_ch[it];      \
            const __nv_bfloat16* src =                                           \
                (tile == 0) ? Ahi + (size_t)(i0 + row) * NN :                    \
                (tile == 1) ? Alo + (size_t)(i0 + row) * NN :                    \
                (tile == 2) ? Bhi + (size_t)(n0 + row) * NN :                    \
                              Blo + (size_t)(n0 + row) * NN;                     \
            const char* gp = (const char*)(src + kc_) + ch * 16;                 \
            uint32_t sp = sb_ + (uint32_t)(tile * TILE_BYTES + row * STRB + ch * 16); \
            asm volatile("cp.async.ca.shared.global [%0], [%1], 16;"             \
                         :: "r"(sp), "l"(gp));                                   \
        }                                                                        \
        asm volatile("cp.async.commit_group;");                                  \
    } while (0)

    G_ISSUE(0);
    for (int s = 0; s < NN / KT; s++) {
        if (s < NN / KT - 1) {
            G_ISSUE(s + 1);
            asm volatile("cp.async.wait_group 1;");
        } else {
            asm volatile("cp.async.wait_group 0;");
        }
        __syncthreads();
        uint32_t base = smb + (s & 1) * STAGE_BYTES;
        uint32_t tAh = base, tAl = base + TILE_BYTES;
        uint32_t tBh = base + 2 * TILE_BYTES, tBl = base + 3 * TILE_BYTES;

        #pragma unroll
        for (int kh = 0; kh < 2; kh++) {
            uint32_t kb = (uint32_t)(kh * 32);
            uint32_t ah[4][4], al[4][4], bh[4][2], bl[4][2];
            #pragma unroll
            for (int mf = 0; mf < 4; mf++) {
                uint32_t ao = aoff + (uint32_t)(mf * 16 * STRB) + kb;
                ldm_x4(ah[mf], tAh + ao);
                ldm_x4(al[mf], tAl + ao);
            }
            #pragma unroll
            for (int p = 0; p < 2; p++) {
                uint32_t bo = boff + (uint32_t)(p * 16 * STRB) + kb;
                uint32_t th[4], tl[4];
                ldm_x4(th, tBh + bo);
                ldm_x4(tl, tBl + bo);
                bh[2*p][0]   = th[0]; bh[2*p][1]   = th[2];
                bh[2*p+1][0] = th[1]; bh[2*p+1][1] = th[3];
                bl[2*p][0]   = tl[0]; bl[2*p][1]   = tl[2];
                bl[2*p+1][0] = tl[1]; bl[2*p+1][1] = tl[3];
            }
            // three sweeps: RAW distance on each accumulator = 16 MMAs
            #pragma unroll
            for (int mf = 0; mf < 4; mf++)
                #pragma unroll
                for (int nf = 0; nf < 4; nf++)
                    mma16(acc[mf][nf], ah[mf], bh[nf]);
            #pragma unroll
            for (int mf = 0; mf < 4; mf++)
                #pragma unroll
                for (int nf = 0; nf < 4; nf++)
                    mma16(acc[mf][nf], ah[mf], bl[nf]);
            #pragma unroll
            for (int mf = 0; mf < 4; mf++)
                #pragma unroll
                for (int nf = 0; nf < 4; nf++)
                    mma16(acc[mf][nf], al[mf], bh[nf]);
        }
        __syncthreads();
    }

    #pragma unroll
    for (int mf = 0; mf < 4; mf++) {
        #pragma unroll
        for (int nf = 0; nf < 4; nf++) {
            int row = i0 + wm + mf * 16 + gid;
            int col = n0 + wn + nf * 8 + tg * 2;
            float2 v0 = make_float2(acc[mf][nf][0], acc[mf][nf][1]);
            float2 v1 = make_float2(acc[mf][nf][2], acc[mf][nf][3]);
            *(float2*)(C + (size_t)row * NN + col)       = v0;
            *(float2*)(C + (size_t)(row + 8) * NN + col) = v1;
        }
    }
}

// ------- kernel soft: row softmax; outputs Em/Nh as bf16 hi/lo aliases -----
__global__ void k_soft() {
    int i = blockIdx.x, b = blockIdx.y;
    size_t ro = ((size_t)b * NN + i) * NN;
    int c = threadIdx.x * 4;
    int wid = threadIdx.x >> 5, lane = threadIdx.x & 31;
    __shared__ float sE[8], sN[8];

    float4 ev = *(float4*)(g_EF + ro + c);
    float4 nv = *(float4*)(g_NG + ro + c);

    float mE = fmaxf(fmaxf(ev.x, ev.y), fmaxf(ev.z, ev.w));
    float mN = fmaxf(fmaxf(nv.x, nv.y), fmaxf(nv.z, nv.w));
    #pragma unroll
    for (int o = 16; o > 0; o >>= 1) {
        mE = fmaxf(mE, __shfl_xor_sync(0xffffffffu, mE, o));
        mN = fmaxf(mN, __shfl_xor_sync(0xffffffffu, mN, o));
    }
    if (lane == 0) { sE[wid] = mE; sN[wid] = mN; }
    __syncthreads();
    mE = sE[0]; mN = sN[0];
    #pragma unroll
    for (int wv = 1; wv < 8; wv++) { mE = fmaxf(mE, sE[wv]); mN = fmaxf(mN, sN[wv]); }
    __syncthreads();

    float4 eE, eN;
    eE.x = __expf(ev.x - mE); eE.y = __expf(ev.y - mE);
    eE.z = __expf(ev.z - mE); eE.w = __expf(ev.w - mE);
    eN.x = __expf(nv.x - mN); eN.y = __expf(nv.y - mN);
    eN.z = __expf(nv.z - mN); eN.w = __expf(nv.w - mN);
    float sumE = eE.x + eE.y + eE.z + eE.w;
    float sumN = eN.x + eN.y + eN.z + eN.w;
    #pragma unroll
    for (int o = 16; o > 0; o >>= 1) {
        sumE += __shfl_xor_sync(0xffffffffu, sumE, o);
        sumN += __shfl_xor_sync(0xffffffffu, sumN, o);
    }
    if (lane == 0) { sE[wid] = sumE; sN[wid] = sumN; }
    __syncthreads();
    sumE = 0.0f; sumN = 0.0f;
    #pragma unroll
    for (int wv = 0; wv < 8; wv++) { sumE += sE[wv]; sumN += sN[wv]; }

    float invE = __fdividef(1.0f, sumE);
    float invN = __fdividef(1.0f, sumN);

    float4 se;
    se.x = eE.x * invE; se.y = eE.y * invE; se.z = eE.z * invE; se.w = eE.w * invE;
    float4 nh;
    nh.x = __fdividef(eN.x * invN, se.x + 1e-5f);
    nh.y = __fdividef(eN.y * invN, se.y + 1e-5f);
    nh.z = __fdividef(eN.z * invN, se.z + 1e-5f);
    nh.w = __fdividef(eN.w * invN, se.w + 1e-5f);

    float4 am = *(float4*)(g_Amix + (size_t)i * NN + c);
    float4 em;
    em.x = se.x + am.x - ((c + 0 == i) ? 1.0f : 0.0f);
    em.y = se.y + am.y - ((c + 1 == i) ? 1.0f : 0.0f);
    em.z = se.z + am.z - ((c + 2 == i) ? 1.0f : 0.0f);
    em.w = se.w + am.w - ((c + 3 == i) ? 1.0f : 0.0f);

    __nv_bfloat16 h0, l0, h1, l1, h2, l2, h3, l3;
    bf16_split(em.x, h0, l0); bf16_split(em.y, h1, l1);
    bf16_split(em.z, h2, l2); bf16_split(em.w, h3, l3);
    *(__nv_bfloat162*)(g_sHi + ro + c)           = __nv_bfloat162{h0, h1};
    *(__nv_bfloat162*)(g_sHi + ro + c + 2)       = __nv_bfloat162{h2, h3};
    *(__nv_bfloat162*)(g_sHi + SZB + ro + c)     = __nv_bfloat162{l0, l1};
    *(__nv_bfloat162*)(g_sHi + SZB + ro + c + 2) = __nv_bfloat162{l2, l3};
    bf16_split(nh.x, h0, l0); bf16_split(nh.y, h1, l1);
    bf16_split(nh.z, h2, l2); bf16_split(nh.w, h3, l3);
    *(__nv_bfloat162*)(g_sLo + ro + c)           = __nv_bfloat162{h0, h1};
    *(__nv_bfloat162*)(g_sLo + ro + c + 2)       = __nv_bfloat162{h2, h3};
    *(__nv_bfloat162*)(g_sLo + SZB + ro + c)     = __nv_bfloat162{l0, l1};
    *(__nv_bfloat162*)(g_sLo + SZB + ro + c + 2) = __nv_bfloat162{l2, l3};
}

// --------- kernel final: f = tanh(Em@xr + add), g = tanh(Nh@xr) (bf16x3 MMA)
#define F_STR    80
#define F_TILE   (128*F_STR)
#define F_XSTR   144
#define F_XTILE  (32*F_XSTR)
#define F_XOFF   (4*F_TILE)
#define F_STAGE  (F_XOFF + 2*F_XTILE)
#define FIN_SMEM (2*F_STAGE)

__global__ void __launch_bounds__(256) k_final(float* __restrict__ out) {
    extern __shared__ char smf[];
    uint32_t smb = smem_u32(smf);
    int tid = threadIdx.x;
    int b = blockIdx.y, i0 = blockIdx.x * 128;
    const __nv_bfloat16* EmH = g_sHi + (size_t)b * NN * NN;
    const __nv_bfloat16* EmL = EmH + SZB;
    const __nv_bfloat16* NhH = g_sLo + (size_t)b * NN * NN;
    const __nv_bfloat16* NhL = NhH + SZB;
    const __nv_bfloat16* xHb = g_xH + (size_t)b * NN * DD;
    const __nv_bfloat16* xLb = g_xL + (size_t)b * NN * DD;

    int wid = tid >> 5, lane = tid & 31;
    int gid = lane >> 2, tg = lane & 3;
    int wm = (wid & 3) * 32, wn = (wid >> 2) * 32;

    int lr    = lane & 7;
    int lrow8 = (lane >> 3) & 1;
    int lk8   = (lane >> 4) & 1;
    uint32_t aoff = (uint32_t)((wm + lrow8 * 8 + lr) * F_STR + lk8 * 16);
    int quad = lane >> 3;
    int xkrow = (quad & 1) * 8 + lr;
    int xn8   = (quad >> 1) * 8;

    float accF[2][4][4], accG[2][4][4];
    #pragma unroll
    for (int mf = 0; mf < 2; mf++)
        #pragma unroll
        for (int nf = 0; nf < 4; nf++)
            #pragma unroll
            for (int q = 0; q < 4; q++) { accF[mf][nf][q] = 0.0f; accG[mf][nf][q] = 0.0f; }

    #define F_ISSUE(S) do {                                                      \
        uint32_t sb_ = smb + ((S) & 1) * F_STAGE;                                \
        int jc_ = (S) * 32;                                                      \
        _Pragma("unroll")                                                        \
        for (int it = 0; it < 10; it++) {                                        \
            int slot = tid + it * 256;                                           \
            if (slot < 2048) {                                                   \
                int tile = slot >> 9;                                            \
                int r2 = slot & 511;                                             \
                int row = r2 >> 2, ch = r2 & 3;                                  \
                const __nv_bfloat16* src =                                       \
                    (tile == 0) ? EmH : (tile == 1) ? EmL :                      \
                    (tile == 2) ? NhH : NhL;                                     \
                const char* gp = (const char*)(src + (size_t)(i0 + row) * NN + jc_ + ch * 8); \
                uint32_t sp = sb_ + (uint32_t)(tile * F_TILE + row * F_STR + ch * 16); \
                asm volatile("cp.async.ca.shared.global [%0], [%1], 16;"         \
                             :: "r"(sp), "l"(gp));                               \
            } else {                                                             \
                int t2 = slot - 2048;                                            \
                int xt = t2 >> 8;                                                \
                int r2 = t2 & 255;                                               \
                int row = r2 >> 3, ch = r2 & 7;                                  \
                const __nv_bfloat16* src = xt ? xLb : xHb;                       \
                const char* gp = (const char*)(src + (size_t)(jc_ + row) * DD + ch * 8); \
                uint32_t sp = sb_ + (uint32_t)(F_XOFF + xt * F_XTILE + row * F_XSTR + ch * 16); \
                asm volatile("cp.async.ca.shared.global [%0], [%1], 16;"         \
                             :: "r"(sp), "l"(gp));                               \
            }                                                                    \
        }                                                                        \
        asm volatile("cp.async.commit_group;");                                  \
    } while (0)

    F_ISSUE(0);
    for (int s = 0; s < NN / 32; s++) {
        if (s < NN / 32 - 1) {
            F_ISSUE(s + 1);
            asm volatile("cp.async.wait_group 1;");
        } else {
            asm volatile("cp.async.wait_group 0;");
        }
        __syncthreads();
        uint32_t base = smb + (s & 1) * F_STAGE;
        uint32_t tEh = base, tEl = base + F_TILE;
        uint32_t tNh = base + 2 * F_TILE, tNl = base + 3 * F_TILE;
        uint32_t tXh = base + F_XOFF, tXl = base + F_XOFF + F_XTILE;

        #pragma unroll
        for (int kh = 0; kh < 2; kh++) {
            uint32_t kb = (uint32_t)(kh * 32);
            uint32_t bxh[4][2], bxl[4][2];
            #pragma unroll
            for (int p = 0; p < 2; p++) {
                uint32_t xad = (uint32_t)((kh * 16 + xkrow) * F_XSTR + (wn + p * 16 + xn8) * 2);
                uint32_t th[4], tl[4];
                ldm_x4t(th, tXh + xad);
                ldm_x4t(tl, tXl + xad);
                bxh[2*p][0]   = th[0]; bxh[2*p][1]   = th[1];
                bxh[2*p+1][0] = th[2]; bxh[2*p+1][1] = th[3];
                bxl[2*p][0]   = tl[0]; bxl[2*p][1]   = tl[1];
                bxl[2*p+1][0] = tl[2]; bxl[2*p+1][1] = tl[3];
            }
            {
                uint32_t ah[2][4], al[2][4];
                #pragma unroll
                for (int mf = 0; mf < 2; mf++) {
                    uint32_t ao = aoff + (uint32_t)(mf * 16 * F_STR) + kb;
                    ldm_x4(ah[mf], tEh + ao);
                    ldm_x4(al[mf], tEl + ao);
                }
                // 3 sweeps: RAW distance = 8
                #pragma unroll
                for (int mf = 0; mf < 2; mf++)
                    #pragma unroll
                    for (int nf = 0; nf < 4; nf++)
                        mma16(accF[mf][nf], ah[mf], bxh[nf]);
                #pragma unroll
                for (int mf = 0; mf < 2; mf++)
                    #pragma unroll
                    for (int nf = 0; nf < 4; nf++)
                        mma16(accF[mf][nf], ah[mf], bxl[nf]);
                #pragma unroll
                for (int mf = 0; mf < 2; mf++)
                    #pragma unroll
                    for (int nf = 0; nf < 4; nf++)
                        mma16(accF[mf][nf], al[mf], bxh[nf]);
            }
            {
                uint32_t ah[2][4], al[2][4];
                #pragma unroll
                for (int mf = 0; mf < 2; mf++) {
                    uint32_t ao = aoff + (uint32_t)(mf * 16 * F_STR) + kb;
                    ldm_x4(ah[mf], tNh + ao);
                    ldm_x4(al[mf], tNl + ao);
                }
                #pragma unroll
                for (int mf = 0; mf < 2; mf++)
                    #pragma unroll
                    for (int nf = 0; nf < 4; nf++)
                        mma16(accG[mf][nf], ah[mf], bxh[nf]);
                #pragma unroll
                for (int mf = 0; mf < 2; mf++)
                    #pragma unroll
                    for (int nf = 0; nf < 4; nf++)
                        mma16(accG[mf][nf], ah[mf], bxl[nf]);
                #pragma unroll
                for (int mf = 0; mf < 2; mf++)
                    #pragma unroll
                    for (int nf = 0; nf < 4; nf++)
                        mma16(accG[mf][nf], al[mf], bxh[nf]);
            }
        }
        __syncthreads();
    }

    #pragma unroll
    for (int mf = 0; mf < 2; mf++) {
        #pragma unroll
        for (int nf = 0; nf < 4; nf++) {
            int row = i0 + wm + mf * 16 + gid;
            int col = wn + nf * 8 + tg * 2;
            size_t o0 = ((size_t)b * NN + row) * DD + col;
            size_t o1 = ((size_t)b * NN + row + 8) * DD + col;
            float2 a0 = *(const float2*)(g_add + o0);
            float2 a1 = *(const float2*)(g_add + o1);
            float2 f0, f1, g0, g1;
            f0.x = tanhf(accF[mf][nf][0] + a0.x);
            f0.y = tanhf(accF[mf][nf][1] + a0.y);
            f1.x = tanhf(accF[mf][nf][2] + a1.x);
            f1.y = tanhf(accF[mf][nf][3] + a1.y);
            g0.x = tanhf(accG[mf][nf][0]);
            g0.y = tanhf(accG[mf][nf][1]);
            g1.x = tanhf(accG[mf][nf][2]);
            g1.y = tanhf(accG[mf][nf][3]);
            *(float2*)(out + o0)        = f0;
            *(float2*)(out + o1)        = f1;
            *(float2*)(out + HALF + o0) = g0;
            *(float2*)(out + HALF + o1) = g1;
        }
    }
}

// ---------------- launch ----------------------------------------------------
extern "C" void kernel_launch(void* const* d_in, const int* in_sizes, int n_in,
                              void* d_out, int out_size) {
    const float* x     = (const float*)d_in[0];
    const float* x0    = (const float*)d_in[1];
    const float* w     = (const float*)d_in[2];
    const float* d     = (const float*)d_in[3];
    const float* alpha = (const float*)d_in[4];
    const float* fw1   = (const float*)d_in[5];
    const float* fw2   = (const float*)d_in[6];
    const float* fvs   = (const float*)d_in[7];
    const float* fbs   = (const float*)d_in[8];
    const float* gw1   = (const float*)d_in[9];
    const float* gw2   = (const float*)d_in[10];
    const float* gvs   = (const float*)d_in[11];
    const float* gbs   = (const float*)d_in[12];
    const float* convw = (const float*)d_in[13];
    const float* convb = (const float*)d_in[14];
    const float* adj   = (const float*)d_in[15];
    float* out = (float*)d_out;

    cudaFuncSetAttribute(k_gemm, cudaFuncAttributeMaxDynamicSharedMemorySize, GEMM_SMEM);
    cudaFuncSetAttribute(k_final, cudaFuncAttributeMaxDynamicSharedMemorySize, FIN_SMEM);

    k_evec   <<<(BB * NN) / 8, 256>>>(x, fw1, fw2, gw1, gw2);
    k_amix   <<<(NN * NN / 4) / 256, 256>>>(adj, convw);
    k_transp <<<dim3(32, 32, 2), dim3(32, 8)>>>(fbs, gbs);
    k_split  <<<(2 * NN * NN / 4) / 256, 256>>>(fvs, gvs);
    k_xsplit <<<(BB * NN * DD / 4) / 256, 256>>>(x);
    k_addterm<<<dim3(16, BB), 256>>>(x, x0, w, d, alpha, convb);
    k_sig    <<<dim3(NN, BB, 2), 256>>>();
    k_gemm   <<<dim3(8, 8, 2 * BB), 256, GEMM_SMEM>>>();
    k_soft   <<<dim3(NN, BB), 256>>>();
    k_final  <<<dim3(NN / 128, BB), 256, FIN_SMEM>>>(out);
}

// round 13
// speedup vs baseline: 1.0428x; 1.0095x over previous
#include <cuda_runtime.h>
#include <cuda_bf16.h>
#include <math.h>
#include <stdint.h>

#define BB 32
#define NN 1024
#define DD 64
#define HALF (BB*NN*DD)
#define SZB ((size_t)BB*NN*NN)

// ---------------- scratch (device globals; no allocation allowed) ----------
static __device__ __nv_bfloat16 g_sHi[2*SZB];  // phase1: sigmoid hi [which][b][n][j]
                                               // phase2: EmHi [0,SZB), EmLo [SZB,2SZB)
static __device__ __nv_bfloat16 g_sLo[2*SZB];  // phase1: sigmoid lo ; phase2: NhHi, NhLo
static __device__ __nv_bfloat16 g_vHi[(size_t)2*NN*NN];
static __device__ __nv_bfloat16 g_vLo[(size_t)2*NN*NN];
static __device__ __nv_bfloat16 g_xH[(size_t)BB*NN*DD];
static __device__ __nv_bfloat16 g_xL[(size_t)BB*NN*DD];
static __device__ float g_EF  [SZB];
static __device__ float g_NG  [SZB];
static __device__ float g_bsTf[(size_t)NN*NN];
static __device__ float g_bsTg[(size_t)NN*NN];
static __device__ float g_e1f[BB*NN], g_e2f[BB*NN], g_e1g[BB*NN], g_e2g[BB*NN];
static __device__ float g_Amix[NN*NN];
static __device__ float g_add[(size_t)BB*NN*DD];   // xw + cb + x0*sig(alpha)

__device__ __forceinline__ float sigm(float v) {
    return __fdividef(1.0f, 1.0f + __expf(-v));
}
__device__ __forceinline__ uint32_t smem_u32(const void* p) {
    uint32_t a;
    asm("{ .reg .u64 t; cvta.to.shared.u64 t, %1; cvt.u32.u64 %0, t; }" : "=r"(a) : "l"(p));
    return a;
}
__device__ __forceinline__ void bf16_split(float x, __nv_bfloat16& hi, __nv_bfloat16& lo) {
    hi = __float2bfloat16(x);
    lo = __float2bfloat16(x - __bfloat162float(hi));
}
__device__ __forceinline__ void mma16(float* c, const uint32_t* a, const uint32_t* b) {
    asm volatile("mma.sync.aligned.m16n8k16.row.col.f32.bf16.bf16.f32 "
                 "{%0,%1,%2,%3}, {%4,%5,%6,%7}, {%8,%9}, {%0,%1,%2,%3};"
                 : "+f"(c[0]), "+f"(c[1]), "+f"(c[2]), "+f"(c[3])
                 : "r"(a[0]), "r"(a[1]), "r"(a[2]), "r"(a[3]),
                   "r"(b[0]), "r"(b[1]));
}
__device__ __forceinline__ void ldm_x4(uint32_t* r, uint32_t addr) {
    asm volatile("ldmatrix.sync.aligned.m8n8.x4.shared.b16 {%0,%1,%2,%3}, [%4];"
                 : "=r"(r[0]), "=r"(r[1]), "=r"(r[2]), "=r"(r[3]) : "r"(addr));
}
__device__ __forceinline__ void ldm_x4t(uint32_t* r, uint32_t addr) {
    asm volatile("ldmatrix.sync.aligned.m8n8.x4.trans.shared.b16 {%0,%1,%2,%3}, [%4];"
                 : "=r"(r[0]), "=r"(r[1]), "=r"(r[2]), "=r"(r[3]) : "r"(addr));
}

// ---------------- kernel: e1/e2 row dots -----------------------------------
__global__ void k_evec(const float* __restrict__ x,
                       const float* __restrict__ fw1, const float* __restrict__ fw2,
                       const float* __restrict__ gw1, const float* __restrict__ gw2) {
    int gwarp = (blockIdx.x * blockDim.x + threadIdx.x) >> 5;
    int lane  = threadIdx.x & 31;
    const float* xp = x + (size_t)gwarp * DD;
    float v0 = xp[lane], v1 = xp[lane + 32];
    float s0 = v0 * fw1[lane] + v1 * fw1[lane + 32];
    float s1 = v0 * fw2[lane] + v1 * fw2[lane + 32];
    float s2 = v0 * gw1[lane] + v1 * gw1[lane + 32];
    float s3 = v0 * gw2[lane] + v1 * gw2[lane + 32];
    #pragma unroll
    for (int o = 16; o > 0; o >>= 1) {
        s0 += __shfl_xor_sync(0xffffffffu, s0, o);
        s1 += __shfl_xor_sync(0xffffffffu, s1, o);
        s2 += __shfl_xor_sync(0xffffffffu, s2, o);
        s3 += __shfl_xor_sync(0xffffffffu, s3, o);
    }
    if (lane == 0) {
        g_e1f[gwarp] = s0; g_e2f[gwarp] = s1;
        g_e1g[gwarp] = s2; g_e2g[gwarp] = s3;
    }
}

// ---------------- kernel: A_mix --------------------------------------------
__global__ void k_amix(const float* __restrict__ adj, const float* __restrict__ convw) {
    int t = blockIdx.x * blockDim.x + threadIdx.x;
    int base = t * 4;
    int i = base >> 10;
    int j = base & (NN - 1);
    float c0 = convw[0], c1 = convw[1];
    float dsub = c0 + c1;
    float4 a0 = *(const float4*)(adj + base);
    float4 a1 = *(const float4*)(adj + (size_t)NN * NN + base);
    float4 r;
    r.x = c0 * a0.x + c1 * a1.x - ((i == j + 0) ? dsub : 0.0f);
    r.y = c0 * a0.y + c1 * a1.y - ((i == j + 1) ? dsub : 0.0f);
    r.z = c0 * a0.z + c1 * a1.z - ((i == j + 2) ? dsub : 0.0f);
    r.w = c0 * a0.w + c1 * a1.w - ((i == j + 3) ? dsub : 0.0f);
    *(float4*)(g_Amix + base) = r;
}

// ---------------- kernel: transpose fbs/gbs --------------------------------
__global__ void k_transp(const float* __restrict__ fbs, const float* __restrict__ gbs) {
    __shared__ float t[32][33];
    const float* src = blockIdx.z ? gbs : fbs;
    float* dst = blockIdx.z ? g_bsTg : g_bsTf;
    int x0 = blockIdx.x * 32, y0 = blockIdx.y * 32;
    #pragma unroll
    for (int r = threadIdx.y; r < 32; r += 8)
        t[r][threadIdx.x] = src[(size_t)(y0 + r) * NN + x0 + threadIdx.x];
    __syncthreads();
    #pragma unroll
    for (int r = threadIdx.y; r < 32; r += 8)
        dst[(size_t)(x0 + r) * NN + y0 + threadIdx.x] = t[threadIdx.x][r];
}

// ---------------- kernel: bf16-split vs ------------------------------------
__global__ void k_split(const float* __restrict__ fvs, const float* __restrict__ gvs) {
    int t = blockIdx.x * blockDim.x + threadIdx.x;
    int which = t >= (NN * NN / 4);
    int e = which ? t - NN * NN / 4 : t;
    const float4* src = (const float4*)(which ? gvs : fvs);
    float4 a = src[e];
    __nv_bfloat16 h0, l0, h1, l1, h2, l2, h3, l3;
    bf16_split(a.x, h0, l0); bf16_split(a.y, h1, l1);
    bf16_split(a.z, h2, l2); bf16_split(a.w, h3, l3);
    size_t off = (size_t)which * NN * NN + (size_t)e * 4;
    __nv_bfloat162* ph = (__nv_bfloat162*)(g_vHi + off);
    __nv_bfloat162* pl = (__nv_bfloat162*)(g_vLo + off);
    ph[0] = __nv_bfloat162{h0, h1}; ph[1] = __nv_bfloat162{h2, h3};
    pl[0] = __nv_bfloat162{l0, l1}; pl[1] = __nv_bfloat162{l2, l3};
}

// ---------------- kernel: bf16-split x -------------------------------------
__global__ void k_xsplit(const float* __restrict__ x) {
    int e = blockIdx.x * blockDim.x + threadIdx.x;
    float4 a = ((const float4*)x)[e];
    __nv_bfloat16 h0, l0, h1, l1, h2, l2, h3, l3;
    bf16_split(a.x, h0, l0); bf16_split(a.y, h1, l1);
    bf16_split(a.z, h2, l2); bf16_split(a.w, h3, l3);
    size_t off = (size_t)e * 4;
    __nv_bfloat162* ph = (__nv_bfloat162*)(g_xH + off);
    __nv_bfloat162* pl = (__nv_bfloat162*)(g_xL + off);
    ph[0] = __nv_bfloat162{h0, h1}; ph[1] = __nv_bfloat162{h2, h3};
    pl[0] = __nv_bfloat162{l0, l1}; pl[1] = __nv_bfloat162{l2, l3};
}

// ------- kernel addterm: g_add = xr@W_hat + cb + x0*sigm(alpha) ------------
#define XSTRIDE 68
__global__ void __launch_bounds__(256) k_addterm(
        const float* __restrict__ x, const float* __restrict__ x0,
        const float* __restrict__ w, const float* __restrict__ d,
        const float* __restrict__ alpha, const float* __restrict__ convb) {
    __shared__ float sWh[64 * 64];
    __shared__ float sXi[64 * XSTRIDE];
    int b = blockIdx.y, i0 = blockIdx.x * 64;
    int tid = threadIdx.x;

    #pragma unroll
    for (int e = 0; e < 16; e++) {
        int idx = tid + e * 256;
        int i = idx >> 6, j = idx & 63;
        float s = 0.0f;
        #pragma unroll 8
        for (int k = 0; k < DD; k++) {
            float dc = fminf(fmaxf(d[k], 0.0f), 1.0f);
            s += w[i * DD + k] * dc * w[j * DD + k];
        }
        sWh[idx] = s - ((i == j) ? 1.0f : 0.0f);
    }
    #pragma unroll
    for (int q = 0; q < 4; q++) {
        int lin = tid + q * 256;
        int row = lin >> 4, cc = (lin & 15) * 4;
        *(float4*)&sXi[row * XSTRIDE + cc] =
            *(const float4*)(x + (size_t)(b * NN + i0 + row) * DD + cc);
    }
    __syncthreads();

    int il = tid >> 2, c0 = (tid & 3) * 16;
    float acc[16];
    #pragma unroll
    for (int q = 0; q < 16; q++) acc[q] = 0.0f;
    #pragma unroll 8
    for (int k = 0; k < DD; k++) {
        float xik = sXi[il * XSTRIDE + k];
        #pragma unroll
        for (int q = 0; q < 4; q++) {
            float4 wv = *(float4*)&sWh[k * 64 + c0 + q * 4];
            acc[q * 4 + 0] += xik * wv.x; acc[q * 4 + 1] += xik * wv.y;
            acc[q * 4 + 2] += xik * wv.z; acc[q * 4 + 3] += xik * wv.w;
        }
    }
    float cb = convb[0];
    float sa = sigm(alpha[i0 + il]);
    size_t obase = ((size_t)b * NN + i0 + il) * DD + c0;
    #pragma unroll
    for (int q = 0; q < 4; q++) {
        float4 x0v = *(const float4*)(x0 + obase + q * 4);
        float4 r;
        r.x = acc[q * 4 + 0] + cb + x0v.x * sa;
        r.y = acc[q * 4 + 1] + cb + x0v.y * sa;
        r.z = acc[q * 4 + 2] + cb + x0v.z * sa;
        r.w = acc[q * 4 + 3] + cb + x0v.w * sa;
        *(float4*)(g_add + obase + q * 4) = r;
    }
}

// -------- kernel sig: S[b,n,j] = sigmoid(e2[b,n]*e1[b,j] + bsT[n,j]), hi/lo
__global__ void k_sig(void) {
    int n = blockIdx.x, b = blockIdx.y, which = blockIdx.z;
    int j = threadIdx.x * 4;
    const float* e1 = which ? g_e1g : g_e1f;
    const float* e2 = which ? g_e2g : g_e2f;
    const float* bsT = (which ? g_bsTg : g_bsTf) + (size_t)n * NN + j;
    size_t off = (((size_t)which * BB + b) * NN + n) * NN + j;
    float  a   = e2[b * NN + n];
    float4 e1v = *(const float4*)(e1 + b * NN + j);
    float4 bv  = *(const float4*)bsT;
    float sx = sigm(a * e1v.x + bv.x);
    float sy = sigm(a * e1v.y + bv.y);
    float sz = sigm(a * e1v.z + bv.z);
    float sw = sigm(a * e1v.w + bv.w);
    __nv_bfloat16 h0, l0, h1, l1, h2, l2, h3, l3;
    bf16_split(sx, h0, l0); bf16_split(sy, h1, l1);
    bf16_split(sz, h2, l2); bf16_split(sw, h3, l3);
    __nv_bfloat162* ph = (__nv_bfloat162*)(g_sHi + off);
    __nv_bfloat162* pl = (__nv_bfloat162*)(g_sLo + off);
    ph[0] = __nv_bfloat162{h0, h1}; ph[1] = __nv_bfloat162{h2, h3};
    pl[0] = __nv_bfloat162{l0, l1}; pl[1] = __nv_bfloat162{l2, l3};
}

// ------- kernel gemm: bf16x3 mma.sync batched GEMM -------------------------
// CTA 128x128, 8 warps (2x4), warp tile 64x32, K-tile 32, single z=64 launch.
// CUTLASS barrier ordering: wait -> sync -> issue(s+1) -> compute(s).
// ONE __syncthreads per stage (was two).
#define KT     32
#define STRB   80
#define TILE_BYTES (128*STRB)
#define STAGE_BYTES (4*TILE_BYTES)
#define GEMM_SMEM  (2*STAGE_BYTES)

__global__ void __launch_bounds__(256) k_gemm() {
    extern __shared__ char smg[];
    uint32_t smb = smem_u32(smg);
    int tid = threadIdx.x;
    int z = blockIdx.z;
    int b = z & (BB - 1);
    int which = z >> 5;
    const __nv_bfloat16* __restrict__ Ahi = g_vHi + (size_t)which * NN * NN;
    const __nv_bfloat16* __restrict__ Alo = g_vLo + (size_t)which * NN * NN;
    const __nv_bfloat16* __restrict__ Bhi = g_sHi + ((size_t)which * BB + b) * NN * NN;
    const __nv_bfloat16* __restrict__ Blo = g_sLo + ((size_t)which * BB + b) * NN * NN;
    float* __restrict__ C = (which ? g_NG : g_EF) + (size_t)b * NN * NN;
    int i0 = blockIdx.y * 128, n0 = blockIdx.x * 128;

    int wid = tid >> 5, lane = tid & 31;
    int gid = lane >> 2, tg = lane & 3;
    int wm = (wid & 1) * 64, wn = (wid >> 1) * 32;

    int lr    = lane & 7;
    int lrow8 = (lane >> 3) & 1;
    int lk8   = (lane >> 4) & 1;
    uint32_t aoff = (uint32_t)((wm + lrow8 * 8 + lr) * STRB + lk8 * 16);
    uint32_t boff = (uint32_t)((wn + lrow8 * 8 + lr) * STRB + lk8 * 16);

    int slot_tile[8], slot_row[8], slot_ch[8];
    #pragma unroll
    for (int it = 0; it < 8; it++) {
        int slot = tid + it * 256;
        slot_tile[it] = slot >> 9;
        int r2 = slot & 511;
        slot_row[it] = r2 >> 2;
        slot_ch[it]  = r2 & 3;
    }

    float acc[4][4][4];
    #pragma unroll
    for (int mf = 0; mf < 4; mf++)
        #pragma unroll
        for (int nf = 0; nf < 4; nf++)
            #pragma unroll
            for (int q = 0; q < 4; q++) acc[mf][nf][q] = 0.0f;

    #define G_ISSUE(S) do {                                                      \
        uint32_t sb_ = smb + ((S) & 1) * STAGE_BYTES;                            \
        int kc_ = (S) * KT;                                                      \
        _Pragma("unroll")                                                        \
        for (int it = 0; it < 8; it++) {                                         \
            int tile = slot_tile[it], row = slot_row[it], ch = slot_ch[it];      \
            const __nv_bfloat16* src =                                           \
                (tile == 0) ? Ahi + (size_t)(i0 + row) * NN :                    \
                (tile == 1) ? Alo + (size_t)(i0 + row) * NN :                    \
                (tile == 2) ? Bhi + (size_t)(n0 + row) * NN :                    \
                              Blo + (size_t)(n0 + row) * NN;                     \
            const char* gp = (const char*)(src + kc_) + ch * 16;                 \
            uint32_t sp = sb_ + (uint32_t)(tile * TILE_BYTES + row * STRB + ch * 16); \
            asm volatile("cp.async.ca.shared.global [%0], [%1], 16;"             \
                         :: "r"(sp), "l"(gp));                                   \
        }                                                                        \
        asm volatile("cp.async.commit_group;");                                  \
    } while (0)

    G_ISSUE(0);
    for (int s = 0; s < NN / KT; s++) {
        asm volatile("cp.async.wait_group 0;");
        __syncthreads();
        if (s < NN / KT - 1) G_ISSUE(s + 1);

        uint32_t base = smb + (s & 1) * STAGE_BYTES;
        uint32_t tAh = base, tAl = base + TILE_BYTES;
        uint32_t tBh = base + 2 * TILE_BYTES, tBl = base + 3 * TILE_BYTES;

        #pragma unroll
        for (int kh = 0; kh < 2; kh++) {
            uint32_t kb = (uint32_t)(kh * 32);
            uint32_t ah[4][4], al[4][4], bh[4][2], bl[4][2];
            #pragma unroll
            for (int mf = 0; mf < 4; mf++) {
                uint32_t ao = aoff + (uint32_t)(mf * 16 * STRB) + kb;
                ldm_x4(ah[mf], tAh + ao);
                ldm_x4(al[mf], tAl + ao);
            }
            #pragma unroll
            for (int p = 0; p < 2; p++) {
                uint32_t bo = boff + (uint32_t)(p * 16 * STRB) + kb;
                uint32_t th[4], tl[4];
                ldm_x4(th, tBh + bo);
                ldm_x4(tl, tBl + bo);
                bh[2*p][0]   = th[0]; bh[2*p][1]   = th[2];
                bh[2*p+1][0] = th[1]; bh[2*p+1][1] = th[3];
                bl[2*p][0]   = tl[0]; bl[2*p][1]   = tl[2];
                bl[2*p+1][0] = tl[1]; bl[2*p+1][1] = tl[3];
            }
            #pragma unroll
            for (int mf = 0; mf < 4; mf++)
                #pragma unroll
                for (int nf = 0; nf < 4; nf++)
                    mma16(acc[mf][nf], ah[mf], bh[nf]);
            #pragma unroll
            for (int mf = 0; mf < 4; mf++)
                #pragma unroll
                for (int nf = 0; nf < 4; nf++)
                    mma16(acc[mf][nf], ah[mf], bl[nf]);
            #pragma unroll
            for (int mf = 0; mf < 4; mf++)
                #pragma unroll
                for (int nf = 0; nf < 4; nf++)
                    mma16(acc[mf][nf], al[mf], bh[nf]);
        }
    }

    #pragma unroll
    for (int mf = 0; mf < 4; mf++) {
        #pragma unroll
        for (int nf = 0; nf < 4; nf++) {
            int row = i0 + wm + mf * 16 + gid;
            int col = n0 + wn + nf * 8 + tg * 2;
            float2 v0 = make_float2(acc[mf][nf][0], acc[mf][nf][1]);
            float2 v1 = make_float2(acc[mf][nf][2], acc[mf][nf][3]);
            *(float2*)(C + (size_t)row * NN + col)       = v0;
            *(float2*)(C + (size_t)(row + 8) * NN + col) = v1;
        }
    }
}

// ------- kernel soft: row softmax; outputs Em/Nh as bf16 hi/lo aliases -----
__global__ void k_soft() {
    int i = blockIdx.x, b = blockIdx.y;
    size_t ro = ((size_t)b * NN + i) * NN;
    int c = threadIdx.x * 4;
    int wid = threadIdx.x >> 5, lane = threadIdx.x & 31;
    __shared__ float sE[8], sN[8];

    float4 ev = *(float4*)(g_EF + ro + c);
    float4 nv = *(float4*)(g_NG + ro + c);

    float mE = fmaxf(fmaxf(ev.x, ev.y), fmaxf(ev.z, ev.w));
    float mN = fmaxf(fmaxf(nv.x, nv.y), fmaxf(nv.z, nv.w));
    #pragma unroll
    for (int o = 16; o > 0; o >>= 1) {
        mE = fmaxf(mE, __shfl_xor_sync(0xffffffffu, mE, o));
        mN = fmaxf(mN, __shfl_xor_sync(0xffffffffu, mN, o));
    }
    if (lane == 0) { sE[wid] = mE; sN[wid] = mN; }
    __syncthreads();
    mE = sE[0]; mN = sN[0];
    #pragma unroll
    for (int wv = 1; wv < 8; wv++) { mE = fmaxf(mE, sE[wv]); mN = fmaxf(mN, sN[wv]); }
    __syncthreads();

    float4 eE, eN;
    eE.x = __expf(ev.x - mE); eE.y = __expf(ev.y - mE);
    eE.z = __expf(ev.z - mE); eE.w = __expf(ev.w - mE);
    eN.x = __expf(nv.x - mN); eN.y = __expf(nv.y - mN);
    eN.z = __expf(nv.z - mN); eN.w = __expf(nv.w - mN);
    float sumE = eE.x + eE.y + eE.z + eE.w;
    float sumN = eN.x + eN.y + eN.z + eN.w;
    #pragma unroll
    for (int o = 16; o > 0; o >>= 1) {
        sumE += __shfl_xor_sync(0xffffffffu, sumE, o);
        sumN += __shfl_xor_sync(0xffffffffu, sumN, o);
    }
    if (lane == 0) { sE[wid] = sumE; sN[wid] = sumN; }
    __syncthreads();
    sumE = 0.0f; sumN = 0.0f;
    #pragma unroll
    for (int wv = 0; wv < 8; wv++) { sumE += sE[wv]; sumN += sN[wv]; }

    float invE = __fdividef(1.0f, sumE);
    float invN = __fdividef(1.0f, sumN);

    float4 se;
    se.x = eE.x * invE; se.y = eE.y * invE; se.z = eE.z * invE; se.w = eE.w * invE;
    float4 nh;
    nh.x = __fdividef(eN.x * invN, se.x + 1e-5f);
    nh.y = __fdividef(eN.y * invN, se.y + 1e-5f);
    nh.z = __fdividef(eN.z * invN, se.z + 1e-5f);
    nh.w = __fdividef(eN.w * invN, se.w + 1e-5f);

    float4 am = *(float4*)(g_Amix + (size_t)i * NN + c);
    float4 em;
    em.x = se.x + am.x - ((c + 0 == i) ? 1.0f : 0.0f);
    em.y = se.y + am.y - ((c + 1 == i) ? 1.0f : 0.0f);
    em.z = se.z + am.z - ((c + 2 == i) ? 1.0f : 0.0f);
    em.w = se.w + am.w - ((c + 3 == i) ? 1.0f : 0.0f);

    __nv_bfloat16 h0, l0, h1, l1, h2, l2, h3, l3;
    bf16_split(em.x, h0, l0); bf16_split(em.y, h1, l1);
    bf16_split(em.z, h2, l2); bf16_split(em.w, h3, l3);
    *(__nv_bfloat162*)(g_sHi + ro + c)           = __nv_bfloat162{h0, h1};
    *(__nv_bfloat162*)(g_sHi + ro + c + 2)       = __nv_bfloat162{h2, h3};
    *(__nv_bfloat162*)(g_sHi + SZB + ro + c)     = __nv_bfloat162{l0, l1};
    *(__nv_bfloat162*)(g_sHi + SZB + ro + c + 2) = __nv_bfloat162{l2, l3};
    bf16_split(nh.x, h0, l0); bf16_split(nh.y, h1, l1);
    bf16_split(nh.z, h2, l2); bf16_split(nh.w, h3, l3);
    *(__nv_bfloat162*)(g_sLo + ro + c)           = __nv_bfloat162{h0, h1};
    *(__nv_bfloat162*)(g_sLo + ro + c + 2)       = __nv_bfloat162{h2, h3};
    *(__nv_bfloat162*)(g_sLo + SZB + ro + c)     = __nv_bfloat162{l0, l1};
    *(__nv_bfloat162*)(g_sLo + SZB + ro + c + 2) = __nv_bfloat162{l2, l3};
}

// --------- kernel final: f = tanh(Em@xr + add), g = tanh(Nh@xr) (bf16x3 MMA)
// Same single-sync-per-stage restructure.
#define F_STR    80
#define F_TILE   (128*F_STR)
#define F_XSTR   144
#define F_XTILE  (32*F_XSTR)
#define F_XOFF   (4*F_TILE)
#define F_STAGE  (F_XOFF + 2*F_XTILE)
#define FIN_SMEM (2*F_STAGE)

__global__ void __launch_bounds__(256) k_final(float* __restrict__ out) {
    extern __shared__ char smf[];
    uint32_t smb = smem_u32(smf);
    int tid = threadIdx.x;
    int b = blockIdx.y, i0 = blockIdx.x * 128;
    const __nv_bfloat16* EmH = g_sHi + (size_t)b * NN * NN;
    const __nv_bfloat16* EmL = EmH + SZB;
    const __nv_bfloat16* NhH = g_sLo + (size_t)b * NN * NN;
    const __nv_bfloat16* NhL = NhH + SZB;
    const __nv_bfloat16* xHb = g_xH + (size_t)b * NN * DD;
    const __nv_bfloat16* xLb = g_xL + (size_t)b * NN * DD;

    int wid = tid >> 5, lane = tid & 31;
    int gid = lane >> 2, tg = lane & 3;
    int wm = (wid & 3) * 32, wn = (wid >> 2) * 32;

    int lr    = lane & 7;
    int lrow8 = (lane >> 3) & 1;
    int lk8   = (lane >> 4) & 1;
    uint32_t aoff = (uint32_t)((wm + lrow8 * 8 + lr) * F_STR + lk8 * 16);
    int quad = lane >> 3;
    int xkrow = (quad & 1) * 8 + lr;
    int xn8   = (quad >> 1) * 8;

    float accF[2][4][4], accG[2][4][4];
    #pragma unroll
    for (int mf = 0; mf < 2; mf++)
        #pragma unroll
        for (int nf = 0; nf < 4; nf++)
            #pragma unroll
            for (int q = 0; q < 4; q++) { accF[mf][nf][q] = 0.0f; accG[mf][nf][q] = 0.0f; }

    #define F_ISSUE(S) do {                                                      \
        uint32_t sb_ = smb + ((S) & 1) * F_STAGE;                                \
        int jc_ = (S) * 32;                                                      \
        _Pragma("unroll")                                                        \
        for (int it = 0; it < 10; it++) {                                        \
            int slot = tid + it * 256;                                           \
            if (slot < 2048) {                                                   \
                int tile = slot >> 9;                                            \
                int r2 = slot & 511;                                             \
                int row = r2 >> 2, ch = r2 & 3;                                  \
                const __nv_bfloat16* src =                                       \
                    (tile == 0) ? EmH : (tile == 1) ? EmL :                      \
                    (tile == 2) ? NhH : NhL;                                     \
                const char* gp = (const char*)(src + (size_t)(i0 + row) * NN + jc_ + ch * 8); \
                uint32_t sp = sb_ + (uint32_t)(tile * F_TILE + row * F_STR + ch * 16); \
                asm volatile("cp.async.ca.shared.global [%0], [%1], 16;"         \
                             :: "r"(sp), "l"(gp));                               \
            } else {                                                             \
                int t2 = slot - 2048;                                            \
                int xt = t2 >> 8;                                                \
                int r2 = t2 & 255;                                               \
                int row = r2 >> 3, ch = r2 & 7;                                  \
                const __nv_bfloat16* src = xt ? xLb : xHb;                       \
                const char* gp = (const char*)(src + (size_t)(jc_ + row) * DD + ch * 8); \
                uint32_t sp = sb_ + (uint32_t)(F_XOFF + xt * F_XTILE + row * F_XSTR + ch * 16); \
                asm volatile("cp.async.ca.shared.global [%0], [%1], 16;"         \
                             :: "r"(sp), "l"(gp));                               \
            }                                                                    \
        }                                                                        \
        asm volatile("cp.async.commit_group;");                                  \
    } while (0)

    F_ISSUE(0);
    for (int s = 0; s < NN / 32; s++) {
        asm volatile("cp.async.wait_group 0;");
        __syncthreads();
        if (s < NN / 32 - 1) F_ISSUE(s + 1);

        uint32_t base = smb + (s & 1) * F_STAGE;
        uint32_t tEh = base, tEl = base + F_TILE;
        uint32_t tNh = base + 2 * F_TILE, tNl = base + 3 * F_TILE;
        uint32_t tXh = base + F_XOFF, tXl = base + F_XOFF + F_XTILE;

        #pragma unroll
        for (int kh = 0; kh < 2; kh++) {
            uint32_t kb = (uint32_t)(kh * 32);
            uint32_t bxh[4][2], bxl[4][2];
            #pragma unroll
            for (int p = 0; p < 2; p++) {
                uint32_t xad = (uint32_t)((kh * 16 + xkrow) * F_XSTR + (wn + p * 16 + xn8) * 2);
                uint32_t th[4], tl[4];
                ldm_x4t(th, tXh + xad);
                ldm_x4t(tl, tXl + xad);
                bxh[2*p][0]   = th[0]; bxh[2*p][1]   = th[1];
                bxh[2*p+1][0] = th[2]; bxh[2*p+1][1] = th[3];
                bxl[2*p][0]   = tl[0]; bxl[2*p][1]   = tl[1];
                bxl[2*p+1][0] = tl[2]; bxl[2*p+1][1] = tl[3];
            }
            {
                uint32_t ah[2][4], al[2][4];
                #pragma unroll
                for (int mf = 0; mf < 2; mf++) {
                    uint32_t ao = aoff + (uint32_t)(mf * 16 * F_STR) + kb;
                    ldm_x4(ah[mf], tEh + ao);
                    ldm_x4(al[mf], tEl + ao);
                }
                #pragma unroll
                for (int mf = 0; mf < 2; mf++)
                    #pragma unroll
                    for (int nf = 0; nf < 4; nf++)
                        mma16(accF[mf][nf], ah[mf], bxh[nf]);
                #pragma unroll
                for (int mf = 0; mf < 2; mf++)
                    #pragma unroll
                    for (int nf = 0; nf < 4; nf++)
                        mma16(accF[mf][nf], ah[mf], bxl[nf]);
                #pragma unroll
                for (int mf = 0; mf < 2; mf++)
                    #pragma unroll
                    for (int nf = 0; nf < 4; nf++)
                        mma16(accF[mf][nf], al[mf], bxh[nf]);
            }
            {
                uint32_t ah[2][4], al[2][4];
                #pragma unroll
                for (int mf = 0; mf < 2; mf++) {
                    uint32_t ao = aoff + (uint32_t)(mf * 16 * F_STR) + kb;
                    ldm_x4(ah[mf], tNh + ao);
                    ldm_x4(al[mf], tNl + ao);
                }
                #pragma unroll
                for (int mf = 0; mf < 2; mf++)
                    #pragma unroll
                    for (int nf = 0; nf < 4; nf++)
                        mma16(accG[mf][nf], ah[mf], bxh[nf]);
                #pragma unroll
                for (int mf = 0; mf < 2; mf++)
                    #pragma unroll
                    for (int nf = 0; nf < 4; nf++)
                        mma16(accG[mf][nf], ah[mf], bxl[nf]);
                #pragma unroll
                for (int mf = 0; mf < 2; mf++)
                    #pragma unroll
                    for (int nf = 0; nf < 4; nf++)
                        mma16(accG[mf][nf], al[mf], bxh[nf]);
            }
        }
    }

    #pragma unroll
    for (int mf = 0; mf < 2; mf++) {
        #pragma unroll
        for (int nf = 0; nf < 4; nf++) {
            int row = i0 + wm + mf * 16 + gid;
            int col = wn + nf * 8 + tg * 2;
            size_t o0 = ((size_t)b * NN + row) * DD + col;
            size_t o1 = ((size_t)b * NN + row + 8) * DD + col;
            float2 a0 = *(const float2*)(g_add + o0);
            float2 a1 = *(const float2*)(g_add + o1);
            float2 f0, f1, g0, g1;
            f0.x = tanhf(accF[mf][nf][0] + a0.x);
            f0.y = tanhf(accF[mf][nf][1] + a0.y);
            f1.x = tanhf(accF[mf][nf][2] + a1.x);
            f1.y = tanhf(accF[mf][nf][3] + a1.y);
            g0.x = tanhf(accG[mf][nf][0]);
            g0.y = tanhf(accG[mf][nf][1]);
            g1.x = tanhf(accG[mf][nf][2]);
            g1.y = tanhf(accG[mf][nf][3]);
            *(float2*)(out + o0)        = f0;
            *(float2*)(out + o1)        = f1;
            *(float2*)(out + HALF + o0) = g0;
            *(float2*)(out + HALF + o1) = g1;
        }
    }
}

// ---------------- launch ----------------------------------------------------
extern "C" void kernel_launch(void* const* d_in, const int* in_sizes, int n_in,
                              void* d_out, int out_size) {
    const float* x     = (const float*)d_in[0];
    const float* x0    = (const float*)d_in[1];
    const float* w     = (const float*)d_in[2];
    const float* d     = (const float*)d_in[3];
    const float* alpha = (const float*)d_in[4];
    const float* fw1   = (const float*)d_in[5];
    const float* fw2   = (const float*)d_in[6];
    const float* fvs   = (const float*)d_in[7];
    const float* fbs   = (const float*)d_in[8];
    const float* gw1   = (const float*)d_in[9];
    const float* gw2   = (const float*)d_in[10];
    const float* gvs   = (const float*)d_in[11];
    const float* gbs   = (const float*)d_in[12];
    const float* convw = (const float*)d_in[13];
    const float* convb = (const float*)d_in[14];
    const float* adj   = (const float*)d_in[15];
    float* out = (float*)d_out;

    cudaFuncSetAttribute(k_gemm, cudaFuncAttributeMaxDynamicSharedMemorySize, GEMM_SMEM);
    cudaFuncSetAttribute(k_final, cudaFuncAttributeMaxDynamicSharedMemorySize, FIN_SMEM);

    k_evec   <<<(BB * NN) / 8, 256>>>(x, fw1, fw2, gw1, gw2);
    k_amix   <<<(NN * NN / 4) / 256, 256>>>(adj, convw);
    k_transp <<<dim3(32, 32, 2), dim3(32, 8)>>>(fbs, gbs);
    k_split  <<<(2 * NN * NN / 4) / 256, 256>>>(fvs, gvs);
    k_xsplit <<<(BB * NN * DD / 4) / 256, 256>>>(x);
    k_addterm<<<dim3(16, BB), 256>>>(x, x0, w, d, alpha, convb);
    k_sig    <<<dim3(NN, BB, 2), 256>>>();
    k_gemm   <<<dim3(8, 8, 2 * BB), 256, GEMM_SMEM>>>();
    k_soft   <<<dim3(NN, BB), 256>>>();
    k_final  <<<dim3(NN / 128, BB), 256, FIN_SMEM>>>(out);
}

// round 14
// speedup vs baseline: 1.0894x; 1.0446x over previous
#include <cuda_runtime.h>
#include <cuda_bf16.h>
#include <math.h>
#include <stdint.h>

#define BB 32
#define NN 1024
#define DD 64
#define HALF (BB*NN*DD)
#define SZB ((size_t)BB*NN*NN)

// ---------------- scratch (device globals; no allocation allowed) ----------
static __device__ __nv_bfloat16 g_sHi[2*SZB];  // sigmoid hi [which][b][n][j]
static __device__ __nv_bfloat16 g_sLo[2*SZB];  // sigmoid lo
static __device__ __nv_bfloat16 g_vHi[(size_t)2*NN*NN];
static __device__ __nv_bfloat16 g_vLo[(size_t)2*NN*NN];
static __device__ float g_EF  [SZB];   // E_pre -> (softmax(E) - I + Amix)
static __device__ float g_NG  [SZB];   // N_pre -> N_hat
static __device__ float g_bsTf[(size_t)NN*NN];
static __device__ float g_bsTg[(size_t)NN*NN];
static __device__ float g_e1f[BB*NN], g_e2f[BB*NN], g_e1g[BB*NN], g_e2g[BB*NN];
static __device__ float g_Amix[NN*NN];
static __device__ float g_What[DD*DD];
static __device__ float g_salpha[NN];

__device__ __forceinline__ float sigm(float v) {
    return __fdividef(1.0f, 1.0f + __expf(-v));
}
__device__ __forceinline__ uint32_t smem_u32(const void* p) {
    uint32_t a;
    asm("{ .reg .u64 t; cvta.to.shared.u64 t, %1; cvt.u32.u64 %0, t; }" : "=r"(a) : "l"(p));
    return a;
}
__device__ __forceinline__ void bf16_split(float x, __nv_bfloat16& hi, __nv_bfloat16& lo) {
    hi = __float2bfloat16(x);
    lo = __float2bfloat16(x - __bfloat162float(hi));
}
__device__ __forceinline__ void mma16(float* c, const uint32_t* a, const uint32_t* b) {
    asm volatile("mma.sync.aligned.m16n8k16.row.col.f32.bf16.bf16.f32 "
                 "{%0,%1,%2,%3}, {%4,%5,%6,%7}, {%8,%9}, {%0,%1,%2,%3};"
                 : "+f"(c[0]), "+f"(c[1]), "+f"(c[2]), "+f"(c[3])
                 : "r"(a[0]), "r"(a[1]), "r"(a[2]), "r"(a[3]),
                   "r"(b[0]), "r"(b[1]));
}
__device__ __forceinline__ void ldm_x4(uint32_t* r, uint32_t addr) {
    asm volatile("ldmatrix.sync.aligned.m8n8.x4.shared.b16 {%0,%1,%2,%3}, [%4];"
                 : "=r"(r[0]), "=r"(r[1]), "=r"(r[2]), "=r"(r[3]) : "r"(addr));
}

// ======== kernel prep: fused (evec | transp | vs-split), independent parts ==
#define PB_EVEC   4096    // (BB*NN) warps / 8 warps-per-block
#define PB_TRANSP 2048    // 2 matrices x 32x32 tiles of 32
#define PB_SPLIT  2048    // 2*NN*NN/4 float4 / 256
__global__ void __launch_bounds__(256) k_prep(
        const float* __restrict__ x,
        const float* __restrict__ fw1, const float* __restrict__ fw2,
        const float* __restrict__ gw1, const float* __restrict__ gw2,
        const float* __restrict__ fvs, const float* __restrict__ gvs,
        const float* __restrict__ fbs, const float* __restrict__ gbs) {
    int bid = blockIdx.x;
    int tid = threadIdx.x;
    if (bid < PB_EVEC) {
        int gwarp = bid * 8 + (tid >> 5);   // 0..BB*NN-1
        int lane  = tid & 31;
        const float* xp = x + (size_t)gwarp * DD;
        float v0 = xp[lane], v1 = xp[lane + 32];
        float s0 = v0 * fw1[lane] + v1 * fw1[lane + 32];
        float s1 = v0 * fw2[lane] + v1 * fw2[lane + 32];
        float s2 = v0 * gw1[lane] + v1 * gw1[lane + 32];
        float s3 = v0 * gw2[lane] + v1 * gw2[lane + 32];
        #pragma unroll
        for (int o = 16; o > 0; o >>= 1) {
            s0 += __shfl_xor_sync(0xffffffffu, s0, o);
            s1 += __shfl_xor_sync(0xffffffffu, s1, o);
            s2 += __shfl_xor_sync(0xffffffffu, s2, o);
            s3 += __shfl_xor_sync(0xffffffffu, s3, o);
        }
        if (lane == 0) {
            g_e1f[gwarp] = s0; g_e2f[gwarp] = s1;
            g_e1g[gwarp] = s2; g_e2g[gwarp] = s3;
        }
        return;
    }
    bid -= PB_EVEC;
    if (bid < PB_TRANSP) {
        __shared__ float t[32][33];
        int z = bid >> 10;                 // 0..1
        int rem = bid & 1023;              // 32x32 tiles
        int x0t = (rem & 31) * 32, y0t = (rem >> 5) * 32;
        const float* src = z ? gbs : fbs;
        float* dst = z ? g_bsTg : g_bsTf;
        int tx = tid & 31, ty = tid >> 5;
        #pragma unroll
        for (int r = ty; r < 32; r += 8)
            t[r][tx] = src[(size_t)(y0t + r) * NN + x0t + tx];
        __syncthreads();
        #pragma unroll
        for (int r = ty; r < 32; r += 8)
            dst[(size_t)(x0t + r) * NN + y0t + tx] = t[tx][r];
        return;
    }
    bid -= PB_TRANSP;
    {
        int t = bid * 256 + tid;           // 0..2*NN*NN/4-1
        int which = t >= (NN * NN / 4);
        int e = which ? t - NN * NN / 4 : t;
        const float4* src = (const float4*)(which ? gvs : fvs);
        float4 a = src[e];
        __nv_bfloat16 h0, l0, h1, l1, h2, l2, h3, l3;
        bf16_split(a.x, h0, l0); bf16_split(a.y, h1, l1);
        bf16_split(a.z, h2, l2); bf16_split(a.w, h3, l3);
        size_t off = (size_t)which * NN * NN + (size_t)e * 4;
        __nv_bfloat162* ph = (__nv_bfloat162*)(g_vHi + off);
        __nv_bfloat162* pl = (__nv_bfloat162*)(g_vLo + off);
        ph[0] = __nv_bfloat162{h0, h1}; ph[1] = __nv_bfloat162{h2, h3};
        pl[0] = __nv_bfloat162{l0, l1}; pl[1] = __nv_bfloat162{l2, l3};
        return;
    }
}

// -------- kernel sig: S[b,n,j] = sigmoid(e2[b,n]*e1[b,j] + bsT[n,j]), hi/lo
__global__ void k_sig(void) {
    int n = blockIdx.x, b = blockIdx.y, which = blockIdx.z;
    int j = threadIdx.x * 4;
    const float* e1 = which ? g_e1g : g_e1f;
    const float* e2 = which ? g_e2g : g_e2f;
    const float* bsT = (which ? g_bsTg : g_bsTf) + (size_t)n * NN + j;
    size_t off = (((size_t)which * BB + b) * NN + n) * NN + j;
    float  a   = e2[b * NN + n];
    float4 e1v = *(const float4*)(e1 + b * NN + j);
    float4 bv  = *(const float4*)bsT;
    float sx = sigm(a * e1v.x + bv.x);
    float sy = sigm(a * e1v.y + bv.y);
    float sz = sigm(a * e1v.z + bv.z);
    float sw = sigm(a * e1v.w + bv.w);
    __nv_bfloat16 h0, l0, h1, l1, h2, l2, h3, l3;
    bf16_split(sx, h0, l0); bf16_split(sy, h1, l1);
    bf16_split(sz, h2, l2); bf16_split(sw, h3, l3);
    __nv_bfloat162* ph = (__nv_bfloat162*)(g_sHi + off);
    __nv_bfloat162* pl = (__nv_bfloat162*)(g_sLo + off);
    ph[0] = __nv_bfloat162{h0, h1}; ph[1] = __nv_bfloat162{h2, h3};
    pl[0] = __nv_bfloat162{l0, l1}; pl[1] = __nv_bfloat162{l2, l3};
}

// ---------------- kernel: A_mix --------------------------------------------
__global__ void k_amix(const float* __restrict__ adj, const float* __restrict__ convw) {
    int t = blockIdx.x * blockDim.x + threadIdx.x;
    int base = t * 4;
    int i = base >> 10;
    int j = base & (NN - 1);
    float c0 = convw[0], c1 = convw[1];
    float dsub = c0 + c1;
    float4 a0 = *(const float4*)(adj + base);
    float4 a1 = *(const float4*)(adj + (size_t)NN * NN + base);
    float4 r;
    r.x = c0 * a0.x + c1 * a1.x - ((i == j + 0) ? dsub : 0.0f);
    r.y = c0 * a0.y + c1 * a1.y - ((i == j + 1) ? dsub : 0.0f);
    r.z = c0 * a0.z + c1 * a1.z - ((i == j + 2) ? dsub : 0.0f);
    r.w = c0 * a0.w + c1 * a1.w - ((i == j + 3) ? dsub : 0.0f);
    *(float4*)(g_Amix + base) = r;
}

// ------- kernel gemm: bf16x3 mma.sync batched GEMM (single-sync pipeline) ---
#define KT     32
#define STRB   80
#define TILE_BYTES (128*STRB)
#define STAGE_BYTES (4*TILE_BYTES)
#define GEMM_SMEM  (2*STAGE_BYTES)

__global__ void __launch_bounds__(256) k_gemm() {
    extern __shared__ char smg[];
    uint32_t smb = smem_u32(smg);
    int tid = threadIdx.x;
    int z = blockIdx.z;
    int b = z & (BB - 1);
    int which = z >> 5;
    const __nv_bfloat16* __restrict__ Ahi = g_vHi + (size_t)which * NN * NN;
    const __nv_bfloat16* __restrict__ Alo = g_vLo + (size_t)which * NN * NN;
    const __nv_bfloat16* __restrict__ Bhi = g_sHi + ((size_t)which * BB + b) * NN * NN;
    const __nv_bfloat16* __restrict__ Blo = g_sLo + ((size_t)which * BB + b) * NN * NN;
    float* __restrict__ C = (which ? g_NG : g_EF) + (size_t)b * NN * NN;
    int i0 = blockIdx.y * 128, n0 = blockIdx.x * 128;

    int wid = tid >> 5, lane = tid & 31;
    int gid = lane >> 2, tg = lane & 3;
    int wm = (wid & 1) * 64, wn = (wid >> 1) * 32;

    int lr    = lane & 7;
    int lrow8 = (lane >> 3) & 1;
    int lk8   = (lane >> 4) & 1;
    uint32_t aoff = (uint32_t)((wm + lrow8 * 8 + lr) * STRB + lk8 * 16);
    uint32_t boff = (uint32_t)((wn + lrow8 * 8 + lr) * STRB + lk8 * 16);

    int slot_tile[8], slot_row[8], slot_ch[8];
    #pragma unroll
    for (int it = 0; it < 8; it++) {
        int slot = tid + it * 256;
        slot_tile[it] = slot >> 9;
        int r2 = slot & 511;
        slot_row[it] = r2 >> 2;
        slot_ch[it]  = r2 & 3;
    }

    float acc[4][4][4];
    #pragma unroll
    for (int mf = 0; mf < 4; mf++)
        #pragma unroll
        for (int nf = 0; nf < 4; nf++)
            #pragma unroll
            for (int q = 0; q < 4; q++) acc[mf][nf][q] = 0.0f;

    #define G_ISSUE(S) do {                                                      \
        uint32_t sb_ = smb + ((S) & 1) * STAGE_BYTES;                            \
        int kc_ = (S) * KT;                                                      \
        _Pragma("unroll")                                                        \
        for (int it = 0; it < 8; it++) {                                         \
            int tile = slot_tile[it], row = slot_row[it], ch = slot_ch[it];      \
            const __nv_bfloat16* src =                                           \
                (tile == 0) ? Ahi + (size_t)(i0 + row) * NN :                    \
                (tile == 1) ? Alo + (size_t)(i0 + row) * NN :                    \
                (tile == 2) ? Bhi + (size_t)(n0 + row) * NN :                    \
                              Blo + (size_t)(n0 + row) * NN;                     \
            const char* gp = (const char*)(src + kc_) + ch * 16;                 \
            uint32_t sp = sb_ + (uint32_t)(tile * TILE_BYTES + row * STRB + ch * 16); \
            asm volatile("cp.async.ca.shared.global [%0], [%1], 16;"             \
                         :: "r"(sp), "l"(gp));                                   \
        }                                                                        \
        asm volatile("cp.async.commit_group;");                                  \
    } while (0)

    G_ISSUE(0);
    for (int s = 0; s < NN / KT; s++) {
        asm volatile("cp.async.wait_group 0;");
        __syncthreads();
        if (s < NN / KT - 1) G_ISSUE(s + 1);

        uint32_t base = smb + (s & 1) * STAGE_BYTES;
        uint32_t tAh = base, tAl = base + TILE_BYTES;
        uint32_t tBh = base + 2 * TILE_BYTES, tBl = base + 3 * TILE_BYTES;

        #pragma unroll
        for (int kh = 0; kh < 2; kh++) {
            uint32_t kb = (uint32_t)(kh * 32);
            uint32_t ah[4][4], al[4][4], bh[4][2], bl[4][2];
            #pragma unroll
            for (int mf = 0; mf < 4; mf++) {
                uint32_t ao = aoff + (uint32_t)(mf * 16 * STRB) + kb;
                ldm_x4(ah[mf], tAh + ao);
                ldm_x4(al[mf], tAl + ao);
            }
            #pragma unroll
            for (int p = 0; p < 2; p++) {
                uint32_t bo = boff + (uint32_t)(p * 16 * STRB) + kb;
                uint32_t th[4], tl[4];
                ldm_x4(th, tBh + bo);
                ldm_x4(tl, tBl + bo);
                bh[2*p][0]   = th[0]; bh[2*p][1]   = th[2];
                bh[2*p+1][0] = th[1]; bh[2*p+1][1] = th[3];
                bl[2*p][0]   = tl[0]; bl[2*p][1]   = tl[2];
                bl[2*p+1][0] = tl[1]; bl[2*p+1][1] = tl[3];
            }
            #pragma unroll
            for (int mf = 0; mf < 4; mf++)
                #pragma unroll
                for (int nf = 0; nf < 4; nf++)
                    mma16(acc[mf][nf], ah[mf], bh[nf]);
            #pragma unroll
            for (int mf = 0; mf < 4; mf++)
                #pragma unroll
                for (int nf = 0; nf < 4; nf++)
                    mma16(acc[mf][nf], ah[mf], bl[nf]);
            #pragma unroll
            for (int mf = 0; mf < 4; mf++)
                #pragma unroll
                for (int nf = 0; nf < 4; nf++)
                    mma16(acc[mf][nf], al[mf], bh[nf]);
        }
    }

    #pragma unroll
    for (int mf = 0; mf < 4; mf++) {
        #pragma unroll
        for (int nf = 0; nf < 4; nf++) {
            int row = i0 + wm + mf * 16 + gid;
            int col = n0 + wn + nf * 8 + tg * 2;
            float2 v0 = make_float2(acc[mf][nf][0], acc[mf][nf][1]);
            float2 v1 = make_float2(acc[mf][nf][2], acc[mf][nf][3]);
            *(float2*)(C + (size_t)row * NN + col)       = v0;
            *(float2*)(C + (size_t)(row + 8) * NN + col) = v1;
        }
    }
}

// ---------------- kernel: W_hat --------------------------------------------
__global__ void k_what(const float* __restrict__ w, const float* __restrict__ d) {
    int t = blockIdx.x * blockDim.x + threadIdx.x;
    int i = t >> 6, j = t & 63;
    float s = 0.0f;
    #pragma unroll 8
    for (int k = 0; k < DD; k++) {
        float dc = fminf(fmaxf(d[k], 0.0f), 1.0f);
        s += w[i * DD + k] * dc * w[j * DD + k];
    }
    g_What[t] = s - ((i == j) ? 1.0f : 0.0f);
}

// ---------------- kernel: sigmoid(alpha) -----------------------------------
__global__ void k_salpha(const float* __restrict__ alpha) {
    int t = blockIdx.x * blockDim.x + threadIdx.x;
    if (t < NN) g_salpha[t] = sigm(alpha[t]);
}

// ---------------- kernel soft: row softmax; fuse N_hat + Emod (fp32) -------
__global__ void k_soft() {
    int i = blockIdx.x, b = blockIdx.y;
    size_t ro = ((size_t)b * NN + i) * NN;
    int c = threadIdx.x * 4;
    int wid = threadIdx.x >> 5, lane = threadIdx.x & 31;
    __shared__ float sE[8], sN[8];

    float4 ev = *(float4*)(g_EF + ro + c);
    float4 nv = *(float4*)(g_NG + ro + c);

    float mE = fmaxf(fmaxf(ev.x, ev.y), fmaxf(ev.z, ev.w));
    float mN = fmaxf(fmaxf(nv.x, nv.y), fmaxf(nv.z, nv.w));
    #pragma unroll
    for (int o = 16; o > 0; o >>= 1) {
        mE = fmaxf(mE, __shfl_xor_sync(0xffffffffu, mE, o));
        mN = fmaxf(mN, __shfl_xor_sync(0xffffffffu, mN, o));
    }
    if (lane == 0) { sE[wid] = mE; sN[wid] = mN; }
    __syncthreads();
    mE = sE[0]; mN = sN[0];
    #pragma unroll
    for (int wv = 1; wv < 8; wv++) { mE = fmaxf(mE, sE[wv]); mN = fmaxf(mN, sN[wv]); }
    __syncthreads();

    float4 eE, eN;
    eE.x = __expf(ev.x - mE); eE.y = __expf(ev.y - mE);
    eE.z = __expf(ev.z - mE); eE.w = __expf(ev.w - mE);
    eN.x = __expf(nv.x - mN); eN.y = __expf(nv.y - mN);
    eN.z = __expf(nv.z - mN); eN.w = __expf(nv.w - mN);
    float sumE = eE.x + eE.y + eE.z + eE.w;
    float sumN = eN.x + eN.y + eN.z + eN.w;
    #pragma unroll
    for (int o = 16; o > 0; o >>= 1) {
        sumE += __shfl_xor_sync(0xffffffffu, sumE, o);
        sumN += __shfl_xor_sync(0xffffffffu, sumN, o);
    }
    if (lane == 0) { sE[wid] = sumE; sN[wid] = sumN; }
    __syncthreads();
    sumE = 0.0f; sumN = 0.0f;
    #pragma unroll
    for (int wv = 0; wv < 8; wv++) { sumE += sE[wv]; sumN += sN[wv]; }

    float invE = __fdividef(1.0f, sumE);
    float invN = __fdividef(1.0f, sumN);

    float4 se;
    se.x = eE.x * invE; se.y = eE.y * invE; se.z = eE.z * invE; se.w = eE.w * invE;
    float4 nh;
    nh.x = __fdividef(eN.x * invN, se.x + 1e-5f);
    nh.y = __fdividef(eN.y * invN, se.y + 1e-5f);
    nh.z = __fdividef(eN.z * invN, se.z + 1e-5f);
    nh.w = __fdividef(eN.w * invN, se.w + 1e-5f);

    float4 am = *(float4*)(g_Amix + (size_t)i * NN + c);
    float4 em;
    em.x = se.x + am.x - ((c + 0 == i) ? 1.0f : 0.0f);
    em.y = se.y + am.y - ((c + 1 == i) ? 1.0f : 0.0f);
    em.z = se.z + am.z - ((c + 2 == i) ? 1.0f : 0.0f);
    em.w = se.w + am.w - ((c + 3 == i) ? 1.0f : 0.0f);

    *(float4*)(g_EF + ro + c) = em;
    *(float4*)(g_NG + ro + c) = nh;
}

// -------- kernel final: SIMT 64x64 fused (R6 version, fastest measured) ----
#define K5_SMEM_FLOATS (64*65 + 64*65 + 64*64)
__global__ void __launch_bounds__(256) k_final(const float* __restrict__ x,
                                               const float* __restrict__ x0,
                                               const float* __restrict__ convb,
                                               float* __restrict__ out) {
    extern __shared__ float smf[];
    float* Es = smf;
    float* Ns = smf + 64 * 65;
    float* xs = smf + 2 * 64 * 65;

    int b = blockIdx.y, i0 = blockIdx.x * 64;
    int tid = threadIdx.x;
    int il = tid >> 2, cg = tid & 3, c0 = cg * 16;
    const float* xr = x    + (size_t)b * NN * DD;
    const float* Em = g_EF + (size_t)b * NN * NN;
    const float* Nh = g_NG + (size_t)b * NN * NN;

    float af[16], ag[16];
    #pragma unroll
    for (int q = 0; q < 16; q++) { af[q] = 0.0f; ag[q] = 0.0f; }

    for (int jc = 0; jc < 16; jc++) {
        #pragma unroll
        for (int q = 0; q < 4; q++) {
            int lin = tid + q * 256;
            int row = lin >> 4, cc = (lin & 15) * 4;
            float4 ev = *(const float4*)(Em + (size_t)(i0 + row) * NN + jc * 64 + cc);
            Es[row * 65 + cc + 0] = ev.x; Es[row * 65 + cc + 1] = ev.y;
            Es[row * 65 + cc + 2] = ev.z; Es[row * 65 + cc + 3] = ev.w;
            float4 nv = *(const float4*)(Nh + (size_t)(i0 + row) * NN + jc * 64 + cc);
            Ns[row * 65 + cc + 0] = nv.x; Ns[row * 65 + cc + 1] = nv.y;
            Ns[row * 65 + cc + 2] = nv.z; Ns[row * 65 + cc + 3] = nv.w;
            *(float4*)&xs[row * 64 + cc] =
                *(const float4*)(xr + (size_t)(jc * 64 + row) * DD + cc);
        }
        __syncthreads();
        #pragma unroll 8
        for (int j = 0; j < 64; j++) {
            float cf  = Es[il * 65 + j];
            float cgv = Ns[il * 65 + j];
            #pragma unroll
            for (int q = 0; q < 4; q++) {
                float4 xv = *(float4*)&xs[j * 64 + c0 + q * 4];
                af[q * 4 + 0] += cf * xv.x;  af[q * 4 + 1] += cf * xv.y;
                af[q * 4 + 2] += cf * xv.z;  af[q * 4 + 3] += cf * xv.w;
                ag[q * 4 + 0] += cgv * xv.x; ag[q * 4 + 1] += cgv * xv.y;
                ag[q * 4 + 2] += cgv * xv.z; ag[q * 4 + 3] += cgv * xv.w;
            }
        }
        __syncthreads();
    }

    #pragma unroll
    for (int q = 0; q < 4; q++) {
        int lin = tid + q * 256;
        int row = lin >> 4, cc = (lin & 15) * 4;
        *(float4*)&xs[row * 64 + cc] = *(const float4*)(g_What + row * DD + cc);
        float4 xiv = *(const float4*)(xr + (size_t)(i0 + row) * DD + cc);
        Es[row * 65 + cc + 0] = xiv.x; Es[row * 65 + cc + 1] = xiv.y;
        Es[row * 65 + cc + 2] = xiv.z; Es[row * 65 + cc + 3] = xiv.w;
    }
    __syncthreads();
    #pragma unroll 8
    for (int k = 0; k < DD; k++) {
        float xik = Es[il * 65 + k];
        #pragma unroll
        for (int q = 0; q < 4; q++) {
            float4 wv = *(float4*)&xs[k * 64 + c0 + q * 4];
            af[q * 4 + 0] += xik * wv.x; af[q * 4 + 1] += xik * wv.y;
            af[q * 4 + 2] += xik * wv.z; af[q * 4 + 3] += xik * wv.w;
        }
    }

    float cb = convb[0];
    float sa = g_salpha[i0 + il];
    size_t obase = ((size_t)b * NN + i0 + il) * DD + c0;
    #pragma unroll
    for (int q = 0; q < 4; q++) {
        float4 x0v = *(const float4*)(x0 + obase + q * 4);
        float4 fo, go;
        fo.x = tanhf(af[q * 4 + 0] + cb + x0v.x * sa);
        fo.y = tanhf(af[q * 4 + 1] + cb + x0v.y * sa);
        fo.z = tanhf(af[q * 4 + 2] + cb + x0v.z * sa);
        fo.w = tanhf(af[q * 4 + 3] + cb + x0v.w * sa);
        go.x = tanhf(ag[q * 4 + 0]);
        go.y = tanhf(ag[q * 4 + 1]);
        go.z = tanhf(ag[q * 4 + 2]);
        go.w = tanhf(ag[q * 4 + 3]);
        *(float4*)(out + obase + q * 4)        = fo;
        *(float4*)(out + HALF + obase + q * 4) = go;
    }
}

// ---------------- launch ----------------------------------------------------
extern "C" void kernel_launch(void* const* d_in, const int* in_sizes, int n_in,
                              void* d_out, int out_size) {
    const float* x     = (const float*)d_in[0];
    const float* x0    = (const float*)d_in[1];
    const float* w     = (const float*)d_in[2];
    const float* d     = (const float*)d_in[3];
    const float* alpha = (const float*)d_in[4];
    const float* fw1   = (const float*)d_in[5];
    const float* fw2   = (const float*)d_in[6];
    const float* fvs   = (const float*)d_in[7];
    const float* fbs   = (const float*)d_in[8];
    const float* gw1   = (const float*)d_in[9];
    const float* gw2   = (const float*)d_in[10];
    const float* gvs   = (const float*)d_in[11];
    const float* gbs   = (const float*)d_in[12];
    const float* convw = (const float*)d_in[13];
    const float* convb = (const float*)d_in[14];
    const float* adj   = (const float*)d_in[15];
    float* out = (float*)d_out;

    cudaFuncSetAttribute(k_gemm, cudaFuncAttributeMaxDynamicSharedMemorySize, GEMM_SMEM);
    cudaFuncSetAttribute(k_final, cudaFuncAttributeMaxDynamicSharedMemorySize,
                         K5_SMEM_FLOATS * (int)sizeof(float));

    // order puts k_gemm at launch index 3 for ncu's fixed-index capture
    k_prep  <<<PB_EVEC + PB_TRANSP + PB_SPLIT, 256>>>(
                x, fw1, fw2, gw1, gw2, fvs, gvs, fbs, gbs);
    k_sig   <<<dim3(NN, BB, 2), 256>>>();
    k_amix  <<<(NN * NN / 4) / 256, 256>>>(adj, convw);
    k_gemm  <<<dim3(8, 8, 2 * BB), 256, GEMM_SMEM>>>();
    k_what  <<<(DD * DD) / 256, 256>>>(w, d);
    k_salpha<<<NN / 256, 256>>>(alpha);
    k_soft  <<<dim3(NN, BB), 256>>>();
    k_final <<<dim3(NN / 64, BB), 256, K5_SMEM_FLOATS * (int)sizeof(float)>>>(x, x0, convb, out);
}

// round 17
// speedup vs baseline: 1.1154x; 1.0239x over previous
#include <cuda_runtime.h>
#include <cuda_bf16.h>
#include <math.h>
#include <stdint.h>

#define BB 32
#define NN 1024
#define DD 64
#define HALF (BB*NN*DD)
#define SZB ((size_t)BB*NN*NN)

// ---------------- scratch (device globals; no allocation allowed) ----------
static __device__ __nv_bfloat16 g_sHi[2*SZB];  // sigmoid hi [which][b][n][j]
static __device__ __nv_bfloat16 g_sLo[2*SZB];  // sigmoid lo
static __device__ __nv_bfloat16 g_vHi[(size_t)2*NN*NN];
static __device__ __nv_bfloat16 g_vLo[(size_t)2*NN*NN];
static __device__ float g_EF  [SZB];   // E_pre (raw GEMM output, read-only after)
static __device__ float g_NG  [SZB];   // N_pre
static __device__ float g_bsTf[(size_t)NN*NN];
static __device__ float g_bsTg[(size_t)NN*NN];
static __device__ float g_e1f[BB*NN], g_e2f[BB*NN], g_e1g[BB*NN], g_e2g[BB*NN];
static __device__ float g_Amix[NN*NN];
static __device__ float g_What[DD*DD];
static __device__ float g_salpha[NN];

__device__ __forceinline__ float sigm(float v) {
    return __fdividef(1.0f, 1.0f + __expf(-v));
}
__device__ __forceinline__ uint32_t smem_u32(const void* p) {
    uint32_t a;
    asm("{ .reg .u64 t; cvta.to.shared.u64 t, %1; cvt.u32.u64 %0, t; }" : "=r"(a) : "l"(p));
    return a;
}
__device__ __forceinline__ void bf16_split(float x, __nv_bfloat16& hi, __nv_bfloat16& lo) {
    hi = __float2bfloat16(x);
    lo = __float2bfloat16(x - __bfloat162float(hi));
}
__device__ __forceinline__ void mma16(float* c, const uint32_t* a, const uint32_t* b) {
    asm volatile("mma.sync.aligned.m16n8k16.row.col.f32.bf16.bf16.f32 "
                 "{%0,%1,%2,%3}, {%4,%5,%6,%7}, {%8,%9}, {%0,%1,%2,%3};"
                 : "+f"(c[0]), "+f"(c[1]), "+f"(c[2]), "+f"(c[3])
                 : "r"(a[0]), "r"(a[1]), "r"(a[2]), "r"(a[3]),
                   "r"(b[0]), "r"(b[1]));
}
__device__ __forceinline__ void ldm_x4(uint32_t* r, uint32_t addr) {
    asm volatile("ldmatrix.sync.aligned.m8n8.x4.shared.b16 {%0,%1,%2,%3}, [%4];"
                 : "=r"(r[0]), "=r"(r[1]), "=r"(r[2]), "=r"(r[3]) : "r"(addr));
}

// ===== kernel prep: fused (evec | transp | vs-split | amix | what | salpha) =
#define PB_EVEC   4096
#define PB_TRANSP 2048
#define PB_SPLIT  2048
#define PB_AMIX   1024
#define PB_WHAT   16
#define PB_SALPHA 4
#define PB_TOTAL  (PB_EVEC + PB_TRANSP + PB_SPLIT + PB_AMIX + PB_WHAT + PB_SALPHA)
__global__ void __launch_bounds__(256) k_prep(
        const float* __restrict__ x,
        const float* __restrict__ fw1, const float* __restrict__ fw2,
        const float* __restrict__ gw1, const float* __restrict__ gw2,
        const float* __restrict__ fvs, const float* __restrict__ gvs,
        const float* __restrict__ fbs, const float* __restrict__ gbs,
        const float* __restrict__ adj, const float* __restrict__ convw,
        const float* __restrict__ w, const float* __restrict__ d,
        const float* __restrict__ alpha) {
    int bid = blockIdx.x;
    int tid = threadIdx.x;
    if (bid < PB_EVEC) {
        int gwarp = bid * 8 + (tid >> 5);
        int lane  = tid & 31;
        const float* xp = x + (size_t)gwarp * DD;
        float v0 = xp[lane], v1 = xp[lane + 32];
        float s0 = v0 * fw1[lane] + v1 * fw1[lane + 32];
        float s1 = v0 * fw2[lane] + v1 * fw2[lane + 32];
        float s2 = v0 * gw1[lane] + v1 * gw1[lane + 32];
        float s3 = v0 * gw2[lane] + v1 * gw2[lane + 32];
        #pragma unroll
        for (int o = 16; o > 0; o >>= 1) {
            s0 += __shfl_xor_sync(0xffffffffu, s0, o);
            s1 += __shfl_xor_sync(0xffffffffu, s1, o);
            s2 += __shfl_xor_sync(0xffffffffu, s2, o);
            s3 += __shfl_xor_sync(0xffffffffu, s3, o);
        }
        if (lane == 0) {
            g_e1f[gwarp] = s0; g_e2f[gwarp] = s1;
            g_e1g[gwarp] = s2; g_e2g[gwarp] = s3;
        }
        return;
    }
    bid -= PB_EVEC;
    if (bid < PB_TRANSP) {
        __shared__ float t[32][33];
        int z = bid >> 10;
        int rem = bid & 1023;
        int x0t = (rem & 31) * 32, y0t = (rem >> 5) * 32;
        const float* src = z ? gbs : fbs;
        float* dst = z ? g_bsTg : g_bsTf;
        int tx = tid & 31, ty = tid >> 5;
        #pragma unroll
        for (int r = ty; r < 32; r += 8)
            t[r][tx] = src[(size_t)(y0t + r) * NN + x0t + tx];
        __syncthreads();
        #pragma unroll
        for (int r = ty; r < 32; r += 8)
            dst[(size_t)(x0t + r) * NN + y0t + tx] = t[tx][r];
        return;
    }
    bid -= PB_TRANSP;
    if (bid < PB_SPLIT) {
        int t = bid * 256 + tid;
        int which = t >= (NN * NN / 4);
        int e = which ? t - NN * NN / 4 : t;
        const float4* src = (const float4*)(which ? gvs : fvs);
        float4 a = src[e];
        __nv_bfloat16 h0, l0, h1, l1, h2, l2, h3, l3;
        bf16_split(a.x, h0, l0); bf16_split(a.y, h1, l1);
        bf16_split(a.z, h2, l2); bf16_split(a.w, h3, l3);
        size_t off = (size_t)which * NN * NN + (size_t)e * 4;
        __nv_bfloat162* ph = (__nv_bfloat162*)(g_vHi + off);
        __nv_bfloat162* pl = (__nv_bfloat162*)(g_vLo + off);
        ph[0] = __nv_bfloat162{h0, h1}; ph[1] = __nv_bfloat162{h2, h3};
        pl[0] = __nv_bfloat162{l0, l1}; pl[1] = __nv_bfloat162{l2, l3};
        return;
    }
    bid -= PB_SPLIT;
    if (bid < PB_AMIX) {
        int t = bid * 256 + tid;
        int base = t * 4;
        int i = base >> 10;
        int j = base & (NN - 1);
        float c0 = convw[0], c1 = convw[1];
        float dsub = c0 + c1;
        float4 a0 = *(const float4*)(adj + base);
        float4 a1 = *(const float4*)(adj + (size_t)NN * NN + base);
        float4 r;
        r.x = c0 * a0.x + c1 * a1.x - ((i == j + 0) ? dsub : 0.0f);
        r.y = c0 * a0.y + c1 * a1.y - ((i == j + 1) ? dsub : 0.0f);
        r.z = c0 * a0.z + c1 * a1.z - ((i == j + 2) ? dsub : 0.0f);
        r.w = c0 * a0.w + c1 * a1.w - ((i == j + 3) ? dsub : 0.0f);
        *(float4*)(g_Amix + base) = r;
        return;
    }
    bid -= PB_AMIX;
    if (bid < PB_WHAT) {
        int t = bid * 256 + tid;
        int i = t >> 6, j = t & 63;
        float s = 0.0f;
        #pragma unroll 8
        for (int k = 0; k < DD; k++) {
            float dc = fminf(fmaxf(d[k], 0.0f), 1.0f);
            s += w[i * DD + k] * dc * w[j * DD + k];
        }
        g_What[t] = s - ((i == j) ? 1.0f : 0.0f);
        return;
    }
    bid -= PB_WHAT;
    {
        int t = bid * 256 + tid;
        if (t < NN) g_salpha[t] = sigm(alpha[t]);
        return;
    }
}

// -------- kernel sig: S[b,n,j] = sigmoid(e2[b,n]*e1[b,j] + bsT[n,j]), hi/lo
__global__ void k_sig(void) {
    int n = blockIdx.x, b = blockIdx.y, which = blockIdx.z;
    int j = threadIdx.x * 4;
    const float* e1 = which ? g_e1g : g_e1f;
    const float* e2 = which ? g_e2g : g_e2f;
    const float* bsT = (which ? g_bsTg : g_bsTf) + (size_t)n * NN + j;
    size_t off = (((size_t)which * BB + b) * NN + n) * NN + j;
    float  a   = e2[b * NN + n];
    float4 e1v = *(const float4*)(e1 + b * NN + j);
    float4 bv  = *(const float4*)bsT;
    float sx = sigm(a * e1v.x + bv.x);
    float sy = sigm(a * e1v.y + bv.y);
    float sz = sigm(a * e1v.z + bv.z);
    float sw = sigm(a * e1v.w + bv.w);
    __nv_bfloat16 h0, l0, h1, l1, h2, l2, h3, l3;
    bf16_split(sx, h0, l0); bf16_split(sy, h1, l1);
    bf16_split(sz, h2, l2); bf16_split(sw, h3, l3);
    __nv_bfloat162* ph = (__nv_bfloat162*)(g_sHi + off);
    __nv_bfloat162* pl = (__nv_bfloat162*)(g_sLo + off);
    ph[0] = __nv_bfloat162{h0, h1}; ph[1] = __nv_bfloat162{h2, h3};
    pl[0] = __nv_bfloat162{l0, l1}; pl[1] = __nv_bfloat162{l2, l3};
}

// ------- kernel gemm: bf16x3 mma.sync batched GEMM (R14, at HW floor) ------
#define KT     32
#define STRB   80
#define TILE_BYTES (128*STRB)
#define STAGE_BYTES (4*TILE_BYTES)
#define GEMM_SMEM  (2*STAGE_BYTES)

__global__ void __launch_bounds__(256) k_gemm() {
    extern __shared__ char smg[];
    uint32_t smb = smem_u32(smg);
    int tid = threadIdx.x;
    int z = blockIdx.z;
    int b = z & (BB - 1);
    int which = z >> 5;
    const __nv_bfloat16* __restrict__ Ahi = g_vHi + (size_t)which * NN * NN;
    const __nv_bfloat16* __restrict__ Alo = g_vLo + (size_t)which * NN * NN;
    const __nv_bfloat16* __restrict__ Bhi = g_sHi + ((size_t)which * BB + b) * NN * NN;
    const __nv_bfloat16* __restrict__ Blo = g_sLo + ((size_t)which * BB + b) * NN * NN;
    float* __restrict__ C = (which ? g_NG : g_EF) + (size_t)b * NN * NN;
    int i0 = blockIdx.y * 128, n0 = blockIdx.x * 128;

    int wid = tid >> 5, lane = tid & 31;
    int gid = lane >> 2, tg = lane & 3;
    int wm = (wid & 1) * 64, wn = (wid >> 1) * 32;

    int lr    = lane & 7;
    int lrow8 = (lane >> 3) & 1;
    int lk8   = (lane >> 4) & 1;
    uint32_t aoff = (uint32_t)((wm + lrow8 * 8 + lr) * STRB + lk8 * 16);
    uint32_t boff = (uint32_t)((wn + lrow8 * 8 + lr) * STRB + lk8 * 16);

    int slot_tile[8], slot_row[8], slot_ch[8];
    #pragma unroll
    for (int it = 0; it < 8; it++) {
        int slot = tid + it * 256;
        slot_tile[it] = slot >> 9;
        int r2 = slot & 511;
        slot_row[it] = r2 >> 2;
        slot_ch[it]  = r2 & 3;
    }

    float acc[4][4][4];
    #pragma unroll
    for (int mf = 0; mf < 4; mf++)
        #pragma unroll
        for (int nf = 0; nf < 4; nf++)
            #pragma unroll
            for (int q = 0; q < 4; q++) acc[mf][nf][q] = 0.0f;

    #define G_ISSUE(S) do {                                                      \
        uint32_t sb_ = smb + ((S) & 1) * STAGE_BYTES;                            \
        int kc_ = (S) * KT;                                                      \
        _Pragma("unroll")                                                        \
        for (int it = 0; it < 8; it++) {                                         \
            int tile = slot_tile[it], row = slot_row[it], ch = slot_ch[it];      \
            const __nv_bfloat16* src =                                           \
                (tile == 0) ? Ahi + (size_t)(i0 + row) * NN :                    \
                (tile == 1) ? Alo + (size_t)(i0 + row) * NN :                    \
                (tile == 2) ? Bhi + (size_t)(n0 + row) * NN :                    \
                              Blo + (size_t)(n0 + row) * NN;                     \
            const char* gp = (const char*)(src + kc_) + ch * 16;                 \
            uint32_t sp = sb_ + (uint32_t)(tile * TILE_BYTES + row * STRB + ch * 16); \
            asm volatile("cp.async.ca.shared.global [%0], [%1], 16;"             \
                         :: "r"(sp), "l"(gp));                                   \
        }                                                                        \
        asm volatile("cp.async.commit_group;");                                  \
    } while (0)

    G_ISSUE(0);
    for (int s = 0; s < NN / KT; s++) {
        asm volatile("cp.async.wait_group 0;");
        __syncthreads();
        if (s < NN / KT - 1) G_ISSUE(s + 1);

        uint32_t base = smb + (s & 1) * STAGE_BYTES;
        uint32_t tAh = base, tAl = base + TILE_BYTES;
        uint32_t tBh = base + 2 * TILE_BYTES, tBl = base + 3 * TILE_BYTES;

        #pragma unroll
        for (int kh = 0; kh < 2; kh++) {
            uint32_t kb = (uint32_t)(kh * 32);
            uint32_t ah[4][4], al[4][4], bh[4][2], bl[4][2];
            #pragma unroll
            for (int mf = 0; mf < 4; mf++) {
                uint32_t ao = aoff + (uint32_t)(mf * 16 * STRB) + kb;
                ldm_x4(ah[mf], tAh + ao);
                ldm_x4(al[mf], tAl + ao);
            }
            #pragma unroll
            for (int p = 0; p < 2; p++) {
                uint32_t bo = boff + (uint32_t)(p * 16 * STRB) + kb;
                uint32_t th[4], tl[4];
                ldm_x4(th, tBh + bo);
                ldm_x4(tl, tBl + bo);
                bh[2*p][0]   = th[0]; bh[2*p][1]   = th[2];
                bh[2*p+1][0] = th[1]; bh[2*p+1][1] = th[3];
                bl[2*p][0]   = tl[0]; bl[2*p][1]   = tl[2];
                bl[2*p+1][0] = tl[1]; bl[2*p+1][1] = tl[3];
            }
            #pragma unroll
            for (int mf = 0; mf < 4; mf++)
                #pragma unroll
                for (int nf = 0; nf < 4; nf++)
                    mma16(acc[mf][nf], ah[mf], bh[nf]);
            #pragma unroll
            for (int mf = 0; mf < 4; mf++)
                #pragma unroll
                for (int nf = 0; nf < 4; nf++)
                    mma16(acc[mf][nf], ah[mf], bl[nf]);
            #pragma unroll
            for (int mf = 0; mf < 4; mf++)
                #pragma unroll
                for (int nf = 0; nf < 4; nf++)
                    mma16(acc[mf][nf], al[mf], bh[nf]);
        }
    }

    #pragma unroll
    for (int mf = 0; mf < 4; mf++) {
        #pragma unroll
        for (int nf = 0; nf < 4; nf++) {
            int row = i0 + wm + mf * 16 + gid;
            int col = n0 + wn + nf * 8 + tg * 2;
            float2 v0 = make_float2(acc[mf][nf][0], acc[mf][nf][1]);
            float2 v1 = make_float2(acc[mf][nf][2], acc[mf][nf][3]);
            *(float2*)(C + (size_t)row * NN + col)       = v0;
            *(float2*)(C + (size_t)(row + 8) * NN + col) = v1;
        }
    }
}

// -------- kernel final: fused softmax + SIMT 64x64 matmuls + epilogue -------
// Phase 1: row max/sum of E_pre/N_pre (64 rows per block).
// Phase 2: tile loader applies softmax/N_hat/Em transform inline, then matmul.
#define K5_SMEM_FLOATS (64*65 + 64*65 + 64*64)
__global__ void __launch_bounds__(256) k_final(const float* __restrict__ x,
                                               const float* __restrict__ x0,
                                               const float* __restrict__ convb,
                                               float* __restrict__ out) {
    extern __shared__ float smf[];
    float* Es = smf;
    float* Ns = smf + 64 * 65;
    float* xs = smf + 2 * 64 * 65;
    __shared__ float sMe[64], sIe[64], sMn[64], sIn[64];

    int b = blockIdx.y, i0 = blockIdx.x * 64;
    int tid = threadIdx.x;
    int wid = tid >> 5, lane = tid & 31;
    const float* xr = x    + (size_t)b * NN * DD;
    const float* Ep = g_EF + (size_t)b * NN * NN;
    const float* Np = g_NG + (size_t)b * NN * NN;

    // ---- phase 1: per-row max & sum(exp) for E and N ----
    #pragma unroll 1
    for (int r8 = 0; r8 < 8; r8++) {
        int row = wid * 8 + r8;
        const float* rpE = Ep + (size_t)(i0 + row) * NN + lane * 4;
        const float* rpN = Np + (size_t)(i0 + row) * NN + lane * 4;
        float4 v[8];
        #pragma unroll
        for (int k = 0; k < 8; k++) v[k] = *(const float4*)(rpE + k * 128);
        float m = -3.4e38f;
        #pragma unroll
        for (int k = 0; k < 8; k++)
            m = fmaxf(m, fmaxf(fmaxf(v[k].x, v[k].y), fmaxf(v[k].z, v[k].w)));
        #pragma unroll
        for (int o = 16; o > 0; o >>= 1) m = fmaxf(m, __shfl_xor_sync(0xffffffffu, m, o));
        float s = 0.0f;
        #pragma unroll
        for (int k = 0; k < 8; k++)
            s += __expf(v[k].x - m) + __expf(v[k].y - m)
               + __expf(v[k].z - m) + __expf(v[k].w - m);
        #pragma unroll
        for (int o = 16; o > 0; o >>= 1) s += __shfl_xor_sync(0xffffffffu, s, o);
        if (lane == 0) { sMe[row] = m; sIe[row] = __fdividef(1.0f, s); }

        #pragma unroll
        for (int k = 0; k < 8; k++) v[k] = *(const float4*)(rpN + k * 128);
        m = -3.4e38f;
        #pragma unroll
        for (int k = 0; k < 8; k++)
            m = fmaxf(m, fmaxf(fmaxf(v[k].x, v[k].y), fmaxf(v[k].z, v[k].w)));
        #pragma unroll
        for (int o = 16; o > 0; o >>= 1) m = fmaxf(m, __shfl_xor_sync(0xffffffffu, m, o));
        s = 0.0f;
        #pragma unroll
        for (int k = 0; k < 8; k++)
            s += __expf(v[k].x - m) + __expf(v[k].y - m)
               + __expf(v[k].z - m) + __expf(v[k].w - m);
        #pragma unroll
        for (int o = 16; o > 0; o >>= 1) s += __shfl_xor_sync(0xffffffffu, s, o);
        if (lane == 0) { sMn[row] = m; sIn[row] = __fdividef(1.0f, s); }
    }
    __syncthreads();

    // ---- phase 2: tiled matmuls with inline transform ----
    int il = tid >> 2, cg = tid & 3, c0 = cg * 16;
    float af[16], ag[16];
    #pragma unroll
    for (int q = 0; q < 16; q++) { af[q] = 0.0f; ag[q] = 0.0f; }

    for (int jc = 0; jc < 16; jc++) {
        #pragma unroll
        for (int q = 0; q < 4; q++) {
            int lin = tid + q * 256;
            int row = lin >> 4, cc = (lin & 15) * 4;
            int gr = i0 + row;
            int gc = jc * 64 + cc;
            float me = sMe[row], ie = sIe[row];
            float mn = sMn[row], in_ = sIn[row];
            float4 ev = *(const float4*)(Ep + (size_t)gr * NN + gc);
            float4 nv = *(const float4*)(Np + (size_t)gr * NN + gc);
            float4 av = *(const float4*)(g_Amix + (size_t)gr * NN + gc);
            float4 se;
            se.x = __expf(ev.x - me) * ie; se.y = __expf(ev.y - me) * ie;
            se.z = __expf(ev.z - me) * ie; se.w = __expf(ev.w - me) * ie;
            float4 nh;
            nh.x = __fdividef(__expf(nv.x - mn) * in_, se.x + 1e-5f);
            nh.y = __fdividef(__expf(nv.y - mn) * in_, se.y + 1e-5f);
            nh.z = __fdividef(__expf(nv.z - mn) * in_, se.z + 1e-5f);
            nh.w = __fdividef(__expf(nv.w - mn) * in_, se.w + 1e-5f);
            Es[row * 65 + cc + 0] = se.x + av.x - ((gc + 0 == gr) ? 1.0f : 0.0f);
            Es[row * 65 + cc + 1] = se.y + av.y - ((gc + 1 == gr) ? 1.0f : 0.0f);
            Es[row * 65 + cc + 2] = se.z + av.z - ((gc + 2 == gr) ? 1.0f : 0.0f);
            Es[row * 65 + cc + 3] = se.w + av.w - ((gc + 3 == gr) ? 1.0f : 0.0f);
            Ns[row * 65 + cc + 0] = nh.x; Ns[row * 65 + cc + 1] = nh.y;
            Ns[row * 65 + cc + 2] = nh.z; Ns[row * 65 + cc + 3] = nh.w;
            *(float4*)&xs[row * 64 + cc] =
                *(const float4*)(xr + (size_t)(jc * 64 + row) * DD + cc);
        }
        __syncthreads();
        #pragma unroll 8
        for (int j = 0; j < 64; j++) {
            float cf  = Es[il * 65 + j];
            float cgv = Ns[il * 65 + j];
            #pragma unroll
            for (int q = 0; q < 4; q++) {
                float4 xv = *(float4*)&xs[j * 64 + c0 + q * 4];
                af[q * 4 + 0] += cf * xv.x;  af[q * 4 + 1] += cf * xv.y;
                af[q * 4 + 2] += cf * xv.z;  af[q * 4 + 3] += cf * xv.w;
                ag[q * 4 + 0] += cgv * xv.x; ag[q * 4 + 1] += cgv * xv.y;
                ag[q * 4 + 2] += cgv * xv.z; ag[q * 4 + 3] += cgv * xv.w;
            }
        }
        __syncthreads();
    }

    // epilogue: xw = xr_i @ W_hat
    #pragma unroll
    for (int q = 0; q < 4; q++) {
        int lin = tid + q * 256;
        int row = lin >> 4, cc = (lin & 15) * 4;
        *(float4*)&xs[row * 64 + cc] = *(const float4*)(g_What + row * DD + cc);
        float4 xiv = *(const float4*)(xr + (size_t)(i0 + row) * DD + cc);
        Es[row * 65 + cc + 0] = xiv.x; Es[row * 65 + cc + 1] = xiv.y;
        Es[row * 65 + cc + 2] = xiv.z; Es[row * 65 + cc + 3] = xiv.w;
    }
    __syncthreads();
    #pragma unroll 8
    for (int k = 0; k < DD; k++) {
        float xik = Es[il * 65 + k];
        #pragma unroll
        for (int q = 0; q < 4; q++) {
            float4 wv = *(float4*)&xs[k * 64 + c0 + q * 4];
            af[q * 4 + 0] += xik * wv.x; af[q * 4 + 1] += xik * wv.y;
            af[q * 4 + 2] += xik * wv.z; af[q * 4 + 3] += xik * wv.w;
        }
    }

    float cb = convb[0];
    float sa = g_salpha[i0 + il];
    size_t obase = ((size_t)b * NN + i0 + il) * DD + c0;
    #pragma unroll
    for (int q = 0; q < 4; q++) {
        float4 x0v = *(const float4*)(x0 + obase + q * 4);
        float4 fo, go;
        fo.x = tanhf(af[q * 4 + 0] + cb + x0v.x * sa);
        fo.y = tanhf(af[q * 4 + 1] + cb + x0v.y * sa);
        fo.z = tanhf(af[q * 4 + 2] + cb + x0v.z * sa);
        fo.w = tanhf(af[q * 4 + 3] + cb + x0v.w * sa);
        go.x = tanhf(ag[q * 4 + 0]);
        go.y = tanhf(ag[q * 4 + 1]);
        go.z = tanhf(ag[q * 4 + 2]);
        go.w = tanhf(ag[q * 4 + 3]);
        *(float4*)(out + obase + q * 4)        = fo;
        *(float4*)(out + HALF + obase + q * 4) = go;
    }
}

// ---------------- launch ----------------------------------------------------
extern "C" void kernel_launch(void* const* d_in, const int* in_sizes, int n_in,
                              void* d_out, int out_size) {
    const float* x     = (const float*)d_in[0];
    const float* x0    = (const float*)d_in[1];
    const float* w     = (const float*)d_in[2];
    const float* d     = (const float*)d_in[3];
    const float* alpha = (const float*)d_in[4];
    const float* fw1   = (const float*)d_in[5];
    const float* fw2   = (const float*)d_in[6];
    const float* fvs   = (const float*)d_in[7];
    const float* fbs   = (const float*)d_in[8];
    const float* gw1   = (const float*)d_in[9];
    const float* gw2   = (const float*)d_in[10];
    const float* gvs   = (const float*)d_in[11];
    const float* gbs   = (const float*)d_in[12];
    const float* convw = (const float*)d_in[13];
    const float* convb = (const float*)d_in[14];
    const float* adj   = (const float*)d_in[15];
    float* out = (float*)d_out;

    cudaFuncSetAttribute(k_gemm, cudaFuncAttributeMaxDynamicSharedMemorySize, GEMM_SMEM);
    cudaFuncSetAttribute(k_final, cudaFuncAttributeMaxDynamicSharedMemorySize,
                         K5_SMEM_FLOATS * (int)sizeof(float));

    k_prep  <<<PB_TOTAL, 256>>>(x, fw1, fw2, gw1, gw2, fvs, gvs, fbs, gbs,
                                adj, convw, w, d, alpha);
    k_sig   <<<dim3(NN, BB, 2), 256>>>();
    k_gemm  <<<dim3(8, 8, 2 * BB), 256, GEMM_SMEM>>>();
    k_final <<<dim3(NN / 64, BB), 256, K5_SMEM_FLOATS * (int)sizeof(float)>>>(x, x0, convb, out);
}